// round 6
// baseline (speedup 1.0000x reference)
#include <cuda_runtime.h>
#include <math.h>
#include <stdint.h>

#define BATCH 2
#define SEQ   2048
#define DIN   2048
#define DOUT  2048
#define NH    32
#define NKV   8
#define HD    64
#define ROWS  (BATCH*SEQ)    /* 4096 */
#define DKV   (NKV*HD)       /* 512  */

// ---------------- scratch (static device arrays; no allocation) ----------------
__device__ uint32_t g_xt [ROWS*DIN];    // x   in tf32
__device__ uint32_t g_Wqt[DIN*DOUT];    // Wq  in tf32
__device__ uint32_t g_Wkt[DIN*DKV];     // Wk  in tf32
__device__ uint32_t g_Wvt[DIN*DKV];     // Wv  in tf32
__device__ uint32_t g_Wot[DOUT*DOUT];   // Wo  in tf32
__device__ uint32_t g_Qr [ROWS*DOUT];   // [B,NH,S,HD]  tf32
__device__ uint32_t g_Kr [ROWS*DKV];    // [B,NKV,S,HD] tf32
__device__ uint32_t g_Vr [ROWS*DKV];    // [B,NKV,S,HD] tf32
__device__ uint32_t g_ctx[ROWS*DOUT];   // [B*S, NH*HD] tf32

__device__ __forceinline__ uint32_t f2tf(float f) {
    uint32_t r;
    asm("cvt.rna.tf32.f32 %0, %1;" : "=r"(r) : "f"(f));
    return r;
}

__device__ __forceinline__ void mma_tf32(float* c, const uint32_t* a,
                                         uint32_t b0, uint32_t b1) {
    asm volatile(
        "mma.sync.aligned.m16n8k8.row.col.f32.tf32.tf32.f32 "
        "{%0,%1,%2,%3}, {%4,%5,%6,%7}, {%8,%9}, {%0,%1,%2,%3};"
        : "+f"(c[0]), "+f"(c[1]), "+f"(c[2]), "+f"(c[3])
        : "r"(a[0]), "r"(a[1]), "r"(a[2]), "r"(a[3]), "r"(b0), "r"(b1));
}

__device__ __forceinline__ void cp16(uint32_t smem_byte, const void* g) {
    asm volatile("cp.async.cg.shared.global [%0], [%1], 16;\n"
                 :: "r"(smem_byte), "l"(g));
}
__device__ __forceinline__ void cp_commit() {
    asm volatile("cp.async.commit_group;\n" ::);
}
template <int N>
__device__ __forceinline__ void cp_wait() {
    asm volatile("cp.async.wait_group %0;\n" :: "n"(N));
}

// ---------------- bulk fp32 -> tf32 conversion ---------------------------------
__global__ __launch_bounds__(256) void cvt_tf32_k(const float4* __restrict__ in,
                                                  uint4* __restrict__ out, int n4)
{
    int i = blockIdx.x * blockDim.x + threadIdx.x;
    if (i < n4) {
        float4 v = in[i];
        out[i] = make_uint4(f2tf(v.x), f2tf(v.y), f2tf(v.z), f2tf(v.w));
    }
}

// smem strides (conflict-free for their access patterns)
#define AST 36
#define BST 136
#define SGEMM_SMEM ((2*128*AST + 2*32*BST) * 4)   /* 71680 bytes */

// ================= fused QKV projection + RoPE + transpose =====================
// All operands pre-converted tf32. grid (24, 32): bx<16 Q, <20 K, else V.
__global__ __launch_bounds__(256, 3) void qkv_tc(
    const uint32_t* __restrict__ x,
    const uint32_t* __restrict__ Wq, const uint32_t* __restrict__ Wk,
    const uint32_t* __restrict__ Wv,
    const float* __restrict__ cosb, const float* __restrict__ sinb,
    uint32_t* __restrict__ Qr, uint32_t* __restrict__ Kr,
    uint32_t* __restrict__ Vr)
{
    extern __shared__ uint32_t smu[];
    uint32_t* As = smu;                    // [2][128][36]
    uint32_t* Bs = smu + 2 * 128 * AST;    // [2][32][136]

    const int bx = blockIdx.x;
    const uint32_t* W; uint32_t* outp; int N, col0, nh; bool dorope;
    if (bx < 16)      { W = Wq; outp = Qr; N = DOUT; col0 = bx * 128;        nh = NH;  dorope = true;  }
    else if (bx < 20) { W = Wk; outp = Kr; N = DKV;  col0 = (bx - 16) * 128; nh = NKV; dorope = true;  }
    else              { W = Wv; outp = Vr; N = DKV;  col0 = (bx - 20) * 128; nh = NKV; dorope = false; }

    const int tid  = threadIdx.x;
    const int warp = tid >> 5, lane = tid & 31;
    const int g    = lane >> 2, t = lane & 3;
    const int wm   = (warp & 3) * 32;
    const int wn   = (warp >> 2) * 64;
    const int row0 = blockIdx.y * 128;

    const uint32_t sA = (uint32_t)__cvta_generic_to_shared(As);
    const uint32_t sB = (uint32_t)__cvta_generic_to_shared(Bs);

    const int a_c = (tid & 7) * 4,  a_r = tid >> 3;
    const int b_c = (tid & 31) * 4, b_r = tid >> 5;

    auto LOAD = [&](int k0, int buf) {
        const uint32_t* ap = x + (size_t)(row0 + a_r) * DIN + k0 + a_c;
        uint32_t da = sA + (uint32_t)(buf * 128 * AST + a_r * AST + a_c) * 4;
        #pragma unroll
        for (int i = 0; i < 4; i++)
            cp16(da + i * 32 * AST * 4, ap + (size_t)i * 32 * DIN);
        const uint32_t* bp = W + (size_t)(k0 + b_r) * N + col0 + b_c;
        uint32_t db = sB + (uint32_t)(buf * 32 * BST + b_r * BST + b_c) * 4;
        #pragma unroll
        for (int i = 0; i < 4; i++)
            cp16(db + i * 8 * BST * 4, bp + (size_t)i * 8 * N);
    };

    float acc[2][8][4];
    #pragma unroll
    for (int mi = 0; mi < 2; mi++)
        #pragma unroll
        for (int ni = 0; ni < 8; ni++)
            #pragma unroll
            for (int r = 0; r < 4; r++) acc[mi][ni][r] = 0.f;

    LOAD(0, 0);
    cp_commit();

    const int niter = DIN / 32;
    for (int it = 0; it < niter; it++) {
        const int buf = it & 1;
        if (it + 1 < niter) {
            LOAD((it + 1) * 32, buf ^ 1);
            cp_commit();
            cp_wait<1>();
        } else {
            cp_wait<0>();
        }
        __syncthreads();

        const uint32_t* Asb = As + buf * 128 * AST;
        const uint32_t* Bsb = Bs + buf * 32 * BST;
        #pragma unroll
        for (int ks = 0; ks < 4; ks++) {
            const int kb = ks * 8;
            uint32_t a[2][4], b[8][2];
            #pragma unroll
            for (int mi = 0; mi < 2; mi++) {
                const int m0 = wm + mi * 16 + g;
                a[mi][0] = Asb[(m0    ) * AST + kb + t];
                a[mi][1] = Asb[(m0 + 8) * AST + kb + t];
                a[mi][2] = Asb[(m0    ) * AST + kb + t + 4];
                a[mi][3] = Asb[(m0 + 8) * AST + kb + t + 4];
            }
            #pragma unroll
            for (int ni = 0; ni < 8; ni++) {
                const int n0 = wn + ni * 8 + g;
                b[ni][0] = Bsb[(kb + t    ) * BST + n0];
                b[ni][1] = Bsb[(kb + t + 4) * BST + n0];
            }
            #pragma unroll
            for (int mi = 0; mi < 2; mi++)
                #pragma unroll
                for (int ni = 0; ni < 8; ni++)
                    mma_tf32(acc[mi][ni], a[mi], b[ni][0], b[ni][1]);
        }
        __syncthreads();
    }

    // ---- fused epilogue: (RoPE) + transpose to [b,h,s,d] + tf32 convert
    const int hq = (col0 + wn) >> 6;
    #pragma unroll
    for (int mi = 0; mi < 2; mi++) {
        const int rbase = row0 + wm + mi * 16 + g;
        #pragma unroll
        for (int v = 0; v < 2; v++) {
            const int r = rbase + v * 8;
            const int b = r >> 11, s = r & 2047;
            uint32_t* op = outp + ((size_t)(b * nh + hq) * SEQ + s) * HD;
            if (dorope) {
                #pragma unroll
                for (int ni = 0; ni < 4; ni++) {
                    const int d = ni * 8 + 2 * t;
                    float x1a = acc[mi][ni    ][v*2], x1b = acc[mi][ni    ][v*2+1];
                    float x2a = acc[mi][ni + 4][v*2], x2b = acc[mi][ni + 4][v*2+1];
                    float2 c1 = *(const float2*)&cosb[s * HD + d];
                    float2 s1 = *(const float2*)&sinb[s * HD + d];
                    float2 c2 = *(const float2*)&cosb[s * HD + d + 32];
                    float2 s2 = *(const float2*)&sinb[s * HD + d + 32];
                    uint2 w1 = make_uint2(f2tf(x1a * c1.x - x2a * s1.x),
                                          f2tf(x1b * c1.y - x2b * s1.y));
                    uint2 w2 = make_uint2(f2tf(x2a * c2.x + x1a * s2.x),
                                          f2tf(x2b * c2.y + x1b * s2.y));
                    *(uint2*)&op[d]      = w1;
                    *(uint2*)&op[d + 32] = w2;
                }
            } else {
                #pragma unroll
                for (int ni = 0; ni < 8; ni++) {
                    const int d = ni * 8 + 2 * t;
                    *(uint2*)&op[d] = make_uint2(f2tf(acc[mi][ni][v*2]),
                                                 f2tf(acc[mi][ni][v*2+1]));
                }
            }
        }
    }
}

// ================= tf32 GEMM (output projection, tf32 operands) ================
__global__ __launch_bounds__(256, 3) void sgemm_tc(
    const uint32_t* __restrict__ A, const uint32_t* __restrict__ B,
    float* __restrict__ C, int M, int N, int K)
{
    extern __shared__ uint32_t smu[];
    uint32_t* As = smu;
    uint32_t* Bs = smu + 2 * 128 * AST;

    const int tid  = threadIdx.x;
    const int warp = tid >> 5, lane = tid & 31;
    const int g    = lane >> 2, t = lane & 3;
    const int wm   = (warp & 3) * 32;
    const int wn   = (warp >> 2) * 64;
    const int row0 = blockIdx.y * 128, col0 = blockIdx.x * 128;

    const uint32_t sA = (uint32_t)__cvta_generic_to_shared(As);
    const uint32_t sB = (uint32_t)__cvta_generic_to_shared(Bs);

    const int a_c = (tid & 7) * 4,  a_r = tid >> 3;
    const int b_c = (tid & 31) * 4, b_r = tid >> 5;

    auto LOAD = [&](int k0, int buf) {
        const uint32_t* ap = A + (size_t)(row0 + a_r) * K + k0 + a_c;
        uint32_t da = sA + (uint32_t)(buf * 128 * AST + a_r * AST + a_c) * 4;
        #pragma unroll
        for (int i = 0; i < 4; i++)
            cp16(da + i * 32 * AST * 4, ap + (size_t)i * 32 * K);
        const uint32_t* bp = B + (size_t)(k0 + b_r) * N + col0 + b_c;
        uint32_t db = sB + (uint32_t)(buf * 32 * BST + b_r * BST + b_c) * 4;
        #pragma unroll
        for (int i = 0; i < 4; i++)
            cp16(db + i * 8 * BST * 4, bp + (size_t)i * 8 * N);
    };

    float acc[2][8][4];
    #pragma unroll
    for (int mi = 0; mi < 2; mi++)
        #pragma unroll
        for (int ni = 0; ni < 8; ni++)
            #pragma unroll
            for (int r = 0; r < 4; r++) acc[mi][ni][r] = 0.f;

    LOAD(0, 0);
    cp_commit();

    const int niter = K / 32;
    for (int it = 0; it < niter; it++) {
        const int buf = it & 1;
        if (it + 1 < niter) {
            LOAD((it + 1) * 32, buf ^ 1);
            cp_commit();
            cp_wait<1>();
        } else {
            cp_wait<0>();
        }
        __syncthreads();

        const uint32_t* Asb = As + buf * 128 * AST;
        const uint32_t* Bsb = Bs + buf * 32 * BST;
        #pragma unroll
        for (int ks = 0; ks < 4; ks++) {
            const int kb = ks * 8;
            uint32_t a[2][4], b[8][2];
            #pragma unroll
            for (int mi = 0; mi < 2; mi++) {
                const int m0 = wm + mi * 16 + g;
                a[mi][0] = Asb[(m0    ) * AST + kb + t];
                a[mi][1] = Asb[(m0 + 8) * AST + kb + t];
                a[mi][2] = Asb[(m0    ) * AST + kb + t + 4];
                a[mi][3] = Asb[(m0 + 8) * AST + kb + t + 4];
            }
            #pragma unroll
            for (int ni = 0; ni < 8; ni++) {
                const int n0 = wn + ni * 8 + g;
                b[ni][0] = Bsb[(kb + t    ) * BST + n0];
                b[ni][1] = Bsb[(kb + t + 4) * BST + n0];
            }
            #pragma unroll
            for (int mi = 0; mi < 2; mi++)
                #pragma unroll
                for (int ni = 0; ni < 8; ni++)
                    mma_tf32(acc[mi][ni], a[mi], b[ni][0], b[ni][1]);
        }
        __syncthreads();
    }

    #pragma unroll
    for (int mi = 0; mi < 2; mi++)
        #pragma unroll
        for (int ni = 0; ni < 8; ni++) {
            const int r = row0 + wm + mi * 16 + g;
            const int c = col0 + wn + ni * 8 + t * 2;
            *(float2*)(C + (size_t)r * N + c) =
                make_float2(acc[mi][ni][0], acc[mi][ni][1]);
            *(float2*)(C + (size_t)(r + 8) * N + c) =
                make_float2(acc[mi][ni][2], acc[mi][ni][3]);
        }
}

// ================= tf32 flash attention (epilogue -> tf32 ctx) =================
#define QST 68
#define VST 72
#define ATTN_SMEM ((128*QST + 2*64*QST + 2*64*VST) * 4)   /* 106496 bytes */

__global__ __launch_bounds__(256) void attn_tc(
    const uint32_t* __restrict__ Qr, const uint32_t* __restrict__ Kr,
    const uint32_t* __restrict__ Vr, uint32_t* __restrict__ ctx)
{
    extern __shared__ uint32_t smu[];
    uint32_t* Pq = smu;                   // [128][68]
    uint32_t* Ks = smu + 128 * QST;       // [2][64][68]
    uint32_t* Vs = Ks  + 2 * 64 * QST;    // [2][64][72]

    const int bh = blockIdx.y;
    const int b = bh >> 5, h = bh & 31, g2 = h >> 2;
    const int qt = gridDim.x - 1 - blockIdx.x;
    const int q0 = qt * 128;
    const int tid = threadIdx.x;
    const int warp = tid >> 5, lane = tid & 31;
    const int g = lane >> 2, t = lane & 3;
    const int wq = warp * 16;

    const uint32_t* Qbase = Qr + ((size_t)bh * SEQ + q0) * HD;
    const uint32_t* Kbase = Kr + (size_t)(b * NKV + g2) * SEQ * HD;
    const uint32_t* Vbase = Vr + (size_t)(b * NKV + g2) * SEQ * HD;

    const uint32_t sK = (uint32_t)__cvta_generic_to_shared(Ks);
    const uint32_t sV = (uint32_t)__cvta_generic_to_shared(Vs);

    const int kc = (tid & 15) * 4, kr = tid >> 4;

    auto LOADKV = [&](int k0, int buf) {
        const uint32_t* kp = Kbase + (size_t)(k0 + kr) * HD + kc;
        const uint32_t* vp = Vbase + (size_t)(k0 + kr) * HD + kc;
        uint32_t dk = sK + (uint32_t)(buf * 64 * QST + kr * QST + kc) * 4;
        uint32_t dv = sV + (uint32_t)(buf * 64 * VST + kr * VST + kc) * 4;
        #pragma unroll
        for (int i = 0; i < 4; i++) {
            cp16(dk + i * 16 * QST * 4, kp + (size_t)i * 16 * HD);
            cp16(dv + i * 16 * VST * 4, vp + (size_t)i * 16 * HD);
        }
    };

    LOADKV(0, 0);
    cp_commit();
    #pragma unroll
    for (int i = 0; i < 8; i++) {
        int idx = i * 256 + tid;
        int r = idx >> 4, c = (idx & 15) * 4;
        *(uint4*)&Pq[r * QST + c] = *(const uint4*)&Qbase[r * HD + c];
    }
    __syncthreads();

    uint32_t qf[8][4];
    #pragma unroll
    for (int s = 0; s < 8; s++) {
        qf[s][0] = Pq[(wq + g    ) * QST + s * 8 + t];
        qf[s][1] = Pq[(wq + g + 8) * QST + s * 8 + t];
        qf[s][2] = Pq[(wq + g    ) * QST + s * 8 + t + 4];
        qf[s][3] = Pq[(wq + g + 8) * QST + s * 8 + t + 4];
    }

    float o[8][4];
    #pragma unroll
    for (int ni = 0; ni < 8; ni++)
        #pragma unroll
        for (int r = 0; r < 4; r++) o[ni][r] = 0.f;
    float m0 = -1e30f, m1 = -1e30f, l0 = 0.f, l1 = 0.f;

    const int ntiles = qt * 2 + 2;
    for (int tt = 0; tt < ntiles; tt++) {
        const int buf = tt & 1;
        if (tt + 1 < ntiles) {
            LOADKV((tt + 1) * 64, buf ^ 1);
            cp_commit();
            cp_wait<1>();
        } else {
            cp_wait<0>();
        }
        __syncthreads();

        const uint32_t* Ksb = Ks + buf * 64 * QST;
        const uint32_t* Vsb = Vs + buf * 64 * VST;
        const int k0 = tt * 64;

        float s[8][4];
        #pragma unroll
        for (int ni = 0; ni < 8; ni++)
            #pragma unroll
            for (int r = 0; r < 4; r++) s[ni][r] = 0.f;

        #pragma unroll
        for (int ds = 0; ds < 8; ds++) {
            #pragma unroll
            for (int ni = 0; ni < 8; ni++) {
                uint32_t b0 = Ksb[(ni * 8 + g) * QST + ds * 8 + t];
                uint32_t b1 = Ksb[(ni * 8 + g) * QST + ds * 8 + t + 4];
                mma_tf32(s[ni], qf[ds], b0, b1);
            }
        }

        const bool do_mask = (k0 + 63 > q0);
        const int qg0 = q0 + wq + g, qg1 = qg0 + 8;
        #pragma unroll
        for (int ni = 0; ni < 8; ni++) {
            #pragma unroll
            for (int r = 0; r < 4; r++) {
                float v = s[ni][r] * 0.125f;
                if (do_mask) {
                    int kg = k0 + ni * 8 + 2 * t + (r & 1);
                    int qg = (r >= 2) ? qg1 : qg0;
                    if (kg > qg) v = -1e30f;
                }
                s[ni][r] = v;
            }
        }

        float tm0 = -1e30f, tm1 = -1e30f;
        #pragma unroll
        for (int ni = 0; ni < 8; ni++) {
            tm0 = fmaxf(tm0, fmaxf(s[ni][0], s[ni][1]));
            tm1 = fmaxf(tm1, fmaxf(s[ni][2], s[ni][3]));
        }
        tm0 = fmaxf(tm0, __shfl_xor_sync(0xffffffffu, tm0, 1));
        tm0 = fmaxf(tm0, __shfl_xor_sync(0xffffffffu, tm0, 2));
        tm1 = fmaxf(tm1, __shfl_xor_sync(0xffffffffu, tm1, 1));
        tm1 = fmaxf(tm1, __shfl_xor_sync(0xffffffffu, tm1, 2));

        float mn0 = fmaxf(m0, tm0), mn1 = fmaxf(m1, tm1);
        float a0 = __expf(m0 - mn0), a1 = __expf(m1 - mn1);
        m0 = mn0; m1 = mn1;

        float rs0 = 0.f, rs1 = 0.f;
        #pragma unroll
        for (int ni = 0; ni < 8; ni++) {
            s[ni][0] = __expf(s[ni][0] - mn0);
            s[ni][1] = __expf(s[ni][1] - mn0);
            s[ni][2] = __expf(s[ni][2] - mn1);
            s[ni][3] = __expf(s[ni][3] - mn1);
            rs0 += s[ni][0] + s[ni][1];
            rs1 += s[ni][2] + s[ni][3];
        }
        rs0 += __shfl_xor_sync(0xffffffffu, rs0, 1);
        rs0 += __shfl_xor_sync(0xffffffffu, rs0, 2);
        rs1 += __shfl_xor_sync(0xffffffffu, rs1, 1);
        rs1 += __shfl_xor_sync(0xffffffffu, rs1, 2);
        l0 = l0 * a0 + rs0;
        l1 = l1 * a1 + rs1;

        #pragma unroll
        for (int ni = 0; ni < 8; ni++) {
            o[ni][0] *= a0; o[ni][1] *= a0;
            o[ni][2] *= a1; o[ni][3] *= a1;
        }

        #pragma unroll
        for (int ni = 0; ni < 8; ni++) {
            uint2 w0 = make_uint2(f2tf(s[ni][0]), f2tf(s[ni][1]));
            uint2 w1 = make_uint2(f2tf(s[ni][2]), f2tf(s[ni][3]));
            *(uint2*)&Pq[(wq + g    ) * QST + ni * 8 + 2 * t] = w0;
            *(uint2*)&Pq[(wq + g + 8) * QST + ni * 8 + 2 * t] = w1;
        }
        __syncwarp();

        #pragma unroll
        for (int ks = 0; ks < 8; ks++) {
            uint32_t a[4];
            a[0] = Pq[(wq + g    ) * QST + ks * 8 + t];
            a[1] = Pq[(wq + g + 8) * QST + ks * 8 + t];
            a[2] = Pq[(wq + g    ) * QST + ks * 8 + t + 4];
            a[3] = Pq[(wq + g + 8) * QST + ks * 8 + t + 4];
            #pragma unroll
            for (int ni = 0; ni < 8; ni++) {
                uint32_t b0 = Vsb[(ks * 8 + t    ) * VST + ni * 8 + g];
                uint32_t b1 = Vsb[(ks * 8 + t + 4) * VST + ni * 8 + g];
                mma_tf32(o[ni], a, b0, b1);
            }
        }
        __syncthreads();
    }

    // epilogue: ctx written directly as tf32 (feeds Wo GEMM)
    float inv0 = 1.f / l0, inv1 = 1.f / l1;
    const int qg0 = q0 + wq + g, qg1 = qg0 + 8;
    #pragma unroll
    for (int ni = 0; ni < 8; ni++) {
        int c = h * HD + ni * 8 + 2 * t;
        *(uint2*)&ctx[(size_t)(b * SEQ + qg0) * DOUT + c] =
            make_uint2(f2tf(o[ni][0] * inv0), f2tf(o[ni][1] * inv0));
        *(uint2*)&ctx[(size_t)(b * SEQ + qg1) * DOUT + c] =
            make_uint2(f2tf(o[ni][2] * inv1), f2tf(o[ni][3] * inv1));
    }
}

// ------------------------------- launcher -------------------------------------
extern "C" void kernel_launch(void* const* d_in, const int* in_sizes, int n_in,
                              void* d_out, int out_size)
{
    const float* x    = (const float*)d_in[0];
    const float* Wq   = (const float*)d_in[1];
    const float* Wk   = (const float*)d_in[2];
    const float* Wv   = (const float*)d_in[3];
    const float* Wo   = (const float*)d_in[4];
    const float* cosb = (const float*)d_in[5];
    const float* sinb = (const float*)d_in[6];
    float* out = (float*)d_out;

    uint32_t *pXt, *pWqt, *pWkt, *pWvt, *pWot, *pQr, *pKr, *pVr, *pCtx;
    cudaGetSymbolAddress((void**)&pXt,  g_xt);
    cudaGetSymbolAddress((void**)&pWqt, g_Wqt);
    cudaGetSymbolAddress((void**)&pWkt, g_Wkt);
    cudaGetSymbolAddress((void**)&pWvt, g_Wvt);
    cudaGetSymbolAddress((void**)&pWot, g_Wot);
    cudaGetSymbolAddress((void**)&pQr,  g_Qr);
    cudaGetSymbolAddress((void**)&pKr,  g_Kr);
    cudaGetSymbolAddress((void**)&pVr,  g_Vr);
    cudaGetSymbolAddress((void**)&pCtx, g_ctx);

    dim3 thr(256);

    cudaFuncSetAttribute(qkv_tc,   cudaFuncAttributeMaxDynamicSharedMemorySize, SGEMM_SMEM);
    cudaFuncSetAttribute(sgemm_tc, cudaFuncAttributeMaxDynamicSharedMemorySize, SGEMM_SMEM);
    cudaFuncSetAttribute(attn_tc,  cudaFuncAttributeMaxDynamicSharedMemorySize, ATTN_SMEM);

    // bulk tf32 pre-conversion (x + all weights)
    cvt_tf32_k<<<(ROWS*DIN/4   + 255)/256, thr>>>((const float4*)x,  (uint4*)pXt,  ROWS*DIN/4);
    cvt_tf32_k<<<(DIN*DOUT/4   + 255)/256, thr>>>((const float4*)Wq, (uint4*)pWqt, DIN*DOUT/4);
    cvt_tf32_k<<<(DIN*DKV/4    + 255)/256, thr>>>((const float4*)Wk, (uint4*)pWkt, DIN*DKV/4);
    cvt_tf32_k<<<(DIN*DKV/4    + 255)/256, thr>>>((const float4*)Wv, (uint4*)pWvt, DIN*DKV/4);
    cvt_tf32_k<<<(DOUT*DOUT/4  + 255)/256, thr>>>((const float4*)Wo, (uint4*)pWot, DOUT*DOUT/4);

    // fused QKV projection + RoPE + head-transpose
    qkv_tc<<<dim3(24, ROWS/128), thr, SGEMM_SMEM>>>(
        pXt, pWqt, pWkt, pWvt, cosb, sinb, pQr, pKr, pVr);

    // causal flash attention
    attn_tc<<<dim3(SEQ/128, BATCH*NH), thr, ATTN_SMEM>>>(pQr, pKr, pVr, pCtx);

    // output projection
    sgemm_tc<<<dim3(DOUT/128, ROWS/128), thr, SGEMM_SMEM>>>(pCtx, pWot, out, ROWS, DOUT, DIN);
}

// round 7
// speedup vs baseline: 1.2182x; 1.2182x over previous
#include <cuda_runtime.h>
#include <math.h>
#include <stdint.h>

#define BATCH 2
#define SEQ   2048
#define DIN   2048
#define DOUT  2048
#define NH    32
#define NKV   8
#define HD    64
#define ROWS  (BATCH*SEQ)    /* 4096 */
#define DKV   (NKV*HD)       /* 512  */

// ---------------- scratch (static device arrays; no allocation) ----------------
__device__ uint32_t g_Wqt[DIN*DOUT];    // Wq  in tf32
__device__ uint32_t g_Wkt[DIN*DKV];     // Wk  in tf32
__device__ uint32_t g_Wvt[DIN*DKV];     // Wv  in tf32
__device__ uint32_t g_Wot[DOUT*DOUT];   // Wo  in tf32
__device__ uint32_t g_Qr [ROWS*DOUT];   // [B,NH,S,HD]  tf32
__device__ uint32_t g_Kr [ROWS*DKV];    // [B,NKV,S,HD] tf32
__device__ uint32_t g_Vr [ROWS*DKV];    // [B,NKV,S,HD] tf32
__device__ uint32_t g_ctx[ROWS*DOUT];   // [B*S, NH*HD] tf32

__device__ __forceinline__ uint32_t f2tf(float f) {
    uint32_t r;
    asm("cvt.rna.tf32.f32 %0, %1;" : "=r"(r) : "f"(f));
    return r;
}

__device__ __forceinline__ void mma_tf32(float* c, const uint32_t* a,
                                         uint32_t b0, uint32_t b1) {
    asm volatile(
        "mma.sync.aligned.m16n8k8.row.col.f32.tf32.tf32.f32 "
        "{%0,%1,%2,%3}, {%4,%5,%6,%7}, {%8,%9}, {%0,%1,%2,%3};"
        : "+f"(c[0]), "+f"(c[1]), "+f"(c[2]), "+f"(c[3])
        : "r"(a[0]), "r"(a[1]), "r"(a[2]), "r"(a[3]), "r"(b0), "r"(b1));
}

__device__ __forceinline__ void cp16(uint32_t smem_byte, const void* g) {
    asm volatile("cp.async.cg.shared.global [%0], [%1], 16;\n"
                 :: "r"(smem_byte), "l"(g));
}
__device__ __forceinline__ void cp_commit() {
    asm volatile("cp.async.commit_group;\n" ::);
}
template <int N>
__device__ __forceinline__ void cp_wait() {
    asm volatile("cp.async.wait_group %0;\n" :: "n"(N));
}

// ---------------- fused weight fp32 -> tf32 conversion -------------------------
#define NQ4 (DIN*DOUT/4)   /* 1048576 */
#define NK4 (DIN*DKV/4)    /* 262144  */
__global__ __launch_bounds__(256) void cvt_weights_k(
    const float4* __restrict__ Wq, const float4* __restrict__ Wk,
    const float4* __restrict__ Wv, const float4* __restrict__ Wo,
    uint4* __restrict__ oq, uint4* __restrict__ ok,
    uint4* __restrict__ ov, uint4* __restrict__ oo)
{
    int i = blockIdx.x * blockDim.x + threadIdx.x;
    const float4* src; uint4* dst; int j;
    if (i < NQ4)                { src = Wq; dst = oq; j = i; }
    else if (i < NQ4 + NK4)     { src = Wk; dst = ok; j = i - NQ4; }
    else if (i < NQ4 + 2*NK4)   { src = Wv; dst = ov; j = i - NQ4 - NK4; }
    else                        { src = Wo; dst = oo; j = i - NQ4 - 2*NK4; }
    float4 v = src[j];
    dst[j] = make_uint4(f2tf(v.x), f2tf(v.y), f2tf(v.z), f2tf(v.w));
}

// smem strides (conflict-free for their access patterns)
#define AST 36
#define BST 136
#define SGEMM_SMEM ((2*128*AST + 2*32*BST) * 4)   /* 71680 bytes */

// ================= fused QKV projection + RoPE + transpose =====================
// A = x (fp32, cvt at fragment load), B = pre-converted tf32 weights.
// grid (24, 32): bx<16 Q, <20 K, else V.
__global__ __launch_bounds__(256, 2) void qkv_tc(
    const float* __restrict__ x,
    const uint32_t* __restrict__ Wq, const uint32_t* __restrict__ Wk,
    const uint32_t* __restrict__ Wv,
    const float* __restrict__ cosb, const float* __restrict__ sinb,
    uint32_t* __restrict__ Qr, uint32_t* __restrict__ Kr,
    uint32_t* __restrict__ Vr)
{
    extern __shared__ uint32_t smu[];
    float*    As = (float*)smu;            // [2][128][36] fp32
    uint32_t* Bs = smu + 2 * 128 * AST;    // [2][32][136] tf32

    const int bx = blockIdx.x;
    const uint32_t* W; uint32_t* outp; int N, col0, nh; bool dorope;
    if (bx < 16)      { W = Wq; outp = Qr; N = DOUT; col0 = bx * 128;        nh = NH;  dorope = true;  }
    else if (bx < 20) { W = Wk; outp = Kr; N = DKV;  col0 = (bx - 16) * 128; nh = NKV; dorope = true;  }
    else              { W = Wv; outp = Vr; N = DKV;  col0 = (bx - 20) * 128; nh = NKV; dorope = false; }

    const int tid  = threadIdx.x;
    const int warp = tid >> 5, lane = tid & 31;
    const int g    = lane >> 2, t = lane & 3;
    const int wm   = (warp & 3) * 32;
    const int wn   = (warp >> 2) * 64;
    const int row0 = blockIdx.y * 128;

    const uint32_t sA = (uint32_t)__cvta_generic_to_shared(As);
    const uint32_t sB = (uint32_t)__cvta_generic_to_shared(Bs);

    const int a_c = (tid & 7) * 4,  a_r = tid >> 3;
    const int b_c = (tid & 31) * 4, b_r = tid >> 5;

    auto LOAD = [&](int k0, int buf) {
        const float* ap = x + (size_t)(row0 + a_r) * DIN + k0 + a_c;
        uint32_t da = sA + (uint32_t)(buf * 128 * AST + a_r * AST + a_c) * 4;
        #pragma unroll
        for (int i = 0; i < 4; i++)
            cp16(da + i * 32 * AST * 4, ap + (size_t)i * 32 * DIN);
        const uint32_t* bp = W + (size_t)(k0 + b_r) * N + col0 + b_c;
        uint32_t db = sB + (uint32_t)(buf * 32 * BST + b_r * BST + b_c) * 4;
        #pragma unroll
        for (int i = 0; i < 4; i++)
            cp16(db + i * 8 * BST * 4, bp + (size_t)i * 8 * N);
    };

    float acc[2][8][4];
    #pragma unroll
    for (int mi = 0; mi < 2; mi++)
        #pragma unroll
        for (int ni = 0; ni < 8; ni++)
            #pragma unroll
            for (int r = 0; r < 4; r++) acc[mi][ni][r] = 0.f;

    LOAD(0, 0);
    cp_commit();

    const int niter = DIN / 32;
    for (int it = 0; it < niter; it++) {
        const int buf = it & 1;
        if (it + 1 < niter) {
            LOAD((it + 1) * 32, buf ^ 1);
            cp_commit();
            cp_wait<1>();
        } else {
            cp_wait<0>();
        }
        __syncthreads();

        const float*    Asb = As + buf * 128 * AST;
        const uint32_t* Bsb = Bs + buf * 32 * BST;
        #pragma unroll
        for (int ks = 0; ks < 4; ks++) {
            const int kb = ks * 8;
            uint32_t a[2][4], b[8][2];
            #pragma unroll
            for (int mi = 0; mi < 2; mi++) {
                const int m0 = wm + mi * 16 + g;
                a[mi][0] = f2tf(Asb[(m0    ) * AST + kb + t]);
                a[mi][1] = f2tf(Asb[(m0 + 8) * AST + kb + t]);
                a[mi][2] = f2tf(Asb[(m0    ) * AST + kb + t + 4]);
                a[mi][3] = f2tf(Asb[(m0 + 8) * AST + kb + t + 4]);
            }
            #pragma unroll
            for (int ni = 0; ni < 8; ni++) {
                const int n0 = wn + ni * 8 + g;
                b[ni][0] = Bsb[(kb + t    ) * BST + n0];
                b[ni][1] = Bsb[(kb + t + 4) * BST + n0];
            }
            #pragma unroll
            for (int mi = 0; mi < 2; mi++)
                #pragma unroll
                for (int ni = 0; ni < 8; ni++)
                    mma_tf32(acc[mi][ni], a[mi], b[ni][0], b[ni][1]);
        }
        __syncthreads();
    }

    // ---- fused epilogue: (RoPE) + transpose to [b,h,s,d] + tf32 convert
    const int hq = (col0 + wn) >> 6;
    #pragma unroll
    for (int mi = 0; mi < 2; mi++) {
        const int rbase = row0 + wm + mi * 16 + g;
        #pragma unroll
        for (int v = 0; v < 2; v++) {
            const int r = rbase + v * 8;
            const int b = r >> 11, s = r & 2047;
            uint32_t* op = outp + ((size_t)(b * nh + hq) * SEQ + s) * HD;
            if (dorope) {
                #pragma unroll
                for (int ni = 0; ni < 4; ni++) {
                    const int d = ni * 8 + 2 * t;
                    float x1a = acc[mi][ni    ][v*2], x1b = acc[mi][ni    ][v*2+1];
                    float x2a = acc[mi][ni + 4][v*2], x2b = acc[mi][ni + 4][v*2+1];
                    float2 c1 = *(const float2*)&cosb[s * HD + d];
                    float2 s1 = *(const float2*)&sinb[s * HD + d];
                    float2 c2 = *(const float2*)&cosb[s * HD + d + 32];
                    float2 s2 = *(const float2*)&sinb[s * HD + d + 32];
                    uint2 w1 = make_uint2(f2tf(x1a * c1.x - x2a * s1.x),
                                          f2tf(x1b * c1.y - x2b * s1.y));
                    uint2 w2 = make_uint2(f2tf(x2a * c2.x + x1a * s2.x),
                                          f2tf(x2b * c2.y + x1b * s2.y));
                    *(uint2*)&op[d]      = w1;
                    *(uint2*)&op[d + 32] = w2;
                }
            } else {
                #pragma unroll
                for (int ni = 0; ni < 8; ni++) {
                    const int d = ni * 8 + 2 * t;
                    *(uint2*)&op[d] = make_uint2(f2tf(acc[mi][ni][v*2]),
                                                 f2tf(acc[mi][ni][v*2+1]));
                }
            }
        }
    }
}

// ================= tf32 GEMM (output projection; both operands tf32) ===========
__global__ __launch_bounds__(256, 2) void sgemm_tc(
    const uint32_t* __restrict__ A, const uint32_t* __restrict__ B,
    float* __restrict__ C, int M, int N, int K)
{
    extern __shared__ uint32_t smu[];
    uint32_t* As = smu;
    uint32_t* Bs = smu + 2 * 128 * AST;

    const int tid  = threadIdx.x;
    const int warp = tid >> 5, lane = tid & 31;
    const int g    = lane >> 2, t = lane & 3;
    const int wm   = (warp & 3) * 32;
    const int wn   = (warp >> 2) * 64;
    const int row0 = blockIdx.y * 128, col0 = blockIdx.x * 128;

    const uint32_t sA = (uint32_t)__cvta_generic_to_shared(As);
    const uint32_t sB = (uint32_t)__cvta_generic_to_shared(Bs);

    const int a_c = (tid & 7) * 4,  a_r = tid >> 3;
    const int b_c = (tid & 31) * 4, b_r = tid >> 5;

    auto LOAD = [&](int k0, int buf) {
        const uint32_t* ap = A + (size_t)(row0 + a_r) * K + k0 + a_c;
        uint32_t da = sA + (uint32_t)(buf * 128 * AST + a_r * AST + a_c) * 4;
        #pragma unroll
        for (int i = 0; i < 4; i++)
            cp16(da + i * 32 * AST * 4, ap + (size_t)i * 32 * K);
        const uint32_t* bp = B + (size_t)(k0 + b_r) * N + col0 + b_c;
        uint32_t db = sB + (uint32_t)(buf * 32 * BST + b_r * BST + b_c) * 4;
        #pragma unroll
        for (int i = 0; i < 4; i++)
            cp16(db + i * 8 * BST * 4, bp + (size_t)i * 8 * N);
    };

    float acc[2][8][4];
    #pragma unroll
    for (int mi = 0; mi < 2; mi++)
        #pragma unroll
        for (int ni = 0; ni < 8; ni++)
            #pragma unroll
            for (int r = 0; r < 4; r++) acc[mi][ni][r] = 0.f;

    LOAD(0, 0);
    cp_commit();

    const int niter = K / 32;
    for (int it = 0; it < niter; it++) {
        const int buf = it & 1;
        if (it + 1 < niter) {
            LOAD((it + 1) * 32, buf ^ 1);
            cp_commit();
            cp_wait<1>();
        } else {
            cp_wait<0>();
        }
        __syncthreads();

        const uint32_t* Asb = As + buf * 128 * AST;
        const uint32_t* Bsb = Bs + buf * 32 * BST;
        #pragma unroll
        for (int ks = 0; ks < 4; ks++) {
            const int kb = ks * 8;
            uint32_t a[2][4], b[8][2];
            #pragma unroll
            for (int mi = 0; mi < 2; mi++) {
                const int m0 = wm + mi * 16 + g;
                a[mi][0] = Asb[(m0    ) * AST + kb + t];
                a[mi][1] = Asb[(m0 + 8) * AST + kb + t];
                a[mi][2] = Asb[(m0    ) * AST + kb + t + 4];
                a[mi][3] = Asb[(m0 + 8) * AST + kb + t + 4];
            }
            #pragma unroll
            for (int ni = 0; ni < 8; ni++) {
                const int n0 = wn + ni * 8 + g;
                b[ni][0] = Bsb[(kb + t    ) * BST + n0];
                b[ni][1] = Bsb[(kb + t + 4) * BST + n0];
            }
            #pragma unroll
            for (int mi = 0; mi < 2; mi++)
                #pragma unroll
                for (int ni = 0; ni < 8; ni++)
                    mma_tf32(acc[mi][ni], a[mi], b[ni][0], b[ni][1]);
        }
        __syncthreads();
    }

    #pragma unroll
    for (int mi = 0; mi < 2; mi++)
        #pragma unroll
        for (int ni = 0; ni < 8; ni++) {
            const int r = row0 + wm + mi * 16 + g;
            const int c = col0 + wn + ni * 8 + t * 2;
            *(float2*)(C + (size_t)r * N + c) =
                make_float2(acc[mi][ni][0], acc[mi][ni][1]);
            *(float2*)(C + (size_t)(r + 8) * N + c) =
                make_float2(acc[mi][ni][2], acc[mi][ni][3]);
        }
}

// ================= tf32 flash attention (epilogue -> tf32 ctx) =================
#define QST 68
#define VST 72
#define ATTN_SMEM ((128*QST + 2*64*QST + 2*64*VST) * 4)   /* 106496 bytes */

__global__ __launch_bounds__(256) void attn_tc(
    const uint32_t* __restrict__ Qr, const uint32_t* __restrict__ Kr,
    const uint32_t* __restrict__ Vr, uint32_t* __restrict__ ctx)
{
    extern __shared__ uint32_t smu[];
    uint32_t* Pq = smu;                   // [128][68]
    uint32_t* Ks = smu + 128 * QST;       // [2][64][68]
    uint32_t* Vs = Ks  + 2 * 64 * QST;    // [2][64][72]

    const int bh = blockIdx.y;
    const int b = bh >> 5, h = bh & 31, g2 = h >> 2;
    const int qt = gridDim.x - 1 - blockIdx.x;
    const int q0 = qt * 128;
    const int tid = threadIdx.x;
    const int warp = tid >> 5, lane = tid & 31;
    const int g = lane >> 2, t = lane & 3;
    const int wq = warp * 16;

    const uint32_t* Qbase = Qr + ((size_t)bh * SEQ + q0) * HD;
    const uint32_t* Kbase = Kr + (size_t)(b * NKV + g2) * SEQ * HD;
    const uint32_t* Vbase = Vr + (size_t)(b * NKV + g2) * SEQ * HD;

    const uint32_t sK = (uint32_t)__cvta_generic_to_shared(Ks);
    const uint32_t sV = (uint32_t)__cvta_generic_to_shared(Vs);

    const int kc = (tid & 15) * 4, kr = tid >> 4;

    auto LOADKV = [&](int k0, int buf) {
        const uint32_t* kp = Kbase + (size_t)(k0 + kr) * HD + kc;
        const uint32_t* vp = Vbase + (size_t)(k0 + kr) * HD + kc;
        uint32_t dk = sK + (uint32_t)(buf * 64 * QST + kr * QST + kc) * 4;
        uint32_t dv = sV + (uint32_t)(buf * 64 * VST + kr * VST + kc) * 4;
        #pragma unroll
        for (int i = 0; i < 4; i++) {
            cp16(dk + i * 16 * QST * 4, kp + (size_t)i * 16 * HD);
            cp16(dv + i * 16 * VST * 4, vp + (size_t)i * 16 * HD);
        }
    };

    LOADKV(0, 0);
    cp_commit();
    #pragma unroll
    for (int i = 0; i < 8; i++) {
        int idx = i * 256 + tid;
        int r = idx >> 4, c = (idx & 15) * 4;
        *(uint4*)&Pq[r * QST + c] = *(const uint4*)&Qbase[r * HD + c];
    }
    __syncthreads();

    uint32_t qf[8][4];
    #pragma unroll
    for (int s = 0; s < 8; s++) {
        qf[s][0] = Pq[(wq + g    ) * QST + s * 8 + t];
        qf[s][1] = Pq[(wq + g + 8) * QST + s * 8 + t];
        qf[s][2] = Pq[(wq + g    ) * QST + s * 8 + t + 4];
        qf[s][3] = Pq[(wq + g + 8) * QST + s * 8 + t + 4];
    }

    float o[8][4];
    #pragma unroll
    for (int ni = 0; ni < 8; ni++)
        #pragma unroll
        for (int r = 0; r < 4; r++) o[ni][r] = 0.f;
    float m0 = -1e30f, m1 = -1e30f, l0 = 0.f, l1 = 0.f;

    const int ntiles = qt * 2 + 2;
    for (int tt = 0; tt < ntiles; tt++) {
        const int buf = tt & 1;
        if (tt + 1 < ntiles) {
            LOADKV((tt + 1) * 64, buf ^ 1);
            cp_commit();
            cp_wait<1>();
        } else {
            cp_wait<0>();
        }
        __syncthreads();

        const uint32_t* Ksb = Ks + buf * 64 * QST;
        const uint32_t* Vsb = Vs + buf * 64 * VST;
        const int k0 = tt * 64;

        float s[8][4];
        #pragma unroll
        for (int ni = 0; ni < 8; ni++)
            #pragma unroll
            for (int r = 0; r < 4; r++) s[ni][r] = 0.f;

        #pragma unroll
        for (int ds = 0; ds < 8; ds++) {
            #pragma unroll
            for (int ni = 0; ni < 8; ni++) {
                uint32_t b0 = Ksb[(ni * 8 + g) * QST + ds * 8 + t];
                uint32_t b1 = Ksb[(ni * 8 + g) * QST + ds * 8 + t + 4];
                mma_tf32(s[ni], qf[ds], b0, b1);
            }
        }

        const bool do_mask = (k0 + 63 > q0);
        const int qg0 = q0 + wq + g, qg1 = qg0 + 8;
        #pragma unroll
        for (int ni = 0; ni < 8; ni++) {
            #pragma unroll
            for (int r = 0; r < 4; r++) {
                float v = s[ni][r] * 0.125f;
                if (do_mask) {
                    int kg = k0 + ni * 8 + 2 * t + (r & 1);
                    int qg = (r >= 2) ? qg1 : qg0;
                    if (kg > qg) v = -1e30f;
                }
                s[ni][r] = v;
            }
        }

        float tm0 = -1e30f, tm1 = -1e30f;
        #pragma unroll
        for (int ni = 0; ni < 8; ni++) {
            tm0 = fmaxf(tm0, fmaxf(s[ni][0], s[ni][1]));
            tm1 = fmaxf(tm1, fmaxf(s[ni][2], s[ni][3]));
        }
        tm0 = fmaxf(tm0, __shfl_xor_sync(0xffffffffu, tm0, 1));
        tm0 = fmaxf(tm0, __shfl_xor_sync(0xffffffffu, tm0, 2));
        tm1 = fmaxf(tm1, __shfl_xor_sync(0xffffffffu, tm1, 1));
        tm1 = fmaxf(tm1, __shfl_xor_sync(0xffffffffu, tm1, 2));

        float mn0 = fmaxf(m0, tm0), mn1 = fmaxf(m1, tm1);
        float a0 = __expf(m0 - mn0), a1 = __expf(m1 - mn1);
        m0 = mn0; m1 = mn1;

        float rs0 = 0.f, rs1 = 0.f;
        #pragma unroll
        for (int ni = 0; ni < 8; ni++) {
            s[ni][0] = __expf(s[ni][0] - mn0);
            s[ni][1] = __expf(s[ni][1] - mn0);
            s[ni][2] = __expf(s[ni][2] - mn1);
            s[ni][3] = __expf(s[ni][3] - mn1);
            rs0 += s[ni][0] + s[ni][1];
            rs1 += s[ni][2] + s[ni][3];
        }
        rs0 += __shfl_xor_sync(0xffffffffu, rs0, 1);
        rs0 += __shfl_xor_sync(0xffffffffu, rs0, 2);
        rs1 += __shfl_xor_sync(0xffffffffu, rs1, 1);
        rs1 += __shfl_xor_sync(0xffffffffu, rs1, 2);
        l0 = l0 * a0 + rs0;
        l1 = l1 * a1 + rs1;

        #pragma unroll
        for (int ni = 0; ni < 8; ni++) {
            o[ni][0] *= a0; o[ni][1] *= a0;
            o[ni][2] *= a1; o[ni][3] *= a1;
        }

        #pragma unroll
        for (int ni = 0; ni < 8; ni++) {
            uint2 w0 = make_uint2(f2tf(s[ni][0]), f2tf(s[ni][1]));
            uint2 w1 = make_uint2(f2tf(s[ni][2]), f2tf(s[ni][3]));
            *(uint2*)&Pq[(wq + g    ) * QST + ni * 8 + 2 * t] = w0;
            *(uint2*)&Pq[(wq + g + 8) * QST + ni * 8 + 2 * t] = w1;
        }
        __syncwarp();

        #pragma unroll
        for (int ks = 0; ks < 8; ks++) {
            uint32_t a[4];
            a[0] = Pq[(wq + g    ) * QST + ks * 8 + t];
            a[1] = Pq[(wq + g + 8) * QST + ks * 8 + t];
            a[2] = Pq[(wq + g    ) * QST + ks * 8 + t + 4];
            a[3] = Pq[(wq + g + 8) * QST + ks * 8 + t + 4];
            #pragma unroll
            for (int ni = 0; ni < 8; ni++) {
                uint32_t b0 = Vsb[(ks * 8 + t    ) * VST + ni * 8 + g];
                uint32_t b1 = Vsb[(ks * 8 + t + 4) * VST + ni * 8 + g];
                mma_tf32(o[ni], a, b0, b1);
            }
        }
        __syncthreads();
    }

    // epilogue: ctx written directly as tf32 (feeds Wo GEMM)
    float inv0 = 1.f / l0, inv1 = 1.f / l1;
    const int qg0 = q0 + wq + g, qg1 = qg0 + 8;
    #pragma unroll
    for (int ni = 0; ni < 8; ni++) {
        int c = h * HD + ni * 8 + 2 * t;
        *(uint2*)&ctx[(size_t)(b * SEQ + qg0) * DOUT + c] =
            make_uint2(f2tf(o[ni][0] * inv0), f2tf(o[ni][1] * inv0));
        *(uint2*)&ctx[(size_t)(b * SEQ + qg1) * DOUT + c] =
            make_uint2(f2tf(o[ni][2] * inv1), f2tf(o[ni][3] * inv1));
    }
}

// ------------------------------- launcher -------------------------------------
extern "C" void kernel_launch(void* const* d_in, const int* in_sizes, int n_in,
                              void* d_out, int out_size)
{
    const float* x    = (const float*)d_in[0];
    const float* Wq   = (const float*)d_in[1];
    const float* Wk   = (const float*)d_in[2];
    const float* Wv   = (const float*)d_in[3];
    const float* Wo   = (const float*)d_in[4];
    const float* cosb = (const float*)d_in[5];
    const float* sinb = (const float*)d_in[6];
    float* out = (float*)d_out;

    uint32_t *pWqt, *pWkt, *pWvt, *pWot, *pQr, *pKr, *pVr, *pCtx;
    cudaGetSymbolAddress((void**)&pWqt, g_Wqt);
    cudaGetSymbolAddress((void**)&pWkt, g_Wkt);
    cudaGetSymbolAddress((void**)&pWvt, g_Wvt);
    cudaGetSymbolAddress((void**)&pWot, g_Wot);
    cudaGetSymbolAddress((void**)&pQr,  g_Qr);
    cudaGetSymbolAddress((void**)&pKr,  g_Kr);
    cudaGetSymbolAddress((void**)&pVr,  g_Vr);
    cudaGetSymbolAddress((void**)&pCtx, g_ctx);

    dim3 thr(256);

    cudaFuncSetAttribute(qkv_tc,   cudaFuncAttributeMaxDynamicSharedMemorySize, SGEMM_SMEM);
    cudaFuncSetAttribute(sgemm_tc, cudaFuncAttributeMaxDynamicSharedMemorySize, SGEMM_SMEM);
    cudaFuncSetAttribute(attn_tc,  cudaFuncAttributeMaxDynamicSharedMemorySize, ATTN_SMEM);

    // fused weight tf32 pre-conversion (Wq|Wk|Wv|Wo in one launch)
    cvt_weights_k<<<(2*NQ4 + 2*NK4) / 256, thr>>>(
        (const float4*)Wq, (const float4*)Wk, (const float4*)Wv, (const float4*)Wo,
        (uint4*)pWqt, (uint4*)pWkt, (uint4*)pWvt, (uint4*)pWot);

    // fused QKV projection + RoPE + head-transpose
    qkv_tc<<<dim3(24, ROWS/128), thr, SGEMM_SMEM>>>(
        x, pWqt, pWkt, pWvt, cosb, sinb, pQr, pKr, pVr);

    // causal flash attention
    attn_tc<<<dim3(SEQ/128, BATCH*NH), thr, ATTN_SMEM>>>(pQr, pKr, pVr, pCtx);

    // output projection
    sgemm_tc<<<dim3(DOUT/128, ROWS/128), thr, SGEMM_SMEM>>>(pCtx, pWot, out, ROWS, DOUT, DIN);
}

// round 8
// speedup vs baseline: 1.2568x; 1.0317x over previous
#include <cuda_runtime.h>
#include <math.h>
#include <stdint.h>

#define BATCH 2
#define SEQ   2048
#define DIN   2048
#define DOUT  2048
#define NH    32
#define NKV   8
#define HD    64
#define ROWS  (BATCH*SEQ)    /* 4096 */
#define DKV   (NKV*HD)       /* 512  */

// ---------------- scratch (static device arrays; no allocation) ----------------
__device__ uint32_t g_xt [ROWS*DIN];    // x in tf32 (row-major)
__device__ uint32_t g_Wqt[DIN*DOUT];    // Wq tf32, packed [K/8][N][8]
__device__ uint32_t g_Wkt[DIN*DKV];     // Wk tf32, packed
__device__ uint32_t g_Wvt[DIN*DKV];     // Wv tf32, packed
__device__ uint32_t g_Wot[DOUT*DOUT];   // Wo tf32, packed
__device__ uint32_t g_Qr [ROWS*DOUT];   // [B,NH,S,HD]  tf32
__device__ uint32_t g_Kr [ROWS*DKV];    // [B,NKV,S,HD] tf32
__device__ uint32_t g_Vr [ROWS*DKV];    // [B,NKV,S/2,HD,2] tf32 key-pair interleaved
__device__ uint32_t g_ctx[ROWS*DOUT];   // [B*S, NH*HD] tf32

__device__ __forceinline__ uint32_t f2tf(float f) {
    uint32_t r;
    asm("cvt.rna.tf32.f32 %0, %1;" : "=r"(r) : "f"(f));
    return r;
}

__device__ __forceinline__ void mma_tf32(float* c, const uint32_t* a,
                                         uint32_t b0, uint32_t b1) {
    asm volatile(
        "mma.sync.aligned.m16n8k8.row.col.f32.tf32.tf32.f32 "
        "{%0,%1,%2,%3}, {%4,%5,%6,%7}, {%8,%9}, {%0,%1,%2,%3};"
        : "+f"(c[0]), "+f"(c[1]), "+f"(c[2]), "+f"(c[3])
        : "r"(a[0]), "r"(a[1]), "r"(a[2]), "r"(a[3]), "r"(b0), "r"(b1));
}

__device__ __forceinline__ void cp16(uint32_t smem_byte, const void* g) {
    asm volatile("cp.async.cg.shared.global [%0], [%1], 16;\n"
                 :: "r"(smem_byte), "l"(g));
}
__device__ __forceinline__ void cp_commit() {
    asm volatile("cp.async.commit_group;\n" ::);
}
template <int N>
__device__ __forceinline__ void cp_wait() {
    asm volatile("cp.async.wait_group %0;\n" :: "n"(N));
}

// ---------------- x fp32 -> tf32 (plain layout) --------------------------------
__global__ __launch_bounds__(256) void cvt_x_k(const float4* __restrict__ in,
                                               uint4* __restrict__ out, int n4)
{
    int i = blockIdx.x * blockDim.x + threadIdx.x;
    if (i < n4) {
        float4 v = in[i];
        out[i] = make_uint4(f2tf(v.x), f2tf(v.y), f2tf(v.z), f2tf(v.w));
    }
}

// ---------------- weight repack: [K][N] fp32 -> [K/8][N][8] tf32 ---------------
__global__ __launch_bounds__(256) void repack_w_k(const float* __restrict__ W,
                                                  uint32_t* __restrict__ out,
                                                  int N, int lgN)
{
    int i = blockIdx.x * blockDim.x + threadIdx.x;   // i = kb*N + n
    int n  = i & (N - 1);
    int kb = i >> lgN;
    const float* src = W + (size_t)(kb * 8) * N + n;
    uint32_t v[8];
    #pragma unroll
    for (int j = 0; j < 8; j++) v[j] = f2tf(src[(size_t)j * N]);
    uint4* dst = (uint4*)(out + (size_t)i * 8);
    dst[0] = make_uint4(v[0], v[1], v[2], v[3]);
    dst[1] = make_uint4(v[4], v[5], v[6], v[7]);
}

// smem geometry
#define AST 40                      /* A row stride (words): bank 8g+2t, conflict-free */
#define BTILE 4096                  /* B buffer: [4 ksb][128 n][8] words */
#define SGEMM_SMEM ((2*128*AST + 2*BTILE) * 4)   /* 73728 bytes */

// ================= fused QKV projection + RoPE + transpose =====================
// A = x (tf32), B = packed weights. grid (24, 32): bx<16 Q, <20 K, else V.
__global__ __launch_bounds__(256, 2) void qkv_tc(
    const uint32_t* __restrict__ x,
    const uint32_t* __restrict__ Wq, const uint32_t* __restrict__ Wk,
    const uint32_t* __restrict__ Wv,
    const float* __restrict__ cosb, const float* __restrict__ sinb,
    uint32_t* __restrict__ Qr, uint32_t* __restrict__ Kr,
    uint32_t* __restrict__ Vr)
{
    extern __shared__ uint32_t smu[];
    uint32_t* As = smu;                    // [2][128][40]
    uint32_t* Bs = smu + 2 * 128 * AST;    // [2][4][128][8]

    const int bx = blockIdx.x;
    const uint32_t* W; uint32_t* outp; int N, col0, nh, kind;
    if (bx < 16)      { W = Wq; outp = Qr; N = DOUT; col0 = bx * 128;        nh = NH;  kind = 0; }
    else if (bx < 20) { W = Wk; outp = Kr; N = DKV;  col0 = (bx - 16) * 128; nh = NKV; kind = 0; }
    else              { W = Wv; outp = Vr; N = DKV;  col0 = (bx - 20) * 128; nh = NKV; kind = 1; }

    const int tid  = threadIdx.x;
    const int warp = tid >> 5, lane = tid & 31;
    const int g    = lane >> 2, t = lane & 3;
    const int wm   = (warp & 3) * 32;
    const int wn   = (warp >> 2) * 64;
    const int row0 = blockIdx.y * 128;

    const uint32_t sA = (uint32_t)__cvta_generic_to_shared(As);
    const uint32_t sB = (uint32_t)__cvta_generic_to_shared(Bs);

    const int a_r = tid >> 3, a_c = (tid & 7) * 4;      // A: 32 rows/pass, 4 passes
    const int b_n = tid >> 1, b_h = (tid & 1) * 4;      // B: 1 ksb/pass, 4 passes

    auto LOAD = [&](int k0, int buf) {
        const uint32_t* ap = x + (size_t)(row0 + a_r) * DIN + k0 + a_c;
        uint32_t da = sA + (uint32_t)(buf * 128 * AST + a_r * AST + a_c) * 4;
        #pragma unroll
        for (int i = 0; i < 4; i++)
            cp16(da + i * 32 * AST * 4, ap + (size_t)i * 32 * DIN);
        uint32_t db = sB + (uint32_t)(buf * BTILE + b_n * 8 + b_h) * 4;
        const uint32_t* bp = W + ((size_t)(k0 >> 3) * N + col0 + b_n) * 8 + b_h;
        #pragma unroll
        for (int i = 0; i < 4; i++)
            cp16(db + i * 1024 * 4, bp + (size_t)i * N * 8);
    };

    float acc[2][8][4];
    #pragma unroll
    for (int mi = 0; mi < 2; mi++)
        #pragma unroll
        for (int ni = 0; ni < 8; ni++)
            #pragma unroll
            for (int r = 0; r < 4; r++) acc[mi][ni][r] = 0.f;

    LOAD(0, 0);
    cp_commit();

    const int niter = DIN / 32;
    for (int it = 0; it < niter; it++) {
        const int buf = it & 1;
        if (it + 1 < niter) {
            LOAD((it + 1) * 32, buf ^ 1);
            cp_commit();
            cp_wait<1>();
        } else {
            cp_wait<0>();
        }
        __syncthreads();

        const uint32_t* Asb = As + buf * 128 * AST;
        const uint32_t* Bsb = Bs + buf * BTILE;
        #pragma unroll
        for (int ks = 0; ks < 4; ks++) {
            uint32_t a[2][4]; uint2 bb[8];
            #pragma unroll
            for (int mi = 0; mi < 2; mi++) {
                const int m0 = wm + mi * 16 + g;
                uint2 lo = *(const uint2*)&Asb[(m0    ) * AST + ks * 8 + 2 * t];
                uint2 hi = *(const uint2*)&Asb[(m0 + 8) * AST + ks * 8 + 2 * t];
                a[mi][0] = lo.x; a[mi][1] = hi.x; a[mi][2] = lo.y; a[mi][3] = hi.y;
            }
            #pragma unroll
            for (int ni = 0; ni < 8; ni++) {
                const int n0 = wn + ni * 8 + g;
                bb[ni] = *(const uint2*)&Bsb[ks * 1024 + n0 * 8 + 2 * t];
            }
            #pragma unroll
            for (int mi = 0; mi < 2; mi++)
                #pragma unroll
                for (int ni = 0; ni < 8; ni++)
                    mma_tf32(acc[mi][ni], a[mi], bb[ni].x, bb[ni].y);
        }
        __syncthreads();
    }

    // ---- epilogue
    const int hq = (col0 + wn) >> 6;
    #pragma unroll
    for (int mi = 0; mi < 2; mi++) {
        const int rbase = row0 + wm + mi * 16 + g;
        #pragma unroll
        for (int v = 0; v < 2; v++) {
            const int r = rbase + v * 8;
            const int b = r >> 11, s = r & 2047;
            uint32_t* op = outp + (size_t)(b * nh + hq) * SEQ * HD;
            if (kind == 0) {           // Q or K: RoPE, logical [s][d] layout
                uint32_t* row = op + (size_t)s * HD;
                #pragma unroll
                for (int ni = 0; ni < 4; ni++) {
                    const int d = ni * 8 + 2 * t;
                    float x1a = acc[mi][ni    ][v*2], x1b = acc[mi][ni    ][v*2+1];
                    float x2a = acc[mi][ni + 4][v*2], x2b = acc[mi][ni + 4][v*2+1];
                    float2 c1 = *(const float2*)&cosb[s * HD + d];
                    float2 s1 = *(const float2*)&sinb[s * HD + d];
                    float2 c2 = *(const float2*)&cosb[s * HD + d + 32];
                    float2 s2 = *(const float2*)&sinb[s * HD + d + 32];
                    *(uint2*)&row[d]      = make_uint2(f2tf(x1a * c1.x - x2a * s1.x),
                                                       f2tf(x1b * c1.y - x2b * s1.y));
                    *(uint2*)&row[d + 32] = make_uint2(f2tf(x2a * c2.x + x1a * s2.x),
                                                       f2tf(x2b * c2.y + x1b * s2.y));
                }
            } else {                   // V: key-pair interleaved [s/2][d][2]
                uint32_t* rowp = op + ((size_t)(s >> 1) * HD) * 2 + (s & 1);
                #pragma unroll
                for (int ni = 0; ni < 8; ni++) {
                    const int d = ni * 8 + 2 * t;
                    rowp[(size_t)d * 2]       = f2tf(acc[mi][ni][v*2]);
                    rowp[(size_t)(d + 1) * 2] = f2tf(acc[mi][ni][v*2+1]);
                }
            }
        }
    }
}

// ================= tf32 GEMM (output projection) ===============================
// A = ctx (tf32 row-major), B = packed Wo, C fp32.
__global__ __launch_bounds__(256, 2) void sgemm_tc(
    const uint32_t* __restrict__ A, const uint32_t* __restrict__ B,
    float* __restrict__ C, int M, int N, int K)
{
    extern __shared__ uint32_t smu[];
    uint32_t* As = smu;
    uint32_t* Bs = smu + 2 * 128 * AST;

    const int tid  = threadIdx.x;
    const int warp = tid >> 5, lane = tid & 31;
    const int g    = lane >> 2, t = lane & 3;
    const int wm   = (warp & 3) * 32;
    const int wn   = (warp >> 2) * 64;
    const int row0 = blockIdx.y * 128, col0 = blockIdx.x * 128;

    const uint32_t sA = (uint32_t)__cvta_generic_to_shared(As);
    const uint32_t sB = (uint32_t)__cvta_generic_to_shared(Bs);

    const int a_r = tid >> 3, a_c = (tid & 7) * 4;
    const int b_n = tid >> 1, b_h = (tid & 1) * 4;

    auto LOAD = [&](int k0, int buf) {
        const uint32_t* ap = A + (size_t)(row0 + a_r) * K + k0 + a_c;
        uint32_t da = sA + (uint32_t)(buf * 128 * AST + a_r * AST + a_c) * 4;
        #pragma unroll
        for (int i = 0; i < 4; i++)
            cp16(da + i * 32 * AST * 4, ap + (size_t)i * 32 * K);
        uint32_t db = sB + (uint32_t)(buf * BTILE + b_n * 8 + b_h) * 4;
        const uint32_t* bp = B + ((size_t)(k0 >> 3) * N + col0 + b_n) * 8 + b_h;
        #pragma unroll
        for (int i = 0; i < 4; i++)
            cp16(db + i * 1024 * 4, bp + (size_t)i * N * 8);
    };

    float acc[2][8][4];
    #pragma unroll
    for (int mi = 0; mi < 2; mi++)
        #pragma unroll
        for (int ni = 0; ni < 8; ni++)
            #pragma unroll
            for (int r = 0; r < 4; r++) acc[mi][ni][r] = 0.f;

    LOAD(0, 0);
    cp_commit();

    const int niter = K / 32;
    for (int it = 0; it < niter; it++) {
        const int buf = it & 1;
        if (it + 1 < niter) {
            LOAD((it + 1) * 32, buf ^ 1);
            cp_commit();
            cp_wait<1>();
        } else {
            cp_wait<0>();
        }
        __syncthreads();

        const uint32_t* Asb = As + buf * 128 * AST;
        const uint32_t* Bsb = Bs + buf * BTILE;
        #pragma unroll
        for (int ks = 0; ks < 4; ks++) {
            uint32_t a[2][4]; uint2 bb[8];
            #pragma unroll
            for (int mi = 0; mi < 2; mi++) {
                const int m0 = wm + mi * 16 + g;
                uint2 lo = *(const uint2*)&Asb[(m0    ) * AST + ks * 8 + 2 * t];
                uint2 hi = *(const uint2*)&Asb[(m0 + 8) * AST + ks * 8 + 2 * t];
                a[mi][0] = lo.x; a[mi][1] = hi.x; a[mi][2] = lo.y; a[mi][3] = hi.y;
            }
            #pragma unroll
            for (int ni = 0; ni < 8; ni++) {
                const int n0 = wn + ni * 8 + g;
                bb[ni] = *(const uint2*)&Bsb[ks * 1024 + n0 * 8 + 2 * t];
            }
            #pragma unroll
            for (int mi = 0; mi < 2; mi++)
                #pragma unroll
                for (int ni = 0; ni < 8; ni++)
                    mma_tf32(acc[mi][ni], a[mi], bb[ni].x, bb[ni].y);
        }
        __syncthreads();
    }

    #pragma unroll
    for (int mi = 0; mi < 2; mi++)
        #pragma unroll
        for (int ni = 0; ni < 8; ni++) {
            const int r = row0 + wm + mi * 16 + g;
            const int c = col0 + wn + ni * 8 + t * 2;
            *(float2*)(C + (size_t)r * N + c) =
                make_float2(acc[mi][ni][0], acc[mi][ni][1]);
            *(float2*)(C + (size_t)(r + 8) * N + c) =
                make_float2(acc[mi][ni][2], acc[mi][ni][3]);
        }
}

// ================= tf32 flash attention ========================================
#define QST 72
#define VSTP 136
#define ATTN_SMEM ((128*QST + 2*64*QST + 2*32*VSTP) * 4)   /* 108544 bytes */

__global__ __launch_bounds__(256) void attn_tc(
    const uint32_t* __restrict__ Qr, const uint32_t* __restrict__ Kr,
    const uint32_t* __restrict__ Vr, uint32_t* __restrict__ ctx)
{
    extern __shared__ uint32_t smu[];
    uint32_t* Pq = smu;                   // [128][72]  Q staging, then P
    uint32_t* Ks = smu + 128 * QST;       // [2][64][72]
    uint32_t* Vs = Ks  + 2 * 64 * QST;    // [2][32][136] key-pair rows

    const int bh = blockIdx.y;
    const int b = bh >> 5, h = bh & 31, g2 = h >> 2;
    const int qt = gridDim.x - 1 - blockIdx.x;
    const int q0 = qt * 128;
    const int tid = threadIdx.x;
    const int warp = tid >> 5, lane = tid & 31;
    const int g = lane >> 2, t = lane & 3;
    const int wq = warp * 16;

    const uint32_t* Qbase = Qr + ((size_t)bh * SEQ + q0) * HD;
    const uint32_t* Kbase = Kr + (size_t)(b * NKV + g2) * SEQ * HD;
    const uint32_t* Vbase = Vr + (size_t)(b * NKV + g2) * SEQ * HD;   // pair layout

    const uint32_t sK = (uint32_t)__cvta_generic_to_shared(Ks);
    const uint32_t sV = (uint32_t)__cvta_generic_to_shared(Vs);

    const int kr = tid >> 4, kc = (tid & 15) * 4;    // K: 16 rows/pass ×4
    const int vr = tid >> 5, vc = (tid & 31) * 4;    // V: 8 pairrows/pass ×4

    auto LOADKV = [&](int k0, int buf) {
        const uint32_t* kp = Kbase + (size_t)(k0 + kr) * HD + kc;
        uint32_t dk = sK + (uint32_t)(buf * 64 * QST + kr * QST + kc) * 4;
        #pragma unroll
        for (int i = 0; i < 4; i++)
            cp16(dk + i * 16 * QST * 4, kp + (size_t)i * 16 * HD);
        const uint32_t* vp = Vbase + ((size_t)(k0 >> 1) + vr) * (HD * 2) + vc;
        uint32_t dv = sV + (uint32_t)(buf * 32 * VSTP + vr * VSTP + vc) * 4;
        #pragma unroll
        for (int i = 0; i < 4; i++)
            cp16(dv + i * 8 * VSTP * 4, vp + (size_t)i * 8 * HD * 2);
    };

    LOADKV(0, 0);
    cp_commit();
    #pragma unroll
    for (int i = 0; i < 8; i++) {
        int idx = i * 256 + tid;
        int r = idx >> 4, c = (idx & 15) * 4;
        *(uint4*)&Pq[r * QST + c] = *(const uint4*)&Qbase[r * HD + c];
    }
    __syncthreads();

    uint32_t qf[8][4];
    #pragma unroll
    for (int s = 0; s < 8; s++) {
        uint2 lo = *(const uint2*)&Pq[(wq + g    ) * QST + s * 8 + 2 * t];
        uint2 hi = *(const uint2*)&Pq[(wq + g + 8) * QST + s * 8 + 2 * t];
        qf[s][0] = lo.x; qf[s][1] = hi.x; qf[s][2] = lo.y; qf[s][3] = hi.y;
    }

    float o[8][4];
    #pragma unroll
    for (int ni = 0; ni < 8; ni++)
        #pragma unroll
        for (int r = 0; r < 4; r++) o[ni][r] = 0.f;
    float m0 = -1e30f, m1 = -1e30f, l0 = 0.f, l1 = 0.f;

    const int ntiles = qt * 2 + 2;
    for (int tt = 0; tt < ntiles; tt++) {
        const int buf = tt & 1;
        if (tt + 1 < ntiles) {
            LOADKV((tt + 1) * 64, buf ^ 1);
            cp_commit();
            cp_wait<1>();
        } else {
            cp_wait<0>();
        }
        __syncthreads();

        const uint32_t* Ksb = Ks + buf * 64 * QST;
        const uint32_t* Vsb = Vs + buf * 32 * VSTP;
        const int k0 = tt * 64;

        // ---- S = Q @ K^T
        float s[8][4];
        #pragma unroll
        for (int ni = 0; ni < 8; ni++)
            #pragma unroll
            for (int r = 0; r < 4; r++) s[ni][r] = 0.f;

        #pragma unroll
        for (int ds = 0; ds < 8; ds++) {
            #pragma unroll
            for (int ni = 0; ni < 8; ni++) {
                uint2 kb2 = *(const uint2*)&Ksb[(ni * 8 + g) * QST + ds * 8 + 2 * t];
                mma_tf32(s[ni], qf[ds], kb2.x, kb2.y);
            }
        }

        // ---- scale + causal mask
        const bool do_mask = (k0 + 63 > q0);
        const int qg0 = q0 + wq + g, qg1 = qg0 + 8;
        #pragma unroll
        for (int ni = 0; ni < 8; ni++) {
            #pragma unroll
            for (int r = 0; r < 4; r++) {
                float v = s[ni][r] * 0.125f;
                if (do_mask) {
                    int kg = k0 + ni * 8 + 2 * t + (r & 1);
                    int qg = (r >= 2) ? qg1 : qg0;
                    if (kg > qg) v = -1e30f;
                }
                s[ni][r] = v;
            }
        }

        // ---- online softmax
        float tm0 = -1e30f, tm1 = -1e30f;
        #pragma unroll
        for (int ni = 0; ni < 8; ni++) {
            tm0 = fmaxf(tm0, fmaxf(s[ni][0], s[ni][1]));
            tm1 = fmaxf(tm1, fmaxf(s[ni][2], s[ni][3]));
        }
        tm0 = fmaxf(tm0, __shfl_xor_sync(0xffffffffu, tm0, 1));
        tm0 = fmaxf(tm0, __shfl_xor_sync(0xffffffffu, tm0, 2));
        tm1 = fmaxf(tm1, __shfl_xor_sync(0xffffffffu, tm1, 1));
        tm1 = fmaxf(tm1, __shfl_xor_sync(0xffffffffu, tm1, 2));

        float mn0 = fmaxf(m0, tm0), mn1 = fmaxf(m1, tm1);
        float a0 = __expf(m0 - mn0), a1 = __expf(m1 - mn1);
        m0 = mn0; m1 = mn1;

        float rs0 = 0.f, rs1 = 0.f;
        #pragma unroll
        for (int ni = 0; ni < 8; ni++) {
            s[ni][0] = __expf(s[ni][0] - mn0);
            s[ni][1] = __expf(s[ni][1] - mn0);
            s[ni][2] = __expf(s[ni][2] - mn1);
            s[ni][3] = __expf(s[ni][3] - mn1);
            rs0 += s[ni][0] + s[ni][1];
            rs1 += s[ni][2] + s[ni][3];
        }
        rs0 += __shfl_xor_sync(0xffffffffu, rs0, 1);
        rs0 += __shfl_xor_sync(0xffffffffu, rs0, 2);
        rs1 += __shfl_xor_sync(0xffffffffu, rs1, 1);
        rs1 += __shfl_xor_sync(0xffffffffu, rs1, 2);
        l0 = l0 * a0 + rs0;
        l1 = l1 * a1 + rs1;

        #pragma unroll
        for (int ni = 0; ni < 8; ni++) {
            o[ni][0] *= a0; o[ni][1] *= a0;
            o[ni][2] *= a1; o[ni][3] *= a1;
        }

        // ---- P -> smem (tf32); key index stays column index
        #pragma unroll
        for (int ni = 0; ni < 8; ni++) {
            *(uint2*)&Pq[(wq + g    ) * QST + ni * 8 + 2 * t] =
                make_uint2(f2tf(s[ni][0]), f2tf(s[ni][1]));
            *(uint2*)&Pq[(wq + g + 8) * QST + ni * 8 + 2 * t] =
                make_uint2(f2tf(s[ni][2]), f2tf(s[ni][3]));
        }
        __syncwarp();

        // ---- O += P @ V  (keys 8ks+2t, 8ks+2t+1 per thread)
        #pragma unroll
        for (int ks = 0; ks < 8; ks++) {
            uint32_t a[4];
            uint2 lo = *(const uint2*)&Pq[(wq + g    ) * QST + ks * 8 + 2 * t];
            uint2 hi = *(const uint2*)&Pq[(wq + g + 8) * QST + ks * 8 + 2 * t];
            a[0] = lo.x; a[1] = hi.x; a[2] = lo.y; a[3] = hi.y;
            #pragma unroll
            for (int ni = 0; ni < 8; ni++) {
                uint2 vb = *(const uint2*)&Vsb[(ks * 4 + t) * VSTP + (ni * 8 + g) * 2];
                mma_tf32(o[ni], a, vb.x, vb.y);
            }
        }
        __syncthreads();
    }

    // ---- epilogue: ctx tf32
    float inv0 = 1.f / l0, inv1 = 1.f / l1;
    const int qg0 = q0 + wq + g, qg1 = qg0 + 8;
    #pragma unroll
    for (int ni = 0; ni < 8; ni++) {
        int c = h * HD + ni * 8 + 2 * t;
        *(uint2*)&ctx[(size_t)(b * SEQ + qg0) * DOUT + c] =
            make_uint2(f2tf(o[ni][0] * inv0), f2tf(o[ni][1] * inv0));
        *(uint2*)&ctx[(size_t)(b * SEQ + qg1) * DOUT + c] =
            make_uint2(f2tf(o[ni][2] * inv1), f2tf(o[ni][3] * inv1));
    }
}

// ------------------------------- launcher -------------------------------------
extern "C" void kernel_launch(void* const* d_in, const int* in_sizes, int n_in,
                              void* d_out, int out_size)
{
    const float* x    = (const float*)d_in[0];
    const float* Wq   = (const float*)d_in[1];
    const float* Wk   = (const float*)d_in[2];
    const float* Wv   = (const float*)d_in[3];
    const float* Wo   = (const float*)d_in[4];
    const float* cosb = (const float*)d_in[5];
    const float* sinb = (const float*)d_in[6];
    float* out = (float*)d_out;

    uint32_t *pXt, *pWqt, *pWkt, *pWvt, *pWot, *pQr, *pKr, *pVr, *pCtx;
    cudaGetSymbolAddress((void**)&pXt,  g_xt);
    cudaGetSymbolAddress((void**)&pWqt, g_Wqt);
    cudaGetSymbolAddress((void**)&pWkt, g_Wkt);
    cudaGetSymbolAddress((void**)&pWvt, g_Wvt);
    cudaGetSymbolAddress((void**)&pWot, g_Wot);
    cudaGetSymbolAddress((void**)&pQr,  g_Qr);
    cudaGetSymbolAddress((void**)&pKr,  g_Kr);
    cudaGetSymbolAddress((void**)&pVr,  g_Vr);
    cudaGetSymbolAddress((void**)&pCtx, g_ctx);

    dim3 thr(256);

    cudaFuncSetAttribute(qkv_tc,   cudaFuncAttributeMaxDynamicSharedMemorySize, SGEMM_SMEM);
    cudaFuncSetAttribute(sgemm_tc, cudaFuncAttributeMaxDynamicSharedMemorySize, SGEMM_SMEM);
    cudaFuncSetAttribute(attn_tc,  cudaFuncAttributeMaxDynamicSharedMemorySize, ATTN_SMEM);

    // pre-conversion / repack
    cvt_x_k<<<(ROWS*DIN/4 + 255)/256, thr>>>((const float4*)x, (uint4*)pXt, ROWS*DIN/4);
    repack_w_k<<<(DIN/8)*DOUT/256, thr>>>(Wq, pWqt, DOUT, 11);
    repack_w_k<<<(DIN/8)*DKV /256, thr>>>(Wk, pWkt, DKV,  9);
    repack_w_k<<<(DIN/8)*DKV /256, thr>>>(Wv, pWvt, DKV,  9);
    repack_w_k<<<(DOUT/8)*DOUT/256, thr>>>(Wo, pWot, DOUT, 11);

    // fused QKV projection + RoPE + head-transpose (+ V pair-interleave)
    qkv_tc<<<dim3(24, ROWS/128), thr, SGEMM_SMEM>>>(
        pXt, pWqt, pWkt, pWvt, cosb, sinb, pQr, pKr, pVr);

    // causal flash attention
    attn_tc<<<dim3(SEQ/128, BATCH*NH), thr, ATTN_SMEM>>>(pQr, pKr, pVr, pCtx);

    // output projection
    sgemm_tc<<<dim3(DOUT/128, ROWS/128), thr, SGEMM_SMEM>>>(pCtx, pWot, out, ROWS, DOUT, DIN);
}

// round 11
// speedup vs baseline: 1.4047x; 1.1177x over previous
#include <cuda_runtime.h>
#include <cuda_fp16.h>
#include <stdint.h>

#define BATCH 2
#define SEQ   2048
#define DIN   2048
#define DOUT  2048
#define NH    32
#define NKV   8
#define HD    64
#define ROWS  (BATCH*SEQ)    /* 4096 */
#define DKV   (NKV*HD)       /* 512  */

// ---------------- scratch (static device arrays; no allocation) ----------------
__device__ __half g_xh [ROWS*DIN];     // x fp16 row-major [M][K]
__device__ __half g_Wqh[DOUT*DIN];     // Wq^T fp16 [N][K]
__device__ __half g_Wkh[DKV*DIN];      // Wk^T fp16 [N][K]
__device__ __half g_Wvh[DKV*DIN];      // Wv^T fp16 [N][K]
__device__ __half g_Woh[DOUT*DOUT];    // Wo^T fp16 [N][K]
__device__ __half g_Qr [ROWS*DOUT];    // [B,NH,S,HD]
__device__ __half g_Kr [ROWS*DKV];     // [B,NKV,S,HD]
__device__ __half g_Vr [ROWS*DKV];     // [B,NKV,S/4,HD,4] quad-interleaved
__device__ __half g_ctx[ROWS*DOUT];    // [B*S, NH*HD]

__device__ __forceinline__ void mma_f16(float* c, const uint32_t* a,
                                        uint32_t b0, uint32_t b1) {
    asm volatile(
        "mma.sync.aligned.m16n8k16.row.col.f32.f16.f16.f32 "
        "{%0,%1,%2,%3}, {%4,%5,%6,%7}, {%8,%9}, {%0,%1,%2,%3};"
        : "+f"(c[0]), "+f"(c[1]), "+f"(c[2]), "+f"(c[3])
        : "r"(a[0]), "r"(a[1]), "r"(a[2]), "r"(a[3]), "r"(b0), "r"(b1));
}

__device__ __forceinline__ void cp16(uint32_t smem_byte, const void* g) {
    asm volatile("cp.async.cg.shared.global [%0], [%1], 16;\n"
                 :: "r"(smem_byte), "l"(g));
}
__device__ __forceinline__ void cp_commit() {
    asm volatile("cp.async.commit_group;\n" ::);
}
template <int N>
__device__ __forceinline__ void cp_wait() {
    asm volatile("cp.async.wait_group %0;\n" :: "n"(N));
}
__device__ __forceinline__ uint32_t smem_u32(const void* p) {
    return (uint32_t)__cvta_generic_to_shared(p);
}

// ---------------- pre-kernels ---------------------------------------------------
__global__ __launch_bounds__(256) void cvt_x_k(const float4* __restrict__ in,
                                               uint4* __restrict__ out, int n8)
{
    int i = blockIdx.x * blockDim.x + threadIdx.x;
    if (i < n8) {
        float4 v0 = in[2 * i], v1 = in[2 * i + 1];
        __half2 h0 = __floats2half2_rn(v0.x, v0.y);
        __half2 h1 = __floats2half2_rn(v0.z, v0.w);
        __half2 h2 = __floats2half2_rn(v1.x, v1.y);
        __half2 h3 = __floats2half2_rn(v1.z, v1.w);
        uint4 u;
        u.x = *(uint32_t*)&h0; u.y = *(uint32_t*)&h1;
        u.z = *(uint32_t*)&h2; u.w = *(uint32_t*)&h3;
        out[i] = u;
    }
}

// W [K][N] fp32 -> Wt [N][K] fp16 (tiled transpose)
__global__ __launch_bounds__(256) void wtrans_k(const float* __restrict__ W,
                                                __half* __restrict__ out,
                                                int K, int N)
{
    __shared__ __half t[32][34];
    int kb = blockIdx.x * 32, nb = blockIdx.y * 32;
    int tx = threadIdx.x & 31, ty = threadIdx.x >> 5;
    #pragma unroll
    for (int i = 0; i < 4; i++)
        t[ty + 8*i][tx] = __float2half_rn(W[(size_t)(kb + ty + 8*i) * N + nb + tx]);
    __syncthreads();
    #pragma unroll
    for (int i = 0; i < 4; i++)
        out[(size_t)(nb + ty + 8*i) * K + kb + tx] = t[tx][ty + 8*i];
}

// ================= fp16 GEMM mainloop (128x128 tile, k-tile 64) ================
// smem: A [2][4 kb][128][16 halves] 32KB, then B same 32KB. Total 64KB.
#define GEMM_SMEM 65536

__device__ __forceinline__ void gemm_mainloop_h(
    const __half* __restrict__ A, const __half* __restrict__ Bt,
    int K, int row0, int col0, char* smem, float acc[2][8][4])
{
    const int tid  = threadIdx.x;
    const int lane = tid & 31, warp = tid >> 5;
    const int g = lane >> 2, t = lane & 3;
    const int wm = (warp & 3) * 32, wn = (warp >> 2) * 64;
    const uint32_t sA = smem_u32(smem);
    const uint32_t sB = sA + 32768;

    const int a_r = tid >> 1;
    const int c8b = (tid & 1) * 4;

    auto LOAD = [&](int k0, int buf) {
        #pragma unroll
        for (int j = 0; j < 4; j++) {
            const int c8 = c8b + j;
            const int kb = c8 >> 1, part = c8 & 1;
            const uint32_t off = (uint32_t)(buf * 16384 + (kb * 128 + a_r) * 32 + part * 16);
            cp16(sA + off, A  + (size_t)(row0 + a_r) * K + k0 + c8 * 8);
            cp16(sB + off, Bt + (size_t)(col0 + a_r) * K + k0 + c8 * 8);
        }
        cp_commit();
    };

    #pragma unroll
    for (int mi = 0; mi < 2; mi++)
        #pragma unroll
        for (int ni = 0; ni < 8; ni++)
            #pragma unroll
            for (int r = 0; r < 4; r++) acc[mi][ni][r] = 0.f;

    LOAD(0, 0);

    const int niter = K / 64;
    for (int it = 0; it < niter; it++) {
        const int buf = it & 1;
        if (it + 1 < niter) {
            LOAD((it + 1) * 64, buf ^ 1);
            cp_wait<1>();
        } else {
            cp_wait<0>();
        }
        __syncthreads();

        const char* Ab = smem + buf * 16384;
        const char* Bb = smem + 32768 + buf * 16384;
        #pragma unroll
        for (int kb = 0; kb < 4; kb++) {
            uint32_t a[2][4]; uint2 bb[8];
            #pragma unroll
            for (int mi = 0; mi < 2; mi++) {
                const char* base = Ab + (kb * 128 + wm + mi * 16 + g) * 32 + t * 8;
                uint2 lo = *(const uint2*)base;
                uint2 hi = *(const uint2*)(base + 8 * 32);
                a[mi][0] = lo.x; a[mi][1] = hi.x; a[mi][2] = lo.y; a[mi][3] = hi.y;
            }
            #pragma unroll
            for (int ni = 0; ni < 8; ni++)
                bb[ni] = *(const uint2*)(Bb + (kb * 128 + wn + ni * 8 + g) * 32 + t * 8);
            #pragma unroll
            for (int mi = 0; mi < 2; mi++)
                #pragma unroll
                for (int ni = 0; ni < 8; ni++)
                    mma_f16(acc[mi][ni], a[mi], bb[ni].x, bb[ni].y);
        }
        __syncthreads();
    }
}

// ================= fused QKV projection + RoPE + transpose =====================
// grid (24, 32): bx<16 Q, <20 K, else V.
__global__ __launch_bounds__(256, 2) void qkv_h(
    const __half* __restrict__ xh,
    const __half* __restrict__ Wqh, const __half* __restrict__ Wkh,
    const __half* __restrict__ Wvh,
    const float* __restrict__ cosb, const float* __restrict__ sinb,
    __half* __restrict__ Qr, __half* __restrict__ Kr, __half* __restrict__ Vr)
{
    extern __shared__ char smem[];
    const int bx = blockIdx.x;
    const __half* W; __half* outp; int col0, nh, kind;
    if (bx < 16)      { W = Wqh; outp = Qr; col0 = bx * 128;        nh = NH;  kind = 0; }
    else if (bx < 20) { W = Wkh; outp = Kr; col0 = (bx - 16) * 128; nh = NKV; kind = 0; }
    else              { W = Wvh; outp = Vr; col0 = (bx - 20) * 128; nh = NKV; kind = 1; }
    const int row0 = blockIdx.y * 128;

    float acc[2][8][4];
    gemm_mainloop_h(xh, W, DIN, row0, col0, smem, acc);

    const int lane = threadIdx.x & 31, warp = threadIdx.x >> 5;
    const int g = lane >> 2, t = lane & 3;
    const int wm = (warp & 3) * 32, wn = (warp >> 2) * 64;
    const int hq = (col0 + wn) >> 6;

    #pragma unroll
    for (int mi = 0; mi < 2; mi++) {
        const int rbase = row0 + wm + mi * 16 + g;
        #pragma unroll
        for (int v = 0; v < 2; v++) {
            const int r = rbase + v * 8;
            const int b = r >> 11, s = r & 2047;
            if (kind == 0) {
                __half* row = outp + ((size_t)(b * nh + hq) * SEQ + s) * HD;
                const float* cs = cosb + s * HD;
                const float* sn = sinb + s * HD;
                #pragma unroll
                for (int ni = 0; ni < 4; ni++) {
                    const int d = ni * 8 + 2 * t;
                    float x1a = acc[mi][ni    ][v*2], x1b = acc[mi][ni    ][v*2+1];
                    float x2a = acc[mi][ni + 4][v*2], x2b = acc[mi][ni + 4][v*2+1];
                    float2 c1 = *(const float2*)&cs[d];
                    float2 s1 = *(const float2*)&sn[d];
                    float2 c2 = *(const float2*)&cs[d + 32];
                    float2 s2 = *(const float2*)&sn[d + 32];
                    *(__half2*)&row[d] =
                        __floats2half2_rn(x1a * c1.x - x2a * s1.x,
                                          x1b * c1.y - x2b * s1.y);
                    *(__half2*)&row[d + 32] =
                        __floats2half2_rn(x2a * c2.x + x1a * s2.x,
                                          x2b * c2.y + x1b * s2.y);
                }
            } else {
                // V quad-interleave: [S/4][HD][4]
                __half* hb = outp + (size_t)(b * nh + hq) * SEQ * HD;
                const size_t sb = (size_t)(s >> 2) * (HD * 4) + (s & 3);
                #pragma unroll
                for (int ni = 0; ni < 8; ni++) {
                    const int d = ni * 8 + 2 * t;
                    hb[sb + (size_t)d * 4]       = __float2half_rn(acc[mi][ni][v*2]);
                    hb[sb + (size_t)(d + 1) * 4] = __float2half_rn(acc[mi][ni][v*2+1]);
                }
            }
        }
    }
}

// ================= output projection ===========================================
__global__ __launch_bounds__(256, 2) void wo_h(
    const __half* __restrict__ ctx, const __half* __restrict__ Woh,
    float* __restrict__ out)
{
    extern __shared__ char smem[];
    const int row0 = blockIdx.y * 128, col0 = blockIdx.x * 128;

    float acc[2][8][4];
    gemm_mainloop_h(ctx, Woh, DOUT, row0, col0, smem, acc);

    const int lane = threadIdx.x & 31, warp = threadIdx.x >> 5;
    const int g = lane >> 2, t = lane & 3;
    const int wm = (warp & 3) * 32, wn = (warp >> 2) * 64;

    #pragma unroll
    for (int mi = 0; mi < 2; mi++)
        #pragma unroll
        for (int ni = 0; ni < 8; ni++) {
            const int r = row0 + wm + mi * 16 + g;
            const int c = col0 + wn + ni * 8 + t * 2;
            *(float2*)(out + (size_t)r * DOUT + c) =
                make_float2(acc[mi][ni][0], acc[mi][ni][1]);
            *(float2*)(out + (size_t)(r + 8) * DOUT + c) =
                make_float2(acc[mi][ni][2], acc[mi][ni][3]);
        }
}

// ================= fp16 flash attention ========================================
// Q/K smem stride 80 halves (160B); V smem stride 272 halves (544B) per 4-key blk.
#define KTB 10240                 /* 64*160 */
#define VTB 8704                  /* 16*544 */
#define ATTN_SMEM (20480 + 2*KTB + 2*VTB)   /* 58368 */

__global__ __launch_bounds__(256) void attn_h(
    const __half* __restrict__ Qr, const __half* __restrict__ Kr,
    const __half* __restrict__ Vr, __half* __restrict__ ctx)
{
    extern __shared__ char sm[];
    char* Pq = sm;                 // [128][160B]  Q staging, then P
    char* Ks = sm + 20480;         // [2][64][160B]
    char* Vs = sm + 20480 + 2 * KTB;   // [2][16][544B]

    const int bh = blockIdx.y;
    const int b = bh >> 5, h = bh & 31, g2 = h >> 2;
    const int qt = gridDim.x - 1 - blockIdx.x;     // heavy tiles first
    const int q0 = qt * 128;
    const int tid = threadIdx.x;
    const int warp = tid >> 5, lane = tid & 31;
    const int g = lane >> 2, t = lane & 3;
    const int wq = warp * 16;

    const __half* Qbase = Qr + ((size_t)bh * SEQ + q0) * HD;
    const __half* Kbase = Kr + (size_t)(b * NKV + g2) * SEQ * HD;
    const __half* Vbase = Vr + (size_t)(b * NKV + g2) * SEQ * HD;   // quad layout

    const uint32_t sK = smem_u32(Ks);
    const uint32_t sV = smem_u32(Vs);
    const uint32_t sP = smem_u32(Pq);

    auto LOADKV = [&](int k0, int buf) {
        #pragma unroll
        for (int i = 0; i < 2; i++) {
            const int ch = tid + i * 256;
            const int row = ch >> 3, c8 = ch & 7;
            cp16(sK + (uint32_t)(buf * KTB + row * 160 + c8 * 16),
                 Kbase + (size_t)(k0 + row) * HD + c8 * 8);
            const int sblk = ch >> 5, c = ch & 31;
            cp16(sV + (uint32_t)(buf * VTB + sblk * 544 + c * 16),
                 Vbase + (size_t)k0 * 64 + sblk * 256 + c * 8);
        }
        cp_commit();
    };

    // stage Q FIRST (its group must drain before qf reads), then prefetch KV0.
    // wait_group<1> then drains Q (older) while KV0 (newest) may still fly.
    #pragma unroll
    for (int i = 0; i < 4; i++) {
        const int ch = tid + i * 256;
        const int row = ch >> 3, c8 = ch & 7;
        cp16(sP + (uint32_t)(row * 160 + c8 * 16), Qbase + (size_t)row * HD + c8 * 8);
    }
    cp_commit();
    LOADKV(0, 0);
    cp_wait<1>();   // Q done; KV0 may still be in flight
    __syncthreads();

    uint32_t qf[4][4];
    #pragma unroll
    for (int ds = 0; ds < 4; ds++) {
        const char* base = Pq + (wq + g) * 160 + ds * 32 + t * 8;
        uint2 lo = *(const uint2*)base;
        uint2 hi = *(const uint2*)(base + 8 * 160);
        qf[ds][0] = lo.x; qf[ds][1] = hi.x; qf[ds][2] = lo.y; qf[ds][3] = hi.y;
    }
    __syncthreads();   // everyone has Q regs before Pq is reused for P

    float o[8][4];
    #pragma unroll
    for (int ni = 0; ni < 8; ni++)
        #pragma unroll
        for (int r = 0; r < 4; r++) o[ni][r] = 0.f;
    float m0 = -1e30f, m1 = -1e30f, l0 = 0.f, l1 = 0.f;

    const int ntiles = qt * 2 + 2;
    for (int tt = 0; tt < ntiles; tt++) {
        const int buf = tt & 1;
        if (tt + 1 < ntiles) {
            LOADKV((tt + 1) * 64, buf ^ 1);
            cp_wait<1>();   // drains KV(tt); KV(tt+1) may fly
        } else {
            cp_wait<0>();
        }
        __syncthreads();

        const char* Ksb = Ks + buf * KTB;
        const char* Vsb = Vs + buf * VTB;
        const int k0 = tt * 64;

        // ---- S = Q @ K^T
        float s[8][4];
        #pragma unroll
        for (int ni = 0; ni < 8; ni++)
            #pragma unroll
            for (int r = 0; r < 4; r++) s[ni][r] = 0.f;

        #pragma unroll
        for (int ds = 0; ds < 4; ds++) {
            #pragma unroll
            for (int ni = 0; ni < 8; ni++) {
                uint2 kb2 = *(const uint2*)(Ksb + (ni * 8 + g) * 160 + ds * 32 + t * 8);
                mma_f16(s[ni], qf[ds], kb2.x, kb2.y);
            }
        }

        // ---- scale + causal mask
        const bool do_mask = (k0 + 63 > q0);
        const int qg0 = q0 + wq + g, qg1 = qg0 + 8;
        #pragma unroll
        for (int ni = 0; ni < 8; ni++) {
            #pragma unroll
            for (int r = 0; r < 4; r++) {
                float v = s[ni][r] * 0.125f;
                if (do_mask) {
                    int kg = k0 + ni * 8 + 2 * t + (r & 1);
                    int qg = (r >= 2) ? qg1 : qg0;
                    if (kg > qg) v = -1e30f;
                }
                s[ni][r] = v;
            }
        }

        // ---- online softmax
        float tm0 = -1e30f, tm1 = -1e30f;
        #pragma unroll
        for (int ni = 0; ni < 8; ni++) {
            tm0 = fmaxf(tm0, fmaxf(s[ni][0], s[ni][1]));
            tm1 = fmaxf(tm1, fmaxf(s[ni][2], s[ni][3]));
        }
        tm0 = fmaxf(tm0, __shfl_xor_sync(0xffffffffu, tm0, 1));
        tm0 = fmaxf(tm0, __shfl_xor_sync(0xffffffffu, tm0, 2));
        tm1 = fmaxf(tm1, __shfl_xor_sync(0xffffffffu, tm1, 1));
        tm1 = fmaxf(tm1, __shfl_xor_sync(0xffffffffu, tm1, 2));

        float mn0 = fmaxf(m0, tm0), mn1 = fmaxf(m1, tm1);
        float a0 = __expf(m0 - mn0), a1 = __expf(m1 - mn1);
        m0 = mn0; m1 = mn1;

        float rs0 = 0.f, rs1 = 0.f;
        #pragma unroll
        for (int ni = 0; ni < 8; ni++) {
            s[ni][0] = __expf(s[ni][0] - mn0);
            s[ni][1] = __expf(s[ni][1] - mn0);
            s[ni][2] = __expf(s[ni][2] - mn1);
            s[ni][3] = __expf(s[ni][3] - mn1);
            rs0 += s[ni][0] + s[ni][1];
            rs1 += s[ni][2] + s[ni][3];
        }
        rs0 += __shfl_xor_sync(0xffffffffu, rs0, 1);
        rs0 += __shfl_xor_sync(0xffffffffu, rs0, 2);
        rs1 += __shfl_xor_sync(0xffffffffu, rs1, 1);
        rs1 += __shfl_xor_sync(0xffffffffu, rs1, 2);
        l0 = l0 * a0 + rs0;
        l1 = l1 * a1 + rs1;

        #pragma unroll
        for (int ni = 0; ni < 8; ni++) {
            o[ni][0] *= a0; o[ni][1] *= a0;
            o[ni][2] *= a1; o[ni][3] *= a1;
        }

        // ---- P -> smem fp16 (keys ni*8+2t, +1 per row)
        #pragma unroll
        for (int ni = 0; ni < 8; ni++) {
            *(__half2*)(Pq + (wq + g    ) * 160 + (ni * 8 + 2 * t) * 2) =
                __floats2half2_rn(s[ni][0], s[ni][1]);
            *(__half2*)(Pq + (wq + g + 8) * 160 + (ni * 8 + 2 * t) * 2) =
                __floats2half2_rn(s[ni][2], s[ni][3]);
        }
        __syncwarp();   // P rows produced/consumed within same warp

        // ---- O += P @ V   (A: logical keys 4t..4t+3; B: V quad blocks)
        #pragma unroll
        for (int ks = 0; ks < 4; ks++) {
            uint32_t a[4];
            const char* base = Pq + (wq + g) * 160 + ks * 32 + t * 8;
            uint2 lo = *(const uint2*)base;
            uint2 hi = *(const uint2*)(base + 8 * 160);
            a[0] = lo.x; a[1] = hi.x; a[2] = lo.y; a[3] = hi.y;
            #pragma unroll
            for (int ni = 0; ni < 8; ni++) {
                uint2 vb = *(const uint2*)(Vsb + (ks * 4 + t) * 544 + (ni * 8 + g) * 8);
                mma_f16(o[ni], a, vb.x, vb.y);
            }
        }
        __syncthreads();
    }

    // ---- epilogue: ctx fp16
    float inv0 = 1.f / l0, inv1 = 1.f / l1;
    const int qg0 = q0 + wq + g, qg1 = qg0 + 8;
    #pragma unroll
    for (int ni = 0; ni < 8; ni++) {
        int c = h * HD + ni * 8 + 2 * t;
        *(__half2*)&ctx[(size_t)(b * SEQ + qg0) * DOUT + c] =
            __floats2half2_rn(o[ni][0] * inv0, o[ni][1] * inv0);
        *(__half2*)&ctx[(size_t)(b * SEQ + qg1) * DOUT + c] =
            __floats2half2_rn(o[ni][2] * inv1, o[ni][3] * inv1);
    }
}

// ------------------------------- launcher -------------------------------------
extern "C" void kernel_launch(void* const* d_in, const int* in_sizes, int n_in,
                              void* d_out, int out_size)
{
    const float* x    = (const float*)d_in[0];
    const float* Wq   = (const float*)d_in[1];
    const float* Wk   = (const float*)d_in[2];
    const float* Wv   = (const float*)d_in[3];
    const float* Wo   = (const float*)d_in[4];
    const float* cosb = (const float*)d_in[5];
    const float* sinb = (const float*)d_in[6];
    float* out = (float*)d_out;

    __half *pXh, *pWqh, *pWkh, *pWvh, *pWoh, *pQr, *pKr, *pVr, *pCtx;
    cudaGetSymbolAddress((void**)&pXh,  g_xh);
    cudaGetSymbolAddress((void**)&pWqh, g_Wqh);
    cudaGetSymbolAddress((void**)&pWkh, g_Wkh);
    cudaGetSymbolAddress((void**)&pWvh, g_Wvh);
    cudaGetSymbolAddress((void**)&pWoh, g_Woh);
    cudaGetSymbolAddress((void**)&pQr,  g_Qr);
    cudaGetSymbolAddress((void**)&pKr,  g_Kr);
    cudaGetSymbolAddress((void**)&pVr,  g_Vr);
    cudaGetSymbolAddress((void**)&pCtx, g_ctx);

    dim3 thr(256);

    cudaFuncSetAttribute(qkv_h,  cudaFuncAttributeMaxDynamicSharedMemorySize, GEMM_SMEM);
    cudaFuncSetAttribute(wo_h,   cudaFuncAttributeMaxDynamicSharedMemorySize, GEMM_SMEM);
    cudaFuncSetAttribute(attn_h, cudaFuncAttributeMaxDynamicSharedMemorySize, ATTN_SMEM);

    // pre-conversion: x -> fp16; weights -> transposed fp16 [N][K]
    cvt_x_k<<<(ROWS*DIN/8 + 255)/256, thr>>>((const float4*)x, (uint4*)pXh, ROWS*DIN/8);
    wtrans_k<<<dim3(DIN/32, DOUT/32),  thr>>>(Wq, pWqh, DIN, DOUT);
    wtrans_k<<<dim3(DIN/32, DKV/32),   thr>>>(Wk, pWkh, DIN, DKV);
    wtrans_k<<<dim3(DIN/32, DKV/32),   thr>>>(Wv, pWvh, DIN, DKV);
    wtrans_k<<<dim3(DOUT/32, DOUT/32), thr>>>(Wo, pWoh, DOUT, DOUT);

    // fused QKV projection + RoPE + head-transpose (+ V quad-interleave)
    qkv_h<<<dim3(24, ROWS/128), thr, GEMM_SMEM>>>(
        pXh, pWqh, pWkh, pWvh, cosb, sinb, pQr, pKr, pVr);

    // causal flash attention (fp16 tensor core)
    attn_h<<<dim3(SEQ/128, BATCH*NH), thr, ATTN_SMEM>>>(pQr, pKr, pVr, pCtx);

    // output projection
    wo_h<<<dim3(DOUT/128, ROWS/128), thr, GEMM_SMEM>>>(pCtx, pWoh, out);
}

// round 12
// speedup vs baseline: 1.4436x; 1.0277x over previous
#include <cuda_runtime.h>
#include <cuda_fp16.h>
#include <stdint.h>

#define BATCH 2
#define SEQ   2048
#define DIN   2048
#define DOUT  2048
#define NH    32
#define NKV   8
#define HD    64
#define ROWS  (BATCH*SEQ)    /* 4096 */
#define DKV   (NKV*HD)       /* 512  */

// ---------------- scratch (static device arrays; no allocation) ----------------
__device__ __half g_xh [ROWS*DIN];     // x fp16 row-major [M][K]
__device__ __half g_Wqh[DOUT*DIN];     // Wq^T fp16 [N][K]
__device__ __half g_Wkh[DKV*DIN];      // Wk^T fp16 [N][K]
__device__ __half g_Wvh[DKV*DIN];      // Wv^T fp16 [N][K]
__device__ __half g_Woh[DOUT*DOUT];    // Wo^T fp16 [N][K]
__device__ __half g_Qr [ROWS*DOUT];    // [B,NH,S,HD]  (pre-scaled by 0.125*log2e)
__device__ __half g_Kr [ROWS*DKV];     // [B,NKV,S,HD]
__device__ __half g_Vr [ROWS*DKV];     // [B,NKV,S/4,HD,4] quad-interleaved
__device__ __half g_ctx[ROWS*DOUT];    // [B*S, NH*HD]

__device__ __forceinline__ void mma_f16(float* c, const uint32_t* a,
                                        uint32_t b0, uint32_t b1) {
    asm volatile(
        "mma.sync.aligned.m16n8k16.row.col.f32.f16.f16.f32 "
        "{%0,%1,%2,%3}, {%4,%5,%6,%7}, {%8,%9}, {%0,%1,%2,%3};"
        : "+f"(c[0]), "+f"(c[1]), "+f"(c[2]), "+f"(c[3])
        : "r"(a[0]), "r"(a[1]), "r"(a[2]), "r"(a[3]), "r"(b0), "r"(b1));
}

__device__ __forceinline__ void cp16(uint32_t smem_byte, const void* g) {
    asm volatile("cp.async.cg.shared.global [%0], [%1], 16;\n"
                 :: "r"(smem_byte), "l"(g));
}
__device__ __forceinline__ void cp_commit() {
    asm volatile("cp.async.commit_group;\n" ::);
}
template <int N>
__device__ __forceinline__ void cp_wait() {
    asm volatile("cp.async.wait_group %0;\n" :: "n"(N));
}
__device__ __forceinline__ uint32_t smem_u32(const void* p) {
    return (uint32_t)__cvta_generic_to_shared(p);
}

#define QLOGSCALE 0.1803368801111204f   /* 0.125 * log2(e) */

// ---------------- pre-kernels ---------------------------------------------------
__global__ __launch_bounds__(256) void cvt_x_k(const float4* __restrict__ in,
                                               uint4* __restrict__ out, int n8)
{
    int i = blockIdx.x * blockDim.x + threadIdx.x;
    if (i < n8) {
        float4 v0 = in[2 * i], v1 = in[2 * i + 1];
        __half2 h0 = __floats2half2_rn(v0.x, v0.y);
        __half2 h1 = __floats2half2_rn(v0.z, v0.w);
        __half2 h2 = __floats2half2_rn(v1.x, v1.y);
        __half2 h3 = __floats2half2_rn(v1.z, v1.w);
        uint4 u;
        u.x = *(uint32_t*)&h0; u.y = *(uint32_t*)&h1;
        u.z = *(uint32_t*)&h2; u.w = *(uint32_t*)&h3;
        out[i] = u;
    }
}

// W [K][N] fp32 -> Wt [N][K] fp16 (tiled transpose)
__global__ __launch_bounds__(256) void wtrans_k(const float* __restrict__ W,
                                                __half* __restrict__ out,
                                                int K, int N)
{
    __shared__ __half t[32][34];
    int kb = blockIdx.x * 32, nb = blockIdx.y * 32;
    int tx = threadIdx.x & 31, ty = threadIdx.x >> 5;
    #pragma unroll
    for (int i = 0; i < 4; i++)
        t[ty + 8*i][tx] = __float2half_rn(W[(size_t)(kb + ty + 8*i) * N + nb + tx]);
    __syncthreads();
    #pragma unroll
    for (int i = 0; i < 4; i++)
        out[(size_t)(nb + ty + 8*i) * K + kb + tx] = t[tx][ty + 8*i];
}

// ================= fp16 GEMM mainloop (128x128 tile, k-tile 64) ================
#define GEMM_SMEM 65536

__device__ __forceinline__ void gemm_mainloop_h(
    const __half* __restrict__ A, const __half* __restrict__ Bt,
    int K, int row0, int col0, char* smem, float acc[2][8][4])
{
    const int tid  = threadIdx.x;
    const int lane = tid & 31, warp = tid >> 5;
    const int g = lane >> 2, t = lane & 3;
    const int wm = (warp & 3) * 32, wn = (warp >> 2) * 64;
    const uint32_t sA = smem_u32(smem);
    const uint32_t sB = sA + 32768;

    const int a_r = tid >> 1;
    const int c8b = (tid & 1) * 4;

    auto LOAD = [&](int k0, int buf) {
        #pragma unroll
        for (int j = 0; j < 4; j++) {
            const int c8 = c8b + j;
            const int kb = c8 >> 1, part = c8 & 1;
            const uint32_t off = (uint32_t)(buf * 16384 + (kb * 128 + a_r) * 32 + part * 16);
            cp16(sA + off, A  + (size_t)(row0 + a_r) * K + k0 + c8 * 8);
            cp16(sB + off, Bt + (size_t)(col0 + a_r) * K + k0 + c8 * 8);
        }
        cp_commit();
    };

    #pragma unroll
    for (int mi = 0; mi < 2; mi++)
        #pragma unroll
        for (int ni = 0; ni < 8; ni++)
            #pragma unroll
            for (int r = 0; r < 4; r++) acc[mi][ni][r] = 0.f;

    LOAD(0, 0);

    const int niter = K / 64;
    for (int it = 0; it < niter; it++) {
        const int buf = it & 1;
        if (it + 1 < niter) {
            LOAD((it + 1) * 64, buf ^ 1);
            cp_wait<1>();
        } else {
            cp_wait<0>();
        }
        __syncthreads();

        const char* Ab = smem + buf * 16384;
        const char* Bb = smem + 32768 + buf * 16384;
        #pragma unroll
        for (int kb = 0; kb < 4; kb++) {
            uint32_t a[2][4]; uint2 bb[8];
            #pragma unroll
            for (int mi = 0; mi < 2; mi++) {
                const char* base = Ab + (kb * 128 + wm + mi * 16 + g) * 32 + t * 8;
                uint2 lo = *(const uint2*)base;
                uint2 hi = *(const uint2*)(base + 8 * 32);
                a[mi][0] = lo.x; a[mi][1] = hi.x; a[mi][2] = lo.y; a[mi][3] = hi.y;
            }
            #pragma unroll
            for (int ni = 0; ni < 8; ni++)
                bb[ni] = *(const uint2*)(Bb + (kb * 128 + wn + ni * 8 + g) * 32 + t * 8);
            #pragma unroll
            for (int mi = 0; mi < 2; mi++)
                #pragma unroll
                for (int ni = 0; ni < 8; ni++)
                    mma_f16(acc[mi][ni], a[mi], bb[ni].x, bb[ni].y);
        }
        __syncthreads();
    }
}

// ================= fused QKV projection + RoPE + transpose =====================
// grid (24, 32): bx<16 Q (RoPE + log2-scale), <20 K (RoPE), else V (quad pack).
__global__ __launch_bounds__(256, 2) void qkv_h(
    const __half* __restrict__ xh,
    const __half* __restrict__ Wqh, const __half* __restrict__ Wkh,
    const __half* __restrict__ Wvh,
    const float* __restrict__ cosb, const float* __restrict__ sinb,
    __half* __restrict__ Qr, __half* __restrict__ Kr, __half* __restrict__ Vr)
{
    extern __shared__ char smem[];
    const int bx = blockIdx.x;
    const __half* W; __half* outp; int col0, nh, kind; float qs;
    if (bx < 16)      { W = Wqh; outp = Qr; col0 = bx * 128;        nh = NH;  kind = 0; qs = QLOGSCALE; }
    else if (bx < 20) { W = Wkh; outp = Kr; col0 = (bx - 16) * 128; nh = NKV; kind = 0; qs = 1.f; }
    else              { W = Wvh; outp = Vr; col0 = (bx - 20) * 128; nh = NKV; kind = 1; qs = 1.f; }
    const int row0 = blockIdx.y * 128;

    float acc[2][8][4];
    gemm_mainloop_h(xh, W, DIN, row0, col0, smem, acc);

    const int lane = threadIdx.x & 31, warp = threadIdx.x >> 5;
    const int g = lane >> 2, t = lane & 3;
    const int wm = (warp & 3) * 32, wn = (warp >> 2) * 64;
    const int hq = (col0 + wn) >> 6;

    #pragma unroll
    for (int mi = 0; mi < 2; mi++) {
        const int rbase = row0 + wm + mi * 16 + g;
        #pragma unroll
        for (int v = 0; v < 2; v++) {
            const int r = rbase + v * 8;
            const int b = r >> 11, s = r & 2047;
            if (kind == 0) {
                __half* row = outp + ((size_t)(b * nh + hq) * SEQ + s) * HD;
                const float* cs = cosb + s * HD;
                const float* sn = sinb + s * HD;
                #pragma unroll
                for (int ni = 0; ni < 4; ni++) {
                    const int d = ni * 8 + 2 * t;
                    float x1a = acc[mi][ni    ][v*2], x1b = acc[mi][ni    ][v*2+1];
                    float x2a = acc[mi][ni + 4][v*2], x2b = acc[mi][ni + 4][v*2+1];
                    float2 c1 = *(const float2*)&cs[d];
                    float2 s1 = *(const float2*)&sn[d];
                    float2 c2 = *(const float2*)&cs[d + 32];
                    float2 s2 = *(const float2*)&sn[d + 32];
                    *(__half2*)&row[d] =
                        __floats2half2_rn((x1a * c1.x - x2a * s1.x) * qs,
                                          (x1b * c1.y - x2b * s1.y) * qs);
                    *(__half2*)&row[d + 32] =
                        __floats2half2_rn((x2a * c2.x + x1a * s2.x) * qs,
                                          (x2b * c2.y + x1b * s2.y) * qs);
                }
            } else {
                // V quad-interleave: [S/4][HD][4]
                __half* hb = outp + (size_t)(b * nh + hq) * SEQ * HD;
                const size_t sb = (size_t)(s >> 2) * (HD * 4) + (s & 3);
                #pragma unroll
                for (int ni = 0; ni < 8; ni++) {
                    const int d = ni * 8 + 2 * t;
                    hb[sb + (size_t)d * 4]       = __float2half_rn(acc[mi][ni][v*2]);
                    hb[sb + (size_t)(d + 1) * 4] = __float2half_rn(acc[mi][ni][v*2+1]);
                }
            }
        }
    }
}

// ================= output projection ===========================================
__global__ __launch_bounds__(256, 2) void wo_h(
    const __half* __restrict__ ctx, const __half* __restrict__ Woh,
    float* __restrict__ out)
{
    extern __shared__ char smem[];
    const int row0 = blockIdx.y * 128, col0 = blockIdx.x * 128;

    float acc[2][8][4];
    gemm_mainloop_h(ctx, Woh, DOUT, row0, col0, smem, acc);

    const int lane = threadIdx.x & 31, warp = threadIdx.x >> 5;
    const int g = lane >> 2, t = lane & 3;
    const int wm = (warp & 3) * 32, wn = (warp >> 2) * 64;

    #pragma unroll
    for (int mi = 0; mi < 2; mi++)
        #pragma unroll
        for (int ni = 0; ni < 8; ni++) {
            const int r = row0 + wm + mi * 16 + g;
            const int c = col0 + wn + ni * 8 + t * 2;
            *(float2*)(out + (size_t)r * DOUT + c) =
                make_float2(acc[mi][ni][0], acc[mi][ni][1]);
            *(float2*)(out + (size_t)(r + 8) * DOUT + c) =
                make_float2(acc[mi][ni][2], acc[mi][ni][3]);
        }
}

// ================= fp16 flash attention (log2-domain softmax) ==================
// Q/K smem stride 160B; V smem stride 608B per 4-key block (72 d-cols: 64 real +
// ones column at d=64 for the MMA row-sum + 7 zero pads).
#define KTB 10240                  /* 64*160 */
#define VST 608
#define VTB (16*VST)               /* 9728 */
#define ATTN_SMEM (20480 + 2*KTB + 2*VTB)   /* 60416 */

__global__ __launch_bounds__(256) void attn_h(
    const __half* __restrict__ Qr, const __half* __restrict__ Kr,
    const __half* __restrict__ Vr, __half* __restrict__ ctx)
{
    extern __shared__ char sm[];
    char* Pq = sm;                 // [128][160B]  Q staging, then P
    char* Ks = sm + 20480;         // [2][64][160B]
    char* Vs = sm + 20480 + 2 * KTB;   // [2][16][608B]

    const int bh = blockIdx.y;
    const int b = bh >> 5, h = bh & 31, g2 = h >> 2;
    const int qt = gridDim.x - 1 - blockIdx.x;     // heavy tiles first
    const int q0 = qt * 128;
    const int tid = threadIdx.x;
    const int warp = tid >> 5, lane = tid & 31;
    const int g = lane >> 2, t = lane & 3;
    const int wq = warp * 16;

    const __half* Qbase = Qr + ((size_t)bh * SEQ + q0) * HD;
    const __half* Kbase = Kr + (size_t)(b * NKV + g2) * SEQ * HD;
    const __half* Vbase = Vr + (size_t)(b * NKV + g2) * SEQ * HD;   // quad layout

    const uint32_t sK = smem_u32(Ks);
    const uint32_t sV = smem_u32(Vs);
    const uint32_t sP = smem_u32(Pq);

    auto LOADKV = [&](int k0, int buf) {
        #pragma unroll
        for (int i = 0; i < 2; i++) {
            const int ch = tid + i * 256;
            const int row = ch >> 3, c8 = ch & 7;
            cp16(sK + (uint32_t)(buf * KTB + row * 160 + c8 * 16),
                 Kbase + (size_t)(k0 + row) * HD + c8 * 8);
            const int sblk = ch >> 5, c = ch & 31;
            cp16(sV + (uint32_t)(buf * VTB + sblk * VST + c * 16),
                 Vbase + (size_t)k0 * 64 + sblk * 256 + c * 8);
        }
        cp_commit();
    };

    // ones/zero pad columns of V smem (bytes [512,608) of every quad-row, both bufs)
    {
        // 32 rows x 96B = 3072B = 256 threads x 12B -> do 2 passes of uint2 + one u32
        const int row = tid >> 3, part = tid & 7;      // 32 rows, 8 x 12B... use simpler: 96B = 12 uint64? do per-thread loop
        char* rp = Vs + (row < 16 ? row * VST : VTB + (row - 16) * VST) + 512;
        // part covers 12 bytes each: part*12 .. part*12+11  (96B total)
        #pragma unroll
        for (int bgo = 0; bgo < 12; bgo += 4) {
            int off = part * 12 + bgo;
            uint32_t val = (off < 8) ? 0x3C003C00u : 0u;   // d=64 halves = 1.0
            *(uint32_t*)(rp + off) = val;
        }
    }

    // stage Q FIRST, then prefetch KV0; wait<1> drains Q while KV0 flies.
    #pragma unroll
    for (int i = 0; i < 4; i++) {
        const int ch = tid + i * 256;
        const int row = ch >> 3, c8 = ch & 7;
        cp16(sP + (uint32_t)(row * 160 + c8 * 16), Qbase + (size_t)row * HD + c8 * 8);
    }
    cp_commit();
    LOADKV(0, 0);
    cp_wait<1>();
    __syncthreads();

    uint32_t qf[4][4];
    #pragma unroll
    for (int ds = 0; ds < 4; ds++) {
        const char* base = Pq + (wq + g) * 160 + ds * 32 + t * 8;
        uint2 lo = *(const uint2*)base;
        uint2 hi = *(const uint2*)(base + 8 * 160);
        qf[ds][0] = lo.x; qf[ds][1] = hi.x; qf[ds][2] = lo.y; qf[ds][3] = hi.y;
    }
    __syncthreads();   // Q regs everywhere before Pq reuse; also covers ones-init

    float o[9][4];     // o[8] = running row-sum (ones column)
    #pragma unroll
    for (int ni = 0; ni < 9; ni++)
        #pragma unroll
        for (int r = 0; r < 4; r++) o[ni][r] = 0.f;
    float m0 = -1e30f, m1 = -1e30f;

    const int ntiles = qt * 2 + 2;
    for (int tt = 0; tt < ntiles; tt++) {
        const int buf = tt & 1;
        if (tt + 1 < ntiles) {
            LOADKV((tt + 1) * 64, buf ^ 1);
            cp_wait<1>();
        } else {
            cp_wait<0>();
        }
        __syncthreads();

        const char* Ksb = Ks + buf * KTB;
        const char* Vsb = Vs + buf * VTB;
        const int k0 = tt * 64;

        // ---- S = Q @ K^T  (already in log2 domain via pre-scaled Q)
        float s[8][4];
        #pragma unroll
        for (int ni = 0; ni < 8; ni++)
            #pragma unroll
            for (int r = 0; r < 4; r++) s[ni][r] = 0.f;

        #pragma unroll
        for (int ds = 0; ds < 4; ds++) {
            #pragma unroll
            for (int ni = 0; ni < 8; ni++) {
                uint2 kb2 = *(const uint2*)(Ksb + (ni * 8 + g) * 160 + ds * 32 + t * 8);
                mma_f16(s[ni], qf[ds], kb2.x, kb2.y);
            }
        }

        // ---- causal mask
        const bool do_mask = (k0 + 63 > q0);
        const int qg0 = q0 + wq + g, qg1 = qg0 + 8;
        if (do_mask) {
            #pragma unroll
            for (int ni = 0; ni < 8; ni++) {
                #pragma unroll
                for (int r = 0; r < 4; r++) {
                    int kg = k0 + ni * 8 + 2 * t + (r & 1);
                    int qg = (r >= 2) ? qg1 : qg0;
                    if (kg > qg) s[ni][r] = -1e30f;
                }
            }
        }

        // ---- online softmax (log2 domain, fp16 packed exp2)
        float tm0 = -1e30f, tm1 = -1e30f;
        #pragma unroll
        for (int ni = 0; ni < 8; ni++) {
            tm0 = fmaxf(tm0, fmaxf(s[ni][0], s[ni][1]));
            tm1 = fmaxf(tm1, fmaxf(s[ni][2], s[ni][3]));
        }
        tm0 = fmaxf(tm0, __shfl_xor_sync(0xffffffffu, tm0, 1));
        tm0 = fmaxf(tm0, __shfl_xor_sync(0xffffffffu, tm0, 2));
        tm1 = fmaxf(tm1, __shfl_xor_sync(0xffffffffu, tm1, 1));
        tm1 = fmaxf(tm1, __shfl_xor_sync(0xffffffffu, tm1, 2));

        float mn0 = fmaxf(m0, tm0), mn1 = fmaxf(m1, tm1);
        float a0 = exp2f(m0 - mn0), a1 = exp2f(m1 - mn1);
        m0 = mn0; m1 = mn1;

        #pragma unroll
        for (int ni = 0; ni < 9; ni++) {
            o[ni][0] *= a0; o[ni][1] *= a0;
            o[ni][2] *= a1; o[ni][3] *= a1;
        }

        // P = 2^(s - m), computed and stored directly as fp16
        #pragma unroll
        for (int ni = 0; ni < 8; ni++) {
            __half2 p0 = h2exp2(__floats2half2_rn(s[ni][0] - mn0, s[ni][1] - mn0));
            __half2 p1 = h2exp2(__floats2half2_rn(s[ni][2] - mn1, s[ni][3] - mn1));
            *(__half2*)(Pq + (wq + g    ) * 160 + (ni * 8 + 2 * t) * 2) = p0;
            *(__half2*)(Pq + (wq + g + 8) * 160 + (ni * 8 + 2 * t) * 2) = p1;
        }
        __syncwarp();   // P rows produced/consumed within same warp

        // ---- O += P @ V  (9th n-block = ones column -> row sums in o[8])
        #pragma unroll
        for (int ks = 0; ks < 4; ks++) {
            uint32_t a[4];
            const char* base = Pq + (wq + g) * 160 + ks * 32 + t * 8;
            uint2 lo = *(const uint2*)base;
            uint2 hi = *(const uint2*)(base + 8 * 160);
            a[0] = lo.x; a[1] = hi.x; a[2] = lo.y; a[3] = hi.y;
            #pragma unroll
            for (int ni = 0; ni < 9; ni++) {
                uint2 vb = *(const uint2*)(Vsb + (ks * 4 + t) * VST + (ni * 8 + g) * 8);
                mma_f16(o[ni], a, vb.x, vb.y);
            }
        }
        __syncthreads();
    }

    // ---- epilogue: l lives in o[8] col 64 (t==0 lane of each quad)
    float l0 = __shfl_sync(0xffffffffu, o[8][0], lane & ~3);
    float l1 = __shfl_sync(0xffffffffu, o[8][2], lane & ~3);
    float inv0 = 1.f / l0, inv1 = 1.f / l1;
    const int qg0 = q0 + wq + g, qg1 = qg0 + 8;
    #pragma unroll
    for (int ni = 0; ni < 8; ni++) {
        int c = h * HD + ni * 8 + 2 * t;
        *(__half2*)&ctx[(size_t)(b * SEQ + qg0) * DOUT + c] =
            __floats2half2_rn(o[ni][0] * inv0, o[ni][1] * inv0);
        *(__half2*)&ctx[(size_t)(b * SEQ + qg1) * DOUT + c] =
            __floats2half2_rn(o[ni][2] * inv1, o[ni][3] * inv1);
    }
}

// ------------------------------- launcher -------------------------------------
extern "C" void kernel_launch(void* const* d_in, const int* in_sizes, int n_in,
                              void* d_out, int out_size)
{
    const float* x    = (const float*)d_in[0];
    const float* Wq   = (const float*)d_in[1];
    const float* Wk   = (const float*)d_in[2];
    const float* Wv   = (const float*)d_in[3];
    const float* Wo   = (const float*)d_in[4];
    const float* cosb = (const float*)d_in[5];
    const float* sinb = (const float*)d_in[6];
    float* out = (float*)d_out;

    __half *pXh, *pWqh, *pWkh, *pWvh, *pWoh, *pQr, *pKr, *pVr, *pCtx;
    cudaGetSymbolAddress((void**)&pXh,  g_xh);
    cudaGetSymbolAddress((void**)&pWqh, g_Wqh);
    cudaGetSymbolAddress((void**)&pWkh, g_Wkh);
    cudaGetSymbolAddress((void**)&pWvh, g_Wvh);
    cudaGetSymbolAddress((void**)&pWoh, g_Woh);
    cudaGetSymbolAddress((void**)&pQr,  g_Qr);
    cudaGetSymbolAddress((void**)&pKr,  g_Kr);
    cudaGetSymbolAddress((void**)&pVr,  g_Vr);
    cudaGetSymbolAddress((void**)&pCtx, g_ctx);

    dim3 thr(256);

    cudaFuncSetAttribute(qkv_h,  cudaFuncAttributeMaxDynamicSharedMemorySize, GEMM_SMEM);
    cudaFuncSetAttribute(wo_h,   cudaFuncAttributeMaxDynamicSharedMemorySize, GEMM_SMEM);
    cudaFuncSetAttribute(attn_h, cudaFuncAttributeMaxDynamicSharedMemorySize, ATTN_SMEM);

    // pre-conversion: x -> fp16; weights -> transposed fp16 [N][K]
    cvt_x_k<<<(ROWS*DIN/8 + 255)/256, thr>>>((const float4*)x, (uint4*)pXh, ROWS*DIN/8);
    wtrans_k<<<dim3(DIN/32, DOUT/32),  thr>>>(Wq, pWqh, DIN, DOUT);
    wtrans_k<<<dim3(DIN/32, DKV/32),   thr>>>(Wk, pWkh, DIN, DKV);
    wtrans_k<<<dim3(DIN/32, DKV/32),   thr>>>(Wv, pWvh, DIN, DKV);
    wtrans_k<<<dim3(DOUT/32, DOUT/32), thr>>>(Wo, pWoh, DOUT, DOUT);

    // fused QKV projection + RoPE (+ Q log2-scale) + head-transpose
    qkv_h<<<dim3(24, ROWS/128), thr, GEMM_SMEM>>>(
        pXh, pWqh, pWkh, pWvh, cosb, sinb, pQr, pKr, pVr);

    // causal flash attention (fp16 tensor core, log2-domain softmax)
    attn_h<<<dim3(SEQ/128, BATCH*NH), thr, ATTN_SMEM>>>(pQr, pKr, pVr, pCtx);

    // output projection
    wo_h<<<dim3(DOUT/128, ROWS/128), thr, GEMM_SMEM>>>(pCtx, pWoh, out);
}

// round 13
// speedup vs baseline: 1.4575x; 1.0096x over previous
#include <cuda_runtime.h>
#include <cuda_fp16.h>
#include <stdint.h>

#define BATCH 2
#define SEQ   2048
#define DIN   2048
#define DOUT  2048
#define NH    32
#define NKV   8
#define HD    64
#define ROWS  (BATCH*SEQ)    /* 4096 */
#define DKV   (NKV*HD)       /* 512  */

// ---------------- scratch (static device arrays; no allocation) ----------------
__device__ __half g_xh [ROWS*DIN];     // x fp16 row-major [M][K]
__device__ __half g_Wqh[DOUT*DIN];     // Wq^T fp16 [N][K]
__device__ __half g_Wkh[DKV*DIN];      // Wk^T fp16 [N][K]
__device__ __half g_Wvh[DKV*DIN];      // Wv^T fp16 [N][K]
__device__ __half g_Woh[DOUT*DOUT];    // Wo^T fp16 [N][K]
__device__ __half g_Qr [ROWS*DOUT];    // [B,NH,S,HD]  (pre-scaled by 0.125*log2e)
__device__ __half g_Kr [ROWS*DKV];     // [B,NKV,S,HD]
__device__ __half g_Vr [ROWS*DKV];     // [B,NKV,S/4,HD,4] quad-interleaved
__device__ __half g_ctx[ROWS*DOUT];    // [B*S, NH*HD]

__device__ __forceinline__ void mma_f16(float* c, const uint32_t* a,
                                        uint32_t b0, uint32_t b1) {
    asm volatile(
        "mma.sync.aligned.m16n8k16.row.col.f32.f16.f16.f32 "
        "{%0,%1,%2,%3}, {%4,%5,%6,%7}, {%8,%9}, {%0,%1,%2,%3};"
        : "+f"(c[0]), "+f"(c[1]), "+f"(c[2]), "+f"(c[3])
        : "r"(a[0]), "r"(a[1]), "r"(a[2]), "r"(a[3]), "r"(b0), "r"(b1));
}

__device__ __forceinline__ void cp16(uint32_t smem_byte, const void* g) {
    asm volatile("cp.async.cg.shared.global [%0], [%1], 16;\n"
                 :: "r"(smem_byte), "l"(g));
}
__device__ __forceinline__ void cp_commit() {
    asm volatile("cp.async.commit_group;\n" ::);
}
template <int N>
__device__ __forceinline__ void cp_wait() {
    asm volatile("cp.async.wait_group %0;\n" :: "n"(N));
}
__device__ __forceinline__ uint32_t smem_u32(const void* p) {
    return (uint32_t)__cvta_generic_to_shared(p);
}

#define QLOGSCALE 0.1803368801111204f   /* 0.125 * log2(e) */

// ---------------- pre-kernels ---------------------------------------------------
__global__ __launch_bounds__(256) void cvt_x_k(const float4* __restrict__ in,
                                               uint4* __restrict__ out, int n8)
{
    int i = blockIdx.x * blockDim.x + threadIdx.x;
    if (i < n8) {
        float4 v0 = in[2 * i], v1 = in[2 * i + 1];
        __half2 h0 = __floats2half2_rn(v0.x, v0.y);
        __half2 h1 = __floats2half2_rn(v0.z, v0.w);
        __half2 h2 = __floats2half2_rn(v1.x, v1.y);
        __half2 h3 = __floats2half2_rn(v1.z, v1.w);
        uint4 u;
        u.x = *(uint32_t*)&h0; u.y = *(uint32_t*)&h1;
        u.z = *(uint32_t*)&h2; u.w = *(uint32_t*)&h3;
        out[i] = u;
    }
}

// Fused 4-way weight transpose: W [K][N] fp32 -> Wt [N][K] fp16.
// Block ranges: [0,4096) Wq, [4096,5120) Wk, [5120,6144) Wv, [6144,10240) Wo.
__global__ __launch_bounds__(256) void wtrans4_k(
    const float* __restrict__ Wq, const float* __restrict__ Wk,
    const float* __restrict__ Wv, const float* __restrict__ Wo,
    __half* __restrict__ oq, __half* __restrict__ ok,
    __half* __restrict__ ov, __half* __restrict__ oo)
{
    __shared__ __half t[32][34];
    int bid = blockIdx.x;
    const float* W; __half* out; int K, N, tile;
    if (bid < 4096)      { W = Wq; out = oq; K = DIN;  N = DOUT; tile = bid; }
    else if (bid < 5120) { W = Wk; out = ok; K = DIN;  N = DKV;  tile = bid - 4096; }
    else if (bid < 6144) { W = Wv; out = ov; K = DIN;  N = DKV;  tile = bid - 5120; }
    else                 { W = Wo; out = oo; K = DOUT; N = DOUT; tile = bid - 6144; }
    const int ntn = N / 32;
    int kb = (tile / ntn) * 32, nb = (tile % ntn) * 32;
    int tx = threadIdx.x & 31, ty = threadIdx.x >> 5;
    #pragma unroll
    for (int i = 0; i < 4; i++)
        t[ty + 8*i][tx] = __float2half_rn(W[(size_t)(kb + ty + 8*i) * N + nb + tx]);
    __syncthreads();
    #pragma unroll
    for (int i = 0; i < 4; i++)
        out[(size_t)(nb + ty + 8*i) * K + kb + tx] = t[tx][ty + 8*i];
}

// ================= fp16 GEMM mainloop (128x128 tile, k-tile 64) ================
#define GEMM_SMEM 65536

__device__ __forceinline__ void gemm_mainloop_h(
    const __half* __restrict__ A, const __half* __restrict__ Bt,
    int K, int row0, int col0, char* smem, float acc[2][8][4])
{
    const int tid  = threadIdx.x;
    const int lane = tid & 31, warp = tid >> 5;
    const int g = lane >> 2, t = lane & 3;
    const int wm = (warp & 3) * 32, wn = (warp >> 2) * 64;
    const uint32_t sA = smem_u32(smem);
    const uint32_t sB = sA + 32768;

    const int a_r = tid >> 1;
    const int c8b = (tid & 1) * 4;

    auto LOAD = [&](int k0, int buf) {
        #pragma unroll
        for (int j = 0; j < 4; j++) {
            const int c8 = c8b + j;
            const int kb = c8 >> 1, part = c8 & 1;
            const uint32_t off = (uint32_t)(buf * 16384 + (kb * 128 + a_r) * 32 + part * 16);
            cp16(sA + off, A  + (size_t)(row0 + a_r) * K + k0 + c8 * 8);
            cp16(sB + off, Bt + (size_t)(col0 + a_r) * K + k0 + c8 * 8);
        }
        cp_commit();
    };

    #pragma unroll
    for (int mi = 0; mi < 2; mi++)
        #pragma unroll
        for (int ni = 0; ni < 8; ni++)
            #pragma unroll
            for (int r = 0; r < 4; r++) acc[mi][ni][r] = 0.f;

    LOAD(0, 0);

    const int niter = K / 64;
    for (int it = 0; it < niter; it++) {
        const int buf = it & 1;
        if (it + 1 < niter) {
            LOAD((it + 1) * 64, buf ^ 1);
            cp_wait<1>();
        } else {
            cp_wait<0>();
        }
        __syncthreads();

        const char* Ab = smem + buf * 16384;
        const char* Bb = smem + 32768 + buf * 16384;
        #pragma unroll
        for (int kb = 0; kb < 4; kb++) {
            uint32_t a[2][4]; uint2 bb[8];
            #pragma unroll
            for (int mi = 0; mi < 2; mi++) {
                const char* base = Ab + (kb * 128 + wm + mi * 16 + g) * 32 + t * 8;
                uint2 lo = *(const uint2*)base;
                uint2 hi = *(const uint2*)(base + 8 * 32);
                a[mi][0] = lo.x; a[mi][1] = hi.x; a[mi][2] = lo.y; a[mi][3] = hi.y;
            }
            #pragma unroll
            for (int ni = 0; ni < 8; ni++)
                bb[ni] = *(const uint2*)(Bb + (kb * 128 + wn + ni * 8 + g) * 32 + t * 8);
            #pragma unroll
            for (int mi = 0; mi < 2; mi++)
                #pragma unroll
                for (int ni = 0; ni < 8; ni++)
                    mma_f16(acc[mi][ni], a[mi], bb[ni].x, bb[ni].y);
        }
        __syncthreads();
    }
}

// ================= fused QKV projection + RoPE + transpose =====================
// grid (24, 32): bx<16 Q (RoPE + log2-scale), <20 K (RoPE), else V (quad pack).
__global__ __launch_bounds__(256, 2) void qkv_h(
    const __half* __restrict__ xh,
    const __half* __restrict__ Wqh, const __half* __restrict__ Wkh,
    const __half* __restrict__ Wvh,
    const float* __restrict__ cosb, const float* __restrict__ sinb,
    __half* __restrict__ Qr, __half* __restrict__ Kr, __half* __restrict__ Vr)
{
    extern __shared__ char smem[];
    const int bx = blockIdx.x;
    const __half* W; __half* outp; int col0, nh, kind; float qs;
    if (bx < 16)      { W = Wqh; outp = Qr; col0 = bx * 128;        nh = NH;  kind = 0; qs = QLOGSCALE; }
    else if (bx < 20) { W = Wkh; outp = Kr; col0 = (bx - 16) * 128; nh = NKV; kind = 0; qs = 1.f; }
    else              { W = Wvh; outp = Vr; col0 = (bx - 20) * 128; nh = NKV; kind = 1; qs = 1.f; }
    const int row0 = blockIdx.y * 128;

    float acc[2][8][4];
    gemm_mainloop_h(xh, W, DIN, row0, col0, smem, acc);

    const int lane = threadIdx.x & 31, warp = threadIdx.x >> 5;
    const int g = lane >> 2, t = lane & 3;
    const int wm = (warp & 3) * 32, wn = (warp >> 2) * 64;
    const int hq = (col0 + wn) >> 6;

    #pragma unroll
    for (int mi = 0; mi < 2; mi++) {
        const int rbase = row0 + wm + mi * 16 + g;
        #pragma unroll
        for (int v = 0; v < 2; v++) {
            const int r = rbase + v * 8;
            const int b = r >> 11, s = r & 2047;
            if (kind == 0) {
                __half* row = outp + ((size_t)(b * nh + hq) * SEQ + s) * HD;
                const float* cs = cosb + s * HD;
                const float* sn = sinb + s * HD;
                #pragma unroll
                for (int ni = 0; ni < 4; ni++) {
                    const int d = ni * 8 + 2 * t;
                    float x1a = acc[mi][ni    ][v*2], x1b = acc[mi][ni    ][v*2+1];
                    float x2a = acc[mi][ni + 4][v*2], x2b = acc[mi][ni + 4][v*2+1];
                    float2 c1 = *(const float2*)&cs[d];
                    float2 s1 = *(const float2*)&sn[d];
                    float2 c2 = *(const float2*)&cs[d + 32];
                    float2 s2 = *(const float2*)&sn[d + 32];
                    *(__half2*)&row[d] =
                        __floats2half2_rn((x1a * c1.x - x2a * s1.x) * qs,
                                          (x1b * c1.y - x2b * s1.y) * qs);
                    *(__half2*)&row[d + 32] =
                        __floats2half2_rn((x2a * c2.x + x1a * s2.x) * qs,
                                          (x2b * c2.y + x1b * s2.y) * qs);
                }
            } else {
                // V quad-interleave: [S/4][HD][4]
                __half* hb = outp + (size_t)(b * nh + hq) * SEQ * HD;
                const size_t sb = (size_t)(s >> 2) * (HD * 4) + (s & 3);
                #pragma unroll
                for (int ni = 0; ni < 8; ni++) {
                    const int d = ni * 8 + 2 * t;
                    hb[sb + (size_t)d * 4]       = __float2half_rn(acc[mi][ni][v*2]);
                    hb[sb + (size_t)(d + 1) * 4] = __float2half_rn(acc[mi][ni][v*2+1]);
                }
            }
        }
    }
}

// ================= output projection ===========================================
__global__ __launch_bounds__(256, 2) void wo_h(
    const __half* __restrict__ ctx, const __half* __restrict__ Woh,
    float* __restrict__ out)
{
    extern __shared__ char smem[];
    const int row0 = blockIdx.y * 128, col0 = blockIdx.x * 128;

    float acc[2][8][4];
    gemm_mainloop_h(ctx, Woh, DOUT, row0, col0, smem, acc);

    const int lane = threadIdx.x & 31, warp = threadIdx.x >> 5;
    const int g = lane >> 2, t = lane & 3;
    const int wm = (warp & 3) * 32, wn = (warp >> 2) * 64;

    #pragma unroll
    for (int mi = 0; mi < 2; mi++)
        #pragma unroll
        for (int ni = 0; ni < 8; ni++) {
            const int r = row0 + wm + mi * 16 + g;
            const int c = col0 + wn + ni * 8 + t * 2;
            *(float2*)(out + (size_t)r * DOUT + c) =
                make_float2(acc[mi][ni][0], acc[mi][ni][1]);
            *(float2*)(out + (size_t)(r + 8) * DOUT + c) =
                make_float2(acc[mi][ni][2], acc[mi][ni][3]);
        }
}

// ================= fp16 flash attention (128-key tiles, 2 sub-iters) ===========
// Q/K smem stride 160B; V smem stride 608B per 4-key block (72 d-cols: 64 real +
// ones column at d=64 + 7 zero pads). Tiles of 128 keys; barriers per 128 keys.
#define KTB 20480                  /* 128*160 */
#define VST 608
#define VTB (32*VST)               /* 19456 */
#define ATTN_SMEM (20480 + 2*KTB + 2*VTB)   /* 100352 */

__global__ __launch_bounds__(256) void attn_h(
    const __half* __restrict__ Qr, const __half* __restrict__ Kr,
    const __half* __restrict__ Vr, __half* __restrict__ ctx)
{
    extern __shared__ char sm[];
    char* Pq = sm;                 // [128][160B]  Q staging, then P
    char* Ks = sm + 20480;         // [2][128][160B]
    char* Vs = sm + 20480 + 2 * KTB;   // [2][32][608B]

    const int bh = blockIdx.y;
    const int b = bh >> 5, h = bh & 31, g2 = h >> 2;
    const int qt = gridDim.x - 1 - blockIdx.x;     // heavy tiles first
    const int q0 = qt * 128;
    const int tid = threadIdx.x;
    const int warp = tid >> 5, lane = tid & 31;
    const int g = lane >> 2, t = lane & 3;
    const int wq = warp * 16;

    const __half* Qbase = Qr + ((size_t)bh * SEQ + q0) * HD;
    const __half* Kbase = Kr + (size_t)(b * NKV + g2) * SEQ * HD;
    const __half* Vbase = Vr + (size_t)(b * NKV + g2) * SEQ * HD;   // quad layout

    const uint32_t sK = smem_u32(Ks);
    const uint32_t sV = smem_u32(Vs);
    const uint32_t sP = smem_u32(Pq);

    // load 128 keys (K: 128 rows x 8 chunks, V: 32 quad-rows x 32 chunks)
    auto LOADKV = [&](int k0, int buf) {
        #pragma unroll
        for (int i = 0; i < 4; i++) {
            const int ch = tid + i * 256;
            const int row = ch >> 3, c8 = ch & 7;
            cp16(sK + (uint32_t)(buf * KTB + row * 160 + c8 * 16),
                 Kbase + (size_t)(k0 + row) * HD + c8 * 8);
            const int sblk = ch >> 5, c = ch & 31;
            cp16(sV + (uint32_t)(buf * VTB + sblk * VST + c * 16),
                 Vbase + (size_t)k0 * 64 + sblk * 256 + c * 8);
        }
        cp_commit();
    };

    // ones/zero pad columns of V smem: 64 quad-rows (2 bufs x 32) x 96B.
    {
        const int row = tid >> 2, part = tid & 3;      // 64 rows, 4 x 24B each
        char* rp = Vs + (row < 32 ? row * VST : VTB + (row - 32) * VST) + 512;
        #pragma unroll
        for (int bgo = 0; bgo < 24; bgo += 4) {
            int off = part * 24 + bgo;
            uint32_t val = (off < 8) ? 0x3C003C00u : 0u;   // d=64 halves = 1.0
            *(uint32_t*)(rp + off) = val;
        }
    }

    // stage Q FIRST, then prefetch KV0; wait<1> drains Q while KV0 flies.
    #pragma unroll
    for (int i = 0; i < 4; i++) {
        const int ch = tid + i * 256;
        const int row = ch >> 3, c8 = ch & 7;
        cp16(sP + (uint32_t)(row * 160 + c8 * 16), Qbase + (size_t)row * HD + c8 * 8);
    }
    cp_commit();
    LOADKV(0, 0);
    cp_wait<1>();
    __syncthreads();

    uint32_t qf[4][4];
    #pragma unroll
    for (int ds = 0; ds < 4; ds++) {
        const char* base = Pq + (wq + g) * 160 + ds * 32 + t * 8;
        uint2 lo = *(const uint2*)base;
        uint2 hi = *(const uint2*)(base + 8 * 160);
        qf[ds][0] = lo.x; qf[ds][1] = hi.x; qf[ds][2] = lo.y; qf[ds][3] = hi.y;
    }
    __syncthreads();   // Q regs everywhere before Pq reuse; also covers ones-init

    float o[9][4];     // o[8] = running row-sum (ones column)
    #pragma unroll
    for (int ni = 0; ni < 9; ni++)
        #pragma unroll
        for (int r = 0; r < 4; r++) o[ni][r] = 0.f;
    float m0 = -1e30f, m1 = -1e30f;

    const int nt128 = qt + 1;      // 128-key tiles (ntiles64 = 2qt+2 is even)
    for (int tt = 0; tt < nt128; tt++) {
        const int buf = tt & 1;
        if (tt + 1 < nt128) {
            LOADKV((tt + 1) * 128, buf ^ 1);
            cp_wait<1>();
        } else {
            cp_wait<0>();
        }
        __syncthreads();

        #pragma unroll
        for (int sub = 0; sub < 2; sub++) {
            const char* Ksb = Ks + buf * KTB + sub * 64 * 160;
            const char* Vsb = Vs + buf * VTB + sub * 16 * VST;
            const int k0 = tt * 128 + sub * 64;

            // ---- S = Q @ K^T  (log2 domain via pre-scaled Q)
            float s[8][4];
            #pragma unroll
            for (int ni = 0; ni < 8; ni++)
                #pragma unroll
                for (int r = 0; r < 4; r++) s[ni][r] = 0.f;

            #pragma unroll
            for (int ds = 0; ds < 4; ds++) {
                #pragma unroll
                for (int ni = 0; ni < 8; ni++) {
                    uint2 kb2 = *(const uint2*)(Ksb + (ni * 8 + g) * 160 + ds * 32 + t * 8);
                    mma_f16(s[ni], qf[ds], kb2.x, kb2.y);
                }
            }

            // ---- causal mask
            const bool do_mask = (k0 + 63 > q0);
            const int qg0 = q0 + wq + g, qg1 = qg0 + 8;
            if (do_mask) {
                #pragma unroll
                for (int ni = 0; ni < 8; ni++) {
                    #pragma unroll
                    for (int r = 0; r < 4; r++) {
                        int kg = k0 + ni * 8 + 2 * t + (r & 1);
                        int qg = (r >= 2) ? qg1 : qg0;
                        if (kg > qg) s[ni][r] = -1e30f;
                    }
                }
            }

            // ---- online softmax (log2 domain)
            float tm0 = -1e30f, tm1 = -1e30f;
            #pragma unroll
            for (int ni = 0; ni < 8; ni++) {
                tm0 = fmaxf(tm0, fmaxf(s[ni][0], s[ni][1]));
                tm1 = fmaxf(tm1, fmaxf(s[ni][2], s[ni][3]));
            }
            tm0 = fmaxf(tm0, __shfl_xor_sync(0xffffffffu, tm0, 1));
            tm0 = fmaxf(tm0, __shfl_xor_sync(0xffffffffu, tm0, 2));
            tm1 = fmaxf(tm1, __shfl_xor_sync(0xffffffffu, tm1, 1));
            tm1 = fmaxf(tm1, __shfl_xor_sync(0xffffffffu, tm1, 2));

            float mn0 = fmaxf(m0, tm0), mn1 = fmaxf(m1, tm1);
            float a0 = exp2f(m0 - mn0), a1 = exp2f(m1 - mn1);
            m0 = mn0; m1 = mn1;

            #pragma unroll
            for (int ni = 0; ni < 9; ni++) {
                o[ni][0] *= a0; o[ni][1] *= a0;
                o[ni][2] *= a1; o[ni][3] *= a1;
            }

            // P = 2^(s - m), fp16 packed, stored directly
            #pragma unroll
            for (int ni = 0; ni < 8; ni++) {
                __half2 p0 = h2exp2(__floats2half2_rn(s[ni][0] - mn0, s[ni][1] - mn0));
                __half2 p1 = h2exp2(__floats2half2_rn(s[ni][2] - mn1, s[ni][3] - mn1));
                *(__half2*)(Pq + (wq + g    ) * 160 + (ni * 8 + 2 * t) * 2) = p0;
                *(__half2*)(Pq + (wq + g + 8) * 160 + (ni * 8 + 2 * t) * 2) = p1;
            }
            __syncwarp();   // P rows produced/consumed within same warp

            // ---- O += P @ V  (9th n-block = ones column -> row sums in o[8])
            #pragma unroll
            for (int ks = 0; ks < 4; ks++) {
                uint32_t a[4];
                const char* base = Pq + (wq + g) * 160 + ks * 32 + t * 8;
                uint2 lo = *(const uint2*)base;
                uint2 hi = *(const uint2*)(base + 8 * 160);
                a[0] = lo.x; a[1] = hi.x; a[2] = lo.y; a[3] = hi.y;
                #pragma unroll
                for (int ni = 0; ni < 9; ni++) {
                    uint2 vb = *(const uint2*)(Vsb + (ks * 4 + t) * VST + (ni * 8 + g) * 8);
                    mma_f16(o[ni], a, vb.x, vb.y);
                }
            }
        }
        __syncthreads();
    }

    // ---- epilogue: l lives in o[8] col 64 (t==0 lane of each quad)
    float l0 = __shfl_sync(0xffffffffu, o[8][0], lane & ~3);
    float l1 = __shfl_sync(0xffffffffu, o[8][2], lane & ~3);
    float inv0 = 1.f / l0, inv1 = 1.f / l1;
    const int qg0 = q0 + wq + g, qg1 = qg0 + 8;
    #pragma unroll
    for (int ni = 0; ni < 8; ni++) {
        int c = h * HD + ni * 8 + 2 * t;
        *(__half2*)&ctx[(size_t)(b * SEQ + qg0) * DOUT + c] =
            __floats2half2_rn(o[ni][0] * inv0, o[ni][1] * inv0);
        *(__half2*)&ctx[(size_t)(b * SEQ + qg1) * DOUT + c] =
            __floats2half2_rn(o[ni][2] * inv1, o[ni][3] * inv1);
    }
}

// ------------------------------- launcher -------------------------------------
extern "C" void kernel_launch(void* const* d_in, const int* in_sizes, int n_in,
                              void* d_out, int out_size)
{
    const float* x    = (const float*)d_in[0];
    const float* Wq   = (const float*)d_in[1];
    const float* Wk   = (const float*)d_in[2];
    const float* Wv   = (const float*)d_in[3];
    const float* Wo   = (const float*)d_in[4];
    const float* cosb = (const float*)d_in[5];
    const float* sinb = (const float*)d_in[6];
    float* out = (float*)d_out;

    __half *pXh, *pWqh, *pWkh, *pWvh, *pWoh, *pQr, *pKr, *pVr, *pCtx;
    cudaGetSymbolAddress((void**)&pXh,  g_xh);
    cudaGetSymbolAddress((void**)&pWqh, g_Wqh);
    cudaGetSymbolAddress((void**)&pWkh, g_Wkh);
    cudaGetSymbolAddress((void**)&pWvh, g_Wvh);
    cudaGetSymbolAddress((void**)&pWoh, g_Woh);
    cudaGetSymbolAddress((void**)&pQr,  g_Qr);
    cudaGetSymbolAddress((void**)&pKr,  g_Kr);
    cudaGetSymbolAddress((void**)&pVr,  g_Vr);
    cudaGetSymbolAddress((void**)&pCtx, g_ctx);

    dim3 thr(256);

    cudaFuncSetAttribute(qkv_h,  cudaFuncAttributeMaxDynamicSharedMemorySize, GEMM_SMEM);
    cudaFuncSetAttribute(wo_h,   cudaFuncAttributeMaxDynamicSharedMemorySize, GEMM_SMEM);
    cudaFuncSetAttribute(attn_h, cudaFuncAttributeMaxDynamicSharedMemorySize, ATTN_SMEM);

    // pre-conversion: x -> fp16; weights -> transposed fp16 [N][K] (one launch)
    cvt_x_k<<<(ROWS*DIN/8 + 255)/256, thr>>>((const float4*)x, (uint4*)pXh, ROWS*DIN/8);
    wtrans4_k<<<10240, thr>>>(Wq, Wk, Wv, Wo, pWqh, pWkh, pWvh, pWoh);

    // fused QKV projection + RoPE (+ Q log2-scale) + head-transpose
    qkv_h<<<dim3(24, ROWS/128), thr, GEMM_SMEM>>>(
        pXh, pWqh, pWkh, pWvh, cosb, sinb, pQr, pKr, pVr);

    // causal flash attention (fp16 tensor core, log2-domain softmax, 128-key tiles)
    attn_h<<<dim3(SEQ/128, BATCH*NH), thr, ATTN_SMEM>>>(pQr, pKr, pVr, pCtx);

    // output projection
    wo_h<<<dim3(DOUT/128, ROWS/128), thr, GEMM_SMEM>>>(pCtx, pWoh, out);
}

// round 14
// speedup vs baseline: 1.4671x; 1.0066x over previous
#include <cuda_runtime.h>
#include <cuda_fp16.h>
#include <stdint.h>

#define BATCH 2
#define SEQ   2048
#define DIN   2048
#define DOUT  2048
#define NH    32
#define NKV   8
#define HD    64
#define ROWS  (BATCH*SEQ)    /* 4096 */
#define DKV   (NKV*HD)       /* 512  */

// ---------------- scratch (static device arrays; no allocation) ----------------
__device__ __half g_xh [ROWS*DIN];     // x fp16 row-major [M][K]
__device__ __half g_Wqh[DOUT*DIN];     // Wq^T fp16 [N][K]
__device__ __half g_Wkh[DKV*DIN];      // Wk^T fp16 [N][K]
__device__ __half g_Wvh[DKV*DIN];      // Wv^T fp16 [N][K]
__device__ __half g_Woh[DOUT*DOUT];    // Wo^T fp16 [N][K]
__device__ __half g_Qr [ROWS*DOUT];    // [B,NH,S,HD]  (pre-scaled by 0.125*log2e)
__device__ __half g_Kr [ROWS*DKV];     // [B,NKV,S,HD]
__device__ __half g_Vr [ROWS*DKV];     // [B,NKV,S/4,HD,4] quad-interleaved
__device__ __half g_ctx[ROWS*DOUT];    // [B*S, NH*HD]

__device__ __forceinline__ void mma_f16(float* c, const uint32_t* a,
                                        uint32_t b0, uint32_t b1) {
    asm volatile(
        "mma.sync.aligned.m16n8k16.row.col.f32.f16.f16.f32 "
        "{%0,%1,%2,%3}, {%4,%5,%6,%7}, {%8,%9}, {%0,%1,%2,%3};"
        : "+f"(c[0]), "+f"(c[1]), "+f"(c[2]), "+f"(c[3])
        : "r"(a[0]), "r"(a[1]), "r"(a[2]), "r"(a[3]), "r"(b0), "r"(b1));
}

__device__ __forceinline__ void cp16(uint32_t smem_byte, const void* g) {
    asm volatile("cp.async.cg.shared.global [%0], [%1], 16;\n"
                 :: "r"(smem_byte), "l"(g));
}
__device__ __forceinline__ void cp_commit() {
    asm volatile("cp.async.commit_group;\n" ::);
}
template <int N>
__device__ __forceinline__ void cp_wait() {
    asm volatile("cp.async.wait_group %0;\n" :: "n"(N));
}
__device__ __forceinline__ uint32_t smem_u32(const void* p) {
    return (uint32_t)__cvta_generic_to_shared(p);
}

#define QLOGSCALE 0.1803368801111204f   /* 0.125 * log2(e) */

// ---------------- pre-kernels ---------------------------------------------------
__global__ __launch_bounds__(256) void cvt_x_k(const float4* __restrict__ in,
                                               uint4* __restrict__ out, int n8)
{
    int i = blockIdx.x * blockDim.x + threadIdx.x;
    if (i < n8) {
        float4 v0 = in[2 * i], v1 = in[2 * i + 1];
        __half2 h0 = __floats2half2_rn(v0.x, v0.y);
        __half2 h1 = __floats2half2_rn(v0.z, v0.w);
        __half2 h2 = __floats2half2_rn(v1.x, v1.y);
        __half2 h3 = __floats2half2_rn(v1.z, v1.w);
        uint4 u;
        u.x = *(uint32_t*)&h0; u.y = *(uint32_t*)&h1;
        u.z = *(uint32_t*)&h2; u.w = *(uint32_t*)&h3;
        out[i] = u;
    }
}

// Fused 4-way weight transpose: W [K][N] fp32 -> Wt [N][K] fp16.
__global__ __launch_bounds__(256) void wtrans4_k(
    const float* __restrict__ Wq, const float* __restrict__ Wk,
    const float* __restrict__ Wv, const float* __restrict__ Wo,
    __half* __restrict__ oq, __half* __restrict__ ok,
    __half* __restrict__ ov, __half* __restrict__ oo)
{
    __shared__ __half t[32][34];
    int bid = blockIdx.x;
    const float* W; __half* out; int K, N, tile;
    if (bid < 4096)      { W = Wq; out = oq; K = DIN;  N = DOUT; tile = bid; }
    else if (bid < 5120) { W = Wk; out = ok; K = DIN;  N = DKV;  tile = bid - 4096; }
    else if (bid < 6144) { W = Wv; out = ov; K = DIN;  N = DKV;  tile = bid - 5120; }
    else                 { W = Wo; out = oo; K = DOUT; N = DOUT; tile = bid - 6144; }
    const int ntn = N / 32;
    int kb = (tile / ntn) * 32, nb = (tile % ntn) * 32;
    int tx = threadIdx.x & 31, ty = threadIdx.x >> 5;
    #pragma unroll
    for (int i = 0; i < 4; i++)
        t[ty + 8*i][tx] = __float2half_rn(W[(size_t)(kb + ty + 8*i) * N + nb + tx]);
    __syncthreads();
    #pragma unroll
    for (int i = 0; i < 4; i++)
        out[(size_t)(nb + ty + 8*i) * K + kb + tx] = t[tx][ty + 8*i];
}

// ================= fp16 GEMM mainloop: 3-stage pipeline, 1 barrier/k-tile ======
// smem: 3 bufs x (A 16KB + B 16KB) = 96KB. 2 CTAs/SM (192KB).
#define GEMM_SMEM 98304

__device__ __forceinline__ void gemm_mainloop_h(
    const __half* __restrict__ A, const __half* __restrict__ Bt,
    int K, int row0, int col0, char* smem, float acc[2][8][4])
{
    const int tid  = threadIdx.x;
    const int lane = tid & 31, warp = tid >> 5;
    const int g = lane >> 2, t = lane & 3;
    const int wm = (warp & 3) * 32, wn = (warp >> 2) * 64;
    const uint32_t sBase = smem_u32(smem);

    const int a_r = tid >> 1;
    const int c8b = (tid & 1) * 4;

    auto LOAD = [&](int k0, int buf) {
        const uint32_t bb = sBase + (uint32_t)buf * 32768;
        #pragma unroll
        for (int j = 0; j < 4; j++) {
            const int c8 = c8b + j;
            const int kb = c8 >> 1, part = c8 & 1;
            const uint32_t off = (uint32_t)((kb * 128 + a_r) * 32 + part * 16);
            cp16(bb + off,         A  + (size_t)(row0 + a_r) * K + k0 + c8 * 8);
            cp16(bb + 16384 + off, Bt + (size_t)(col0 + a_r) * K + k0 + c8 * 8);
        }
        cp_commit();
    };

    #pragma unroll
    for (int mi = 0; mi < 2; mi++)
        #pragma unroll
        for (int ni = 0; ni < 8; ni++)
            #pragma unroll
            for (int r = 0; r < 4; r++) acc[mi][ni][r] = 0.f;

    const int niter = K / 64;
    LOAD(0, 0);
    LOAD(64, 1);

    for (int it = 0; it < niter; it++) {
        if (it < niter - 1) cp_wait<1>();   // drains group it (oldest of 2)
        else                cp_wait<0>();
        __syncthreads();                    // all warps done with buf (it-1)%3
        if (it + 2 < niter)
            LOAD((it + 2) * 64, (it + 2) % 3);   // overwrites buf computed at it-1

        const char* Ab = smem + (it % 3) * 32768;
        const char* Bb = Ab + 16384;
        #pragma unroll
        for (int kb = 0; kb < 4; kb++) {
            uint32_t a[2][4]; uint2 bb[8];
            #pragma unroll
            for (int mi = 0; mi < 2; mi++) {
                const char* base = Ab + (kb * 128 + wm + mi * 16 + g) * 32 + t * 8;
                uint2 lo = *(const uint2*)base;
                uint2 hi = *(const uint2*)(base + 8 * 32);
                a[mi][0] = lo.x; a[mi][1] = hi.x; a[mi][2] = lo.y; a[mi][3] = hi.y;
            }
            #pragma unroll
            for (int ni = 0; ni < 8; ni++)
                bb[ni] = *(const uint2*)(Bb + (kb * 128 + wn + ni * 8 + g) * 32 + t * 8);
            #pragma unroll
            for (int mi = 0; mi < 2; mi++)
                #pragma unroll
                for (int ni = 0; ni < 8; ni++)
                    mma_f16(acc[mi][ni], a[mi], bb[ni].x, bb[ni].y);
        }
    }
}

// ================= fused QKV projection + RoPE + transpose =====================
// grid (24, 32): bx<16 Q (RoPE + log2-scale), <20 K (RoPE), else V (quad pack).
__global__ __launch_bounds__(256, 2) void qkv_h(
    const __half* __restrict__ xh,
    const __half* __restrict__ Wqh, const __half* __restrict__ Wkh,
    const __half* __restrict__ Wvh,
    const float* __restrict__ cosb, const float* __restrict__ sinb,
    __half* __restrict__ Qr, __half* __restrict__ Kr, __half* __restrict__ Vr)
{
    extern __shared__ char smem[];
    const int bx = blockIdx.x;
    const __half* W; __half* outp; int col0, nh, kind; float qs;
    if (bx < 16)      { W = Wqh; outp = Qr; col0 = bx * 128;        nh = NH;  kind = 0; qs = QLOGSCALE; }
    else if (bx < 20) { W = Wkh; outp = Kr; col0 = (bx - 16) * 128; nh = NKV; kind = 0; qs = 1.f; }
    else              { W = Wvh; outp = Vr; col0 = (bx - 20) * 128; nh = NKV; kind = 1; qs = 1.f; }
    const int row0 = blockIdx.y * 128;

    float acc[2][8][4];
    gemm_mainloop_h(xh, W, DIN, row0, col0, smem, acc);

    const int lane = threadIdx.x & 31, warp = threadIdx.x >> 5;
    const int g = lane >> 2, t = lane & 3;
    const int wm = (warp & 3) * 32, wn = (warp >> 2) * 64;
    const int hq = (col0 + wn) >> 6;

    #pragma unroll
    for (int mi = 0; mi < 2; mi++) {
        const int rbase = row0 + wm + mi * 16 + g;
        #pragma unroll
        for (int v = 0; v < 2; v++) {
            const int r = rbase + v * 8;
            const int b = r >> 11, s = r & 2047;
            if (kind == 0) {
                __half* row = outp + ((size_t)(b * nh + hq) * SEQ + s) * HD;
                const float* cs = cosb + s * HD;
                const float* sn = sinb + s * HD;
                #pragma unroll
                for (int ni = 0; ni < 4; ni++) {
                    const int d = ni * 8 + 2 * t;
                    float x1a = acc[mi][ni    ][v*2], x1b = acc[mi][ni    ][v*2+1];
                    float x2a = acc[mi][ni + 4][v*2], x2b = acc[mi][ni + 4][v*2+1];
                    float2 c1 = *(const float2*)&cs[d];
                    float2 s1 = *(const float2*)&sn[d];
                    float2 c2 = *(const float2*)&cs[d + 32];
                    float2 s2 = *(const float2*)&sn[d + 32];
                    *(__half2*)&row[d] =
                        __floats2half2_rn((x1a * c1.x - x2a * s1.x) * qs,
                                          (x1b * c1.y - x2b * s1.y) * qs);
                    *(__half2*)&row[d + 32] =
                        __floats2half2_rn((x2a * c2.x + x1a * s2.x) * qs,
                                          (x2b * c2.y + x1b * s2.y) * qs);
                }
            } else {
                // V quad-interleave: [S/4][HD][4]
                __half* hb = outp + (size_t)(b * nh + hq) * SEQ * HD;
                const size_t sb = (size_t)(s >> 2) * (HD * 4) + (s & 3);
                #pragma unroll
                for (int ni = 0; ni < 8; ni++) {
                    const int d = ni * 8 + 2 * t;
                    hb[sb + (size_t)d * 4]       = __float2half_rn(acc[mi][ni][v*2]);
                    hb[sb + (size_t)(d + 1) * 4] = __float2half_rn(acc[mi][ni][v*2+1]);
                }
            }
        }
    }
}

// ================= output projection ===========================================
__global__ __launch_bounds__(256, 2) void wo_h(
    const __half* __restrict__ ctx, const __half* __restrict__ Woh,
    float* __restrict__ out)
{
    extern __shared__ char smem[];
    const int row0 = blockIdx.y * 128, col0 = blockIdx.x * 128;

    float acc[2][8][4];
    gemm_mainloop_h(ctx, Woh, DOUT, row0, col0, smem, acc);

    const int lane = threadIdx.x & 31, warp = threadIdx.x >> 5;
    const int g = lane >> 2, t = lane & 3;
    const int wm = (warp & 3) * 32, wn = (warp >> 2) * 64;

    #pragma unroll
    for (int mi = 0; mi < 2; mi++)
        #pragma unroll
        for (int ni = 0; ni < 8; ni++) {
            const int r = row0 + wm + mi * 16 + g;
            const int c = col0 + wn + ni * 8 + t * 2;
            *(float2*)(out + (size_t)r * DOUT + c) =
                make_float2(acc[mi][ni][0], acc[mi][ni][1]);
            *(float2*)(out + (size_t)(r + 8) * DOUT + c) =
                make_float2(acc[mi][ni][2], acc[mi][ni][3]);
        }
}

// ================= fp16 flash attention (128-key tiles, 2 sub-iters) ===========
#define KTB 20480                  /* 128*160 */
#define VST 608
#define VTB (32*VST)               /* 19456 */
#define ATTN_SMEM (20480 + 2*KTB + 2*VTB)   /* 100352 */

__global__ __launch_bounds__(256) void attn_h(
    const __half* __restrict__ Qr, const __half* __restrict__ Kr,
    const __half* __restrict__ Vr, __half* __restrict__ ctx)
{
    extern __shared__ char sm[];
    char* Pq = sm;                 // [128][160B]  Q staging, then P
    char* Ks = sm + 20480;         // [2][128][160B]
    char* Vs = sm + 20480 + 2 * KTB;   // [2][32][608B]

    const int bh = blockIdx.y;
    const int b = bh >> 5, h = bh & 31, g2 = h >> 2;
    const int qt = gridDim.x - 1 - blockIdx.x;     // heavy tiles first
    const int q0 = qt * 128;
    const int tid = threadIdx.x;
    const int warp = tid >> 5, lane = tid & 31;
    const int g = lane >> 2, t = lane & 3;
    const int wq = warp * 16;

    const __half* Qbase = Qr + ((size_t)bh * SEQ + q0) * HD;
    const __half* Kbase = Kr + (size_t)(b * NKV + g2) * SEQ * HD;
    const __half* Vbase = Vr + (size_t)(b * NKV + g2) * SEQ * HD;   // quad layout

    const uint32_t sK = smem_u32(Ks);
    const uint32_t sV = smem_u32(Vs);
    const uint32_t sP = smem_u32(Pq);

    auto LOADKV = [&](int k0, int buf) {
        #pragma unroll
        for (int i = 0; i < 4; i++) {
            const int ch = tid + i * 256;
            const int row = ch >> 3, c8 = ch & 7;
            cp16(sK + (uint32_t)(buf * KTB + row * 160 + c8 * 16),
                 Kbase + (size_t)(k0 + row) * HD + c8 * 8);
            const int sblk = ch >> 5, c = ch & 31;
            cp16(sV + (uint32_t)(buf * VTB + sblk * VST + c * 16),
                 Vbase + (size_t)k0 * 64 + sblk * 256 + c * 8);
        }
        cp_commit();
    };

    // ones/zero pad columns of V smem: 64 quad-rows (2 bufs x 32) x 96B.
    {
        const int row = tid >> 2, part = tid & 3;
        char* rp = Vs + (row < 32 ? row * VST : VTB + (row - 32) * VST) + 512;
        #pragma unroll
        for (int bgo = 0; bgo < 24; bgo += 4) {
            int off = part * 24 + bgo;
            uint32_t val = (off < 8) ? 0x3C003C00u : 0u;   // d=64 halves = 1.0
            *(uint32_t*)(rp + off) = val;
        }
    }

    // stage Q FIRST, then prefetch KV0; wait<1> drains Q while KV0 flies.
    #pragma unroll
    for (int i = 0; i < 4; i++) {
        const int ch = tid + i * 256;
        const int row = ch >> 3, c8 = ch & 7;
        cp16(sP + (uint32_t)(row * 160 + c8 * 16), Qbase + (size_t)row * HD + c8 * 8);
    }
    cp_commit();
    LOADKV(0, 0);
    cp_wait<1>();
    __syncthreads();

    uint32_t qf[4][4];
    #pragma unroll
    for (int ds = 0; ds < 4; ds++) {
        const char* base = Pq + (wq + g) * 160 + ds * 32 + t * 8;
        uint2 lo = *(const uint2*)base;
        uint2 hi = *(const uint2*)(base + 8 * 160);
        qf[ds][0] = lo.x; qf[ds][1] = hi.x; qf[ds][2] = lo.y; qf[ds][3] = hi.y;
    }
    __syncthreads();   // Q regs everywhere before Pq reuse; also covers ones-init

    float o[9][4];     // o[8] = running row-sum (ones column)
    #pragma unroll
    for (int ni = 0; ni < 9; ni++)
        #pragma unroll
        for (int r = 0; r < 4; r++) o[ni][r] = 0.f;
    float m0 = -1e30f, m1 = -1e30f;

    const int nt128 = qt + 1;
    for (int tt = 0; tt < nt128; tt++) {
        const int buf = tt & 1;
        if (tt + 1 < nt128) {
            LOADKV((tt + 1) * 128, buf ^ 1);
            cp_wait<1>();
        } else {
            cp_wait<0>();
        }
        __syncthreads();

        #pragma unroll
        for (int sub = 0; sub < 2; sub++) {
            const char* Ksb = Ks + buf * KTB + sub * 64 * 160;
            const char* Vsb = Vs + buf * VTB + sub * 16 * VST;
            const int k0 = tt * 128 + sub * 64;

            // ---- S = Q @ K^T  (log2 domain via pre-scaled Q)
            float s[8][4];
            #pragma unroll
            for (int ni = 0; ni < 8; ni++)
                #pragma unroll
                for (int r = 0; r < 4; r++) s[ni][r] = 0.f;

            #pragma unroll
            for (int ds = 0; ds < 4; ds++) {
                #pragma unroll
                for (int ni = 0; ni < 8; ni++) {
                    uint2 kb2 = *(const uint2*)(Ksb + (ni * 8 + g) * 160 + ds * 32 + t * 8);
                    mma_f16(s[ni], qf[ds], kb2.x, kb2.y);
                }
            }

            // ---- causal mask
            const bool do_mask = (k0 + 63 > q0);
            const int qg0 = q0 + wq + g, qg1 = qg0 + 8;
            if (do_mask) {
                #pragma unroll
                for (int ni = 0; ni < 8; ni++) {
                    #pragma unroll
                    for (int r = 0; r < 4; r++) {
                        int kg = k0 + ni * 8 + 2 * t + (r & 1);
                        int qg = (r >= 2) ? qg1 : qg0;
                        if (kg > qg) s[ni][r] = -1e30f;
                    }
                }
            }

            // ---- online softmax (log2 domain)
            float tm0 = -1e30f, tm1 = -1e30f;
            #pragma unroll
            for (int ni = 0; ni < 8; ni++) {
                tm0 = fmaxf(tm0, fmaxf(s[ni][0], s[ni][1]));
                tm1 = fmaxf(tm1, fmaxf(s[ni][2], s[ni][3]));
            }
            tm0 = fmaxf(tm0, __shfl_xor_sync(0xffffffffu, tm0, 1));
            tm0 = fmaxf(tm0, __shfl_xor_sync(0xffffffffu, tm0, 2));
            tm1 = fmaxf(tm1, __shfl_xor_sync(0xffffffffu, tm1, 1));
            tm1 = fmaxf(tm1, __shfl_xor_sync(0xffffffffu, tm1, 2));

            float mn0 = fmaxf(m0, tm0), mn1 = fmaxf(m1, tm1);
            float a0 = exp2f(m0 - mn0), a1 = exp2f(m1 - mn1);
            m0 = mn0; m1 = mn1;

            #pragma unroll
            for (int ni = 0; ni < 9; ni++) {
                o[ni][0] *= a0; o[ni][1] *= a0;
                o[ni][2] *= a1; o[ni][3] *= a1;
            }

            // P = 2^(s - m), fp16 packed, stored directly
            #pragma unroll
            for (int ni = 0; ni < 8; ni++) {
                __half2 p0 = h2exp2(__floats2half2_rn(s[ni][0] - mn0, s[ni][1] - mn0));
                __half2 p1 = h2exp2(__floats2half2_rn(s[ni][2] - mn1, s[ni][3] - mn1));
                *(__half2*)(Pq + (wq + g    ) * 160 + (ni * 8 + 2 * t) * 2) = p0;
                *(__half2*)(Pq + (wq + g + 8) * 160 + (ni * 8 + 2 * t) * 2) = p1;
            }
            __syncwarp();   // P rows produced/consumed within same warp

            // ---- O += P @ V  (9th n-block = ones column -> row sums in o[8])
            #pragma unroll
            for (int ks = 0; ks < 4; ks++) {
                uint32_t a[4];
                const char* base = Pq + (wq + g) * 160 + ks * 32 + t * 8;
                uint2 lo = *(const uint2*)base;
                uint2 hi = *(const uint2*)(base + 8 * 160);
                a[0] = lo.x; a[1] = hi.x; a[2] = lo.y; a[3] = hi.y;
                #pragma unroll
                for (int ni = 0; ni < 9; ni++) {
                    uint2 vb = *(const uint2*)(Vsb + (ks * 4 + t) * VST + (ni * 8 + g) * 8);
                    mma_f16(o[ni], a, vb.x, vb.y);
                }
            }
        }
        __syncthreads();
    }

    // ---- epilogue: l lives in o[8] col 64 (t==0 lane of each quad)
    float l0 = __shfl_sync(0xffffffffu, o[8][0], lane & ~3);
    float l1 = __shfl_sync(0xffffffffu, o[8][2], lane & ~3);
    float inv0 = 1.f / l0, inv1 = 1.f / l1;
    const int qg0 = q0 + wq + g, qg1 = qg0 + 8;
    #pragma unroll
    for (int ni = 0; ni < 8; ni++) {
        int c = h * HD + ni * 8 + 2 * t;
        *(__half2*)&ctx[(size_t)(b * SEQ + qg0) * DOUT + c] =
            __floats2half2_rn(o[ni][0] * inv0, o[ni][1] * inv0);
        *(__half2*)&ctx[(size_t)(b * SEQ + qg1) * DOUT + c] =
            __floats2half2_rn(o[ni][2] * inv1, o[ni][3] * inv1);
    }
}

// ------------------------------- launcher -------------------------------------
extern "C" void kernel_launch(void* const* d_in, const int* in_sizes, int n_in,
                              void* d_out, int out_size)
{
    const float* x    = (const float*)d_in[0];
    const float* Wq   = (const float*)d_in[1];
    const float* Wk   = (const float*)d_in[2];
    const float* Wv   = (const float*)d_in[3];
    const float* Wo   = (const float*)d_in[4];
    const float* cosb = (const float*)d_in[5];
    const float* sinb = (const float*)d_in[6];
    float* out = (float*)d_out;

    __half *pXh, *pWqh, *pWkh, *pWvh, *pWoh, *pQr, *pKr, *pVr, *pCtx;
    cudaGetSymbolAddress((void**)&pXh,  g_xh);
    cudaGetSymbolAddress((void**)&pWqh, g_Wqh);
    cudaGetSymbolAddress((void**)&pWkh, g_Wkh);
    cudaGetSymbolAddress((void**)&pWvh, g_Wvh);
    cudaGetSymbolAddress((void**)&pWoh, g_Woh);
    cudaGetSymbolAddress((void**)&pQr,  g_Qr);
    cudaGetSymbolAddress((void**)&pKr,  g_Kr);
    cudaGetSymbolAddress((void**)&pVr,  g_Vr);
    cudaGetSymbolAddress((void**)&pCtx, g_ctx);

    dim3 thr(256);

    cudaFuncSetAttribute(qkv_h,  cudaFuncAttributeMaxDynamicSharedMemorySize, GEMM_SMEM);
    cudaFuncSetAttribute(wo_h,   cudaFuncAttributeMaxDynamicSharedMemorySize, GEMM_SMEM);
    cudaFuncSetAttribute(attn_h, cudaFuncAttributeMaxDynamicSharedMemorySize, ATTN_SMEM);

    // pre-conversion: x -> fp16; weights -> transposed fp16 [N][K] (one launch)
    cvt_x_k<<<(ROWS*DIN/8 + 255)/256, thr>>>((const float4*)x, (uint4*)pXh, ROWS*DIN/8);
    wtrans4_k<<<10240, thr>>>(Wq, Wk, Wv, Wo, pWqh, pWkh, pWvh, pWoh);

    // fused QKV projection + RoPE (+ Q log2-scale) + head-transpose
    qkv_h<<<dim3(24, ROWS/128), thr, GEMM_SMEM>>>(
        pXh, pWqh, pWkh, pWvh, cosb, sinb, pQr, pKr, pVr);

    // causal flash attention (fp16 tensor core, log2-domain softmax)
    attn_h<<<dim3(SEQ/128, BATCH*NH), thr, ATTN_SMEM>>>(pQr, pKr, pVr, pCtx);

    // output projection
    wo_h<<<dim3(DOUT/128, ROWS/128), thr, GEMM_SMEM>>>(pCtx, pWoh, out);
}

// round 16
// speedup vs baseline: 1.6336x; 1.1135x over previous
#include <cuda_runtime.h>
#include <cuda_fp16.h>
#include <stdint.h>

#define BATCH 2
#define SEQ   2048
#define DIN   2048
#define DOUT  2048
#define NH    32
#define NKV   8
#define HD    64
#define ROWS  (BATCH*SEQ)    /* 4096 */
#define DKV   (NKV*HD)       /* 512  */

// ---------------- scratch (static device arrays; no allocation) ----------------
__device__ __half g_xh [ROWS*DIN];     // x fp16 row-major [M][K]
__device__ __half g_Wqh[DOUT*DIN];     // Wq^T fp16 [N][K]
__device__ __half g_Wkh[DKV*DIN];      // Wk^T fp16 [N][K]
__device__ __half g_Wvh[DKV*DIN];      // Wv^T fp16 [N][K]
__device__ __half g_Woh[DOUT*DOUT];    // Wo^T fp16 [N][K]
__device__ __half g_Qr [ROWS*DOUT];    // [B,NH,S,HD]  (pre-scaled by 0.125*log2e)
__device__ __half g_Kr [ROWS*DKV];     // [B,NKV,S,HD]
__device__ __half g_Vr [ROWS*DKV];     // [B,NKV,S/4,HD,4] quad-interleaved
__device__ __half g_ctx[ROWS*DOUT];    // [B*S, NH*HD]

__device__ __forceinline__ void mma_f16(float* c, const uint32_t* a,
                                        uint32_t b0, uint32_t b1) {
    asm volatile(
        "mma.sync.aligned.m16n8k16.row.col.f32.f16.f16.f32 "
        "{%0,%1,%2,%3}, {%4,%5,%6,%7}, {%8,%9}, {%0,%1,%2,%3};"
        : "+f"(c[0]), "+f"(c[1]), "+f"(c[2]), "+f"(c[3])
        : "r"(a[0]), "r"(a[1]), "r"(a[2]), "r"(a[3]), "r"(b0), "r"(b1));
}

__device__ __forceinline__ void ldsm_x4(uint32_t* r, uint32_t addr) {
    asm volatile("ldmatrix.sync.aligned.m8n8.x4.shared.b16 {%0,%1,%2,%3}, [%4];"
        : "=r"(r[0]), "=r"(r[1]), "=r"(r[2]), "=r"(r[3]) : "r"(addr));
}

__device__ __forceinline__ void cp16(uint32_t smem_byte, const void* g) {
    asm volatile("cp.async.cg.shared.global [%0], [%1], 16;\n"
                 :: "r"(smem_byte), "l"(g));
}
__device__ __forceinline__ void cp_commit() {
    asm volatile("cp.async.commit_group;\n" ::);
}
template <int N>
__device__ __forceinline__ void cp_wait() {
    asm volatile("cp.async.wait_group %0;\n" :: "n"(N));
}
__device__ __forceinline__ uint32_t smem_u32(const void* p) {
    return (uint32_t)__cvta_generic_to_shared(p);
}

#define QLOGSCALE 0.1803368801111204f   /* 0.125 * log2(e) */

// ---------------- pre-kernels ---------------------------------------------------
__global__ __launch_bounds__(256) void cvt_x_k(const float4* __restrict__ in,
                                               uint4* __restrict__ out, int n8)
{
    int i = blockIdx.x * blockDim.x + threadIdx.x;
    if (i < n8) {
        float4 v0 = in[2 * i], v1 = in[2 * i + 1];
        __half2 h0 = __floats2half2_rn(v0.x, v0.y);
        __half2 h1 = __floats2half2_rn(v0.z, v0.w);
        __half2 h2 = __floats2half2_rn(v1.x, v1.y);
        __half2 h3 = __floats2half2_rn(v1.z, v1.w);
        uint4 u;
        u.x = *(uint32_t*)&h0; u.y = *(uint32_t*)&h1;
        u.z = *(uint32_t*)&h2; u.w = *(uint32_t*)&h3;
        out[i] = u;
    }
}

// Fused 4-way weight transpose: W [K][N] fp32 -> Wt [N][K] fp16.
__global__ __launch_bounds__(256) void wtrans4_k(
    const float* __restrict__ Wq, const float* __restrict__ Wk,
    const float* __restrict__ Wv, const float* __restrict__ Wo,
    __half* __restrict__ oq, __half* __restrict__ ok,
    __half* __restrict__ ov, __half* __restrict__ oo)
{
    __shared__ __half t[32][34];
    int bid = blockIdx.x;
    const float* W; __half* out; int K, N, tile;
    if (bid < 4096)      { W = Wq; out = oq; K = DIN;  N = DOUT; tile = bid; }
    else if (bid < 5120) { W = Wk; out = ok; K = DIN;  N = DKV;  tile = bid - 4096; }
    else if (bid < 6144) { W = Wv; out = ov; K = DIN;  N = DKV;  tile = bid - 5120; }
    else                 { W = Wo; out = oo; K = DOUT; N = DOUT; tile = bid - 6144; }
    const int ntn = N / 32;
    int kb = (tile / ntn) * 32, nb = (tile % ntn) * 32;
    int tx = threadIdx.x & 31, ty = threadIdx.x >> 5;
    #pragma unroll
    for (int i = 0; i < 4; i++)
        t[ty + 8*i][tx] = __float2half_rn(W[(size_t)(kb + ty + 8*i) * N + nb + tx]);
    __syncthreads();
    #pragma unroll
    for (int i = 0; i < 4; i++)
        out[(size_t)(nb + ty + 8*i) * K + kb + tx] = t[tx][ty + 8*i];
}

// ================= fp16 GEMM mainloop: 3-stage pipeline + ldmatrix =============
// smem: 3 bufs x (A 16KB + B 16KB) = 96KB. 2 CTAs/SM.
// Rows are 32B (16 halves); 16B chunks XOR-swizzled: p = c ^ ((row>>2)&1)
// so each ldmatrix 8-row gather hits 8 distinct bank quads.
// B stored [n][k] -> NON-trans ldmatrix yields the canonical mma B fragment
// (consecutive-k pair per n).
#define GEMM_SMEM 98304

__device__ __forceinline__ void gemm_mainloop_h(
    const __half* __restrict__ A, const __half* __restrict__ Bt,
    int K, int row0, int col0, char* smem, float acc[2][8][4])
{
    const int tid  = threadIdx.x;
    const int lane = tid & 31, warp = tid >> 5;
    const int wm = (warp & 3) * 32, wn = (warp >> 2) * 64;
    const uint32_t sBase = smem_u32(smem);

    const int a_r = tid >> 1;
    const int c8b = (tid & 1) * 4;

    auto LOAD = [&](int k0, int buf) {
        const uint32_t bb = sBase + (uint32_t)buf * 32768;
        #pragma unroll
        for (int j = 0; j < 4; j++) {
            const int c8 = c8b + j;                 // logical chunk: kb*2 + part
            const int kb = c8 >> 1, part = c8 & 1;
            const int sw = part ^ ((a_r >> 2) & 1); // swizzled 16B slot
            const uint32_t off = (uint32_t)((kb * 128 + a_r) * 32 + sw * 16);
            cp16(bb + off,         A  + (size_t)(row0 + a_r) * K + k0 + c8 * 8);
            cp16(bb + 16384 + off, Bt + (size_t)(col0 + a_r) * K + k0 + c8 * 8);
        }
        cp_commit();
    };

    // ldmatrix lane addresses (within a kb block, before +kb*4096)
    uint32_t aoff[2], boff[4];
    #pragma unroll
    for (int mi = 0; mi < 2; mi++) {
        int row = wm + mi * 16 + ((lane >> 3) & 1) * 8 + (lane & 7);
        int c   = (lane >> 4) & 1;                  // chunk select (k0-7 / k8-15)
        aoff[mi] = (uint32_t)(row * 32 + (c ^ ((row >> 2) & 1)) * 16);
    }
    #pragma unroll
    for (int np = 0; np < 4; np++) {
        int row = wn + np * 16 + ((lane >> 4) & 1) * 8 + (lane & 7);
        int c   = (lane >> 3) & 1;
        boff[np] = (uint32_t)(row * 32 + (c ^ ((row >> 2) & 1)) * 16);
    }

    #pragma unroll
    for (int mi = 0; mi < 2; mi++)
        #pragma unroll
        for (int ni = 0; ni < 8; ni++)
            #pragma unroll
            for (int r = 0; r < 4; r++) acc[mi][ni][r] = 0.f;

    const int niter = K / 64;
    LOAD(0, 0);
    LOAD(64, 1);

    for (int it = 0; it < niter; it++) {
        if (it < niter - 1) cp_wait<1>();
        else                cp_wait<0>();
        __syncthreads();
        if (it + 2 < niter)
            LOAD((it + 2) * 64, (it + 2) % 3);

        const uint32_t Ab = sBase + (uint32_t)(it % 3) * 32768;
        const uint32_t Bb = Ab + 16384;
        #pragma unroll
        for (int kb = 0; kb < 4; kb++) {
            uint32_t a[2][4], b[4][4];
            ldsm_x4(a[0], Ab + kb * 4096 + aoff[0]);
            ldsm_x4(a[1], Ab + kb * 4096 + aoff[1]);
            #pragma unroll
            for (int np = 0; np < 4; np++)
                ldsm_x4(b[np], Bb + kb * 4096 + boff[np]);
            #pragma unroll
            for (int mi = 0; mi < 2; mi++)
                #pragma unroll
                for (int np = 0; np < 4; np++) {
                    mma_f16(acc[mi][2 * np    ], a[mi], b[np][0], b[np][1]);
                    mma_f16(acc[mi][2 * np + 1], a[mi], b[np][2], b[np][3]);
                }
        }
    }
}

// ================= fused QKV projection + RoPE + transpose =====================
// grid (24, 32): bx<16 Q (RoPE + log2-scale), <20 K (RoPE), else V (quad pack).
__global__ __launch_bounds__(256, 2) void qkv_h(
    const __half* __restrict__ xh,
    const __half* __restrict__ Wqh, const __half* __restrict__ Wkh,
    const __half* __restrict__ Wvh,
    const float* __restrict__ cosb, const float* __restrict__ sinb,
    __half* __restrict__ Qr, __half* __restrict__ Kr, __half* __restrict__ Vr)
{
    extern __shared__ char smem[];
    const int bx = blockIdx.x;
    const __half* W; __half* outp; int col0, nh, kind; float qs;
    if (bx < 16)      { W = Wqh; outp = Qr; col0 = bx * 128;        nh = NH;  kind = 0; qs = QLOGSCALE; }
    else if (bx < 20) { W = Wkh; outp = Kr; col0 = (bx - 16) * 128; nh = NKV; kind = 0; qs = 1.f; }
    else              { W = Wvh; outp = Vr; col0 = (bx - 20) * 128; nh = NKV; kind = 1; qs = 1.f; }
    const int row0 = blockIdx.y * 128;

    float acc[2][8][4];
    gemm_mainloop_h(xh, W, DIN, row0, col0, smem, acc);

    const int lane = threadIdx.x & 31, warp = threadIdx.x >> 5;
    const int g = lane >> 2, t = lane & 3;
    const int wm = (warp & 3) * 32, wn = (warp >> 2) * 64;
    const int hq = (col0 + wn) >> 6;

    #pragma unroll
    for (int mi = 0; mi < 2; mi++) {
        const int rbase = row0 + wm + mi * 16 + g;
        #pragma unroll
        for (int v = 0; v < 2; v++) {
            const int r = rbase + v * 8;
            const int b = r >> 11, s = r & 2047;
            if (kind == 0) {
                __half* row = outp + ((size_t)(b * nh + hq) * SEQ + s) * HD;
                const float* cs = cosb + s * HD;
                const float* sn = sinb + s * HD;
                #pragma unroll
                for (int ni = 0; ni < 4; ni++) {
                    const int d = ni * 8 + 2 * t;
                    float x1a = acc[mi][ni    ][v*2], x1b = acc[mi][ni    ][v*2+1];
                    float x2a = acc[mi][ni + 4][v*2], x2b = acc[mi][ni + 4][v*2+1];
                    float2 c1 = *(const float2*)&cs[d];
                    float2 s1 = *(const float2*)&sn[d];
                    float2 c2 = *(const float2*)&cs[d + 32];
                    float2 s2 = *(const float2*)&sn[d + 32];
                    *(__half2*)&row[d] =
                        __floats2half2_rn((x1a * c1.x - x2a * s1.x) * qs,
                                          (x1b * c1.y - x2b * s1.y) * qs);
                    *(__half2*)&row[d + 32] =
                        __floats2half2_rn((x2a * c2.x + x1a * s2.x) * qs,
                                          (x2b * c2.y + x1b * s2.y) * qs);
                }
            } else {
                // V quad-interleave: [S/4][HD][4]
                __half* hb = outp + (size_t)(b * nh + hq) * SEQ * HD;
                const size_t sb = (size_t)(s >> 2) * (HD * 4) + (s & 3);
                #pragma unroll
                for (int ni = 0; ni < 8; ni++) {
                    const int d = ni * 8 + 2 * t;
                    hb[sb + (size_t)d * 4]       = __float2half_rn(acc[mi][ni][v*2]);
                    hb[sb + (size_t)(d + 1) * 4] = __float2half_rn(acc[mi][ni][v*2+1]);
                }
            }
        }
    }
}

// ================= output projection ===========================================
__global__ __launch_bounds__(256, 2) void wo_h(
    const __half* __restrict__ ctx, const __half* __restrict__ Woh,
    float* __restrict__ out)
{
    extern __shared__ char smem[];
    const int row0 = blockIdx.y * 128, col0 = blockIdx.x * 128;

    float acc[2][8][4];
    gemm_mainloop_h(ctx, Woh, DOUT, row0, col0, smem, acc);

    const int lane = threadIdx.x & 31, warp = threadIdx.x >> 5;
    const int g = lane >> 2, t = lane & 3;
    const int wm = (warp & 3) * 32, wn = (warp >> 2) * 64;

    #pragma unroll
    for (int mi = 0; mi < 2; mi++)
        #pragma unroll
        for (int ni = 0; ni < 8; ni++) {
            const int r = row0 + wm + mi * 16 + g;
            const int c = col0 + wn + ni * 8 + t * 2;
            *(float2*)(out + (size_t)r * DOUT + c) =
                make_float2(acc[mi][ni][0], acc[mi][ni][1]);
            *(float2*)(out + (size_t)(r + 8) * DOUT + c) =
                make_float2(acc[mi][ni][2], acc[mi][ni][3]);
        }
}

// ================= fp16 flash attention (128-key tiles, 2 sub-iters) ===========
#define KTB 20480                  /* 128*160 */
#define VST 608
#define VTB (32*VST)               /* 19456 */
#define ATTN_SMEM (20480 + 2*KTB + 2*VTB)   /* 100352 */

__global__ __launch_bounds__(256) void attn_h(
    const __half* __restrict__ Qr, const __half* __restrict__ Kr,
    const __half* __restrict__ Vr, __half* __restrict__ ctx)
{
    extern __shared__ char sm[];
    char* Pq = sm;                 // [128][160B]  Q staging, then P
    char* Ks = sm + 20480;         // [2][128][160B]
    char* Vs = sm + 20480 + 2 * KTB;   // [2][32][608B]

    const int bh = blockIdx.y;
    const int b = bh >> 5, h = bh & 31, g2 = h >> 2;
    const int qt = gridDim.x - 1 - blockIdx.x;     // heavy tiles first
    const int q0 = qt * 128;
    const int tid = threadIdx.x;
    const int warp = tid >> 5, lane = tid & 31;
    const int g = lane >> 2, t = lane & 3;
    const int wq = warp * 16;

    const __half* Qbase = Qr + ((size_t)bh * SEQ + q0) * HD;
    const __half* Kbase = Kr + (size_t)(b * NKV + g2) * SEQ * HD;
    const __half* Vbase = Vr + (size_t)(b * NKV + g2) * SEQ * HD;   // quad layout

    const uint32_t sK = smem_u32(Ks);
    const uint32_t sV = smem_u32(Vs);
    const uint32_t sP = smem_u32(Pq);

    auto LOADKV = [&](int k0, int buf) {
        #pragma unroll
        for (int i = 0; i < 4; i++) {
            const int ch = tid + i * 256;
            const int row = ch >> 3, c8 = ch & 7;
            cp16(sK + (uint32_t)(buf * KTB + row * 160 + c8 * 16),
                 Kbase + (size_t)(k0 + row) * HD + c8 * 8);
            const int sblk = ch >> 5, c = ch & 31;
            cp16(sV + (uint32_t)(buf * VTB + sblk * VST + c * 16),
                 Vbase + (size_t)k0 * 64 + sblk * 256 + c * 8);
        }
        cp_commit();
    };

    // ones/zero pad columns of V smem: 64 quad-rows (2 bufs x 32) x 96B.
    {
        const int row = tid >> 2, part = tid & 3;
        char* rp = Vs + (row < 32 ? row * VST : VTB + (row - 32) * VST) + 512;
        #pragma unroll
        for (int bgo = 0; bgo < 24; bgo += 4) {
            int off = part * 24 + bgo;
            uint32_t val = (off < 8) ? 0x3C003C00u : 0u;   // d=64 halves = 1.0
            *(uint32_t*)(rp + off) = val;
        }
    }

    // stage Q FIRST, then prefetch KV0; wait<1> drains Q while KV0 flies.
    #pragma unroll
    for (int i = 0; i < 4; i++) {
        const int ch = tid + i * 256;
        const int row = ch >> 3, c8 = ch & 7;
        cp16(sP + (uint32_t)(row * 160 + c8 * 16), Qbase + (size_t)row * HD + c8 * 8);
    }
    cp_commit();
    LOADKV(0, 0);
    cp_wait<1>();
    __syncthreads();

    uint32_t qf[4][4];
    #pragma unroll
    for (int ds = 0; ds < 4; ds++) {
        const char* base = Pq + (wq + g) * 160 + ds * 32 + t * 8;
        uint2 lo = *(const uint2*)base;
        uint2 hi = *(const uint2*)(base + 8 * 160);
        qf[ds][0] = lo.x; qf[ds][1] = hi.x; qf[ds][2] = lo.y; qf[ds][3] = hi.y;
    }
    __syncthreads();   // Q regs everywhere before Pq reuse; also covers ones-init

    float o[9][4];     // o[8] = running row-sum (ones column)
    #pragma unroll
    for (int ni = 0; ni < 9; ni++)
        #pragma unroll
        for (int r = 0; r < 4; r++) o[ni][r] = 0.f;
    float m0 = -1e30f, m1 = -1e30f;

    const int nt128 = qt + 1;
    for (int tt = 0; tt < nt128; tt++) {
        const int buf = tt & 1;
        if (tt + 1 < nt128) {
            LOADKV((tt + 1) * 128, buf ^ 1);
            cp_wait<1>();
        } else {
            cp_wait<0>();
        }
        __syncthreads();

        #pragma unroll
        for (int sub = 0; sub < 2; sub++) {
            const char* Ksb = Ks + buf * KTB + sub * 64 * 160;
            const char* Vsb = Vs + buf * VTB + sub * 16 * VST;
            const int k0 = tt * 128 + sub * 64;

            // ---- S = Q @ K^T  (log2 domain via pre-scaled Q)
            float s[8][4];
            #pragma unroll
            for (int ni = 0; ni < 8; ni++)
                #pragma unroll
                for (int r = 0; r < 4; r++) s[ni][r] = 0.f;

            #pragma unroll
            for (int ds = 0; ds < 4; ds++) {
                #pragma unroll
                for (int ni = 0; ni < 8; ni++) {
                    uint2 kb2 = *(const uint2*)(Ksb + (ni * 8 + g) * 160 + ds * 32 + t * 8);
                    mma_f16(s[ni], qf[ds], kb2.x, kb2.y);
                }
            }

            // ---- causal mask
            const bool do_mask = (k0 + 63 > q0);
            const int qg0 = q0 + wq + g, qg1 = qg0 + 8;
            if (do_mask) {
                #pragma unroll
                for (int ni = 0; ni < 8; ni++) {
                    #pragma unroll
                    for (int r = 0; r < 4; r++) {
                        int kg = k0 + ni * 8 + 2 * t + (r & 1);
                        int qg = (r >= 2) ? qg1 : qg0;
                        if (kg > qg) s[ni][r] = -1e30f;
                    }
                }
            }

            // ---- online softmax (log2 domain)
            float tm0 = -1e30f, tm1 = -1e30f;
            #pragma unroll
            for (int ni = 0; ni < 8; ni++) {
                tm0 = fmaxf(tm0, fmaxf(s[ni][0], s[ni][1]));
                tm1 = fmaxf(tm1, fmaxf(s[ni][2], s[ni][3]));
            }
            tm0 = fmaxf(tm0, __shfl_xor_sync(0xffffffffu, tm0, 1));
            tm0 = fmaxf(tm0, __shfl_xor_sync(0xffffffffu, tm0, 2));
            tm1 = fmaxf(tm1, __shfl_xor_sync(0xffffffffu, tm1, 1));
            tm1 = fmaxf(tm1, __shfl_xor_sync(0xffffffffu, tm1, 2));

            float mn0 = fmaxf(m0, tm0), mn1 = fmaxf(m1, tm1);
            float a0 = exp2f(m0 - mn0), a1 = exp2f(m1 - mn1);
            m0 = mn0; m1 = mn1;

            #pragma unroll
            for (int ni = 0; ni < 9; ni++) {
                o[ni][0] *= a0; o[ni][1] *= a0;
                o[ni][2] *= a1; o[ni][3] *= a1;
            }

            // P = 2^(s - m), fp16 packed, stored directly
            #pragma unroll
            for (int ni = 0; ni < 8; ni++) {
                __half2 p0 = h2exp2(__floats2half2_rn(s[ni][0] - mn0, s[ni][1] - mn0));
                __half2 p1 = h2exp2(__floats2half2_rn(s[ni][2] - mn1, s[ni][3] - mn1));
                *(__half2*)(Pq + (wq + g    ) * 160 + (ni * 8 + 2 * t) * 2) = p0;
                *(__half2*)(Pq + (wq + g + 8) * 160 + (ni * 8 + 2 * t) * 2) = p1;
            }
            __syncwarp();   // P rows produced/consumed within same warp

            // ---- O += P @ V  (9th n-block = ones column -> row sums in o[8])
            #pragma unroll
            for (int ks = 0; ks < 4; ks++) {
                uint32_t a[4];
                const char* base = Pq + (wq + g) * 160 + ks * 32 + t * 8;
                uint2 lo = *(const uint2*)base;
                uint2 hi = *(const uint2*)(base + 8 * 160);
                a[0] = lo.x; a[1] = hi.x; a[2] = lo.y; a[3] = hi.y;
                #pragma unroll
                for (int ni = 0; ni < 9; ni++) {
                    uint2 vb = *(const uint2*)(Vsb + (ks * 4 + t) * VST + (ni * 8 + g) * 8);
                    mma_f16(o[ni], a, vb.x, vb.y);
                }
            }
        }
        __syncthreads();
    }

    // ---- epilogue: l lives in o[8] col 64 (t==0 lane of each quad)
    float l0 = __shfl_sync(0xffffffffu, o[8][0], lane & ~3);
    float l1 = __shfl_sync(0xffffffffu, o[8][2], lane & ~3);
    float inv0 = 1.f / l0, inv1 = 1.f / l1;
    const int qg0 = q0 + wq + g, qg1 = qg0 + 8;
    #pragma unroll
    for (int ni = 0; ni < 8; ni++) {
        int c = h * HD + ni * 8 + 2 * t;
        *(__half2*)&ctx[(size_t)(b * SEQ + qg0) * DOUT + c] =
            __floats2half2_rn(o[ni][0] * inv0, o[ni][1] * inv0);
        *(__half2*)&ctx[(size_t)(b * SEQ + qg1) * DOUT + c] =
            __floats2half2_rn(o[ni][2] * inv1, o[ni][3] * inv1);
    }
}

// ------------------------------- launcher -------------------------------------
extern "C" void kernel_launch(void* const* d_in, const int* in_sizes, int n_in,
                              void* d_out, int out_size)
{
    const float* x    = (const float*)d_in[0];
    const float* Wq   = (const float*)d_in[1];
    const float* Wk   = (const float*)d_in[2];
    const float* Wv   = (const float*)d_in[3];
    const float* Wo   = (const float*)d_in[4];
    const float* cosb = (const float*)d_in[5];
    const float* sinb = (const float*)d_in[6];
    float* out = (float*)d_out;

    __half *pXh, *pWqh, *pWkh, *pWvh, *pWoh, *pQr, *pKr, *pVr, *pCtx;
    cudaGetSymbolAddress((void**)&pXh,  g_xh);
    cudaGetSymbolAddress((void**)&pWqh, g_Wqh);
    cudaGetSymbolAddress((void**)&pWkh, g_Wkh);
    cudaGetSymbolAddress((void**)&pWvh, g_Wvh);
    cudaGetSymbolAddress((void**)&pWoh, g_Woh);
    cudaGetSymbolAddress((void**)&pQr,  g_Qr);
    cudaGetSymbolAddress((void**)&pKr,  g_Kr);
    cudaGetSymbolAddress((void**)&pVr,  g_Vr);
    cudaGetSymbolAddress((void**)&pCtx, g_ctx);

    dim3 thr(256);

    cudaFuncSetAttribute(qkv_h,  cudaFuncAttributeMaxDynamicSharedMemorySize, GEMM_SMEM);
    cudaFuncSetAttribute(wo_h,   cudaFuncAttributeMaxDynamicSharedMemorySize, GEMM_SMEM);
    cudaFuncSetAttribute(attn_h, cudaFuncAttributeMaxDynamicSharedMemorySize, ATTN_SMEM);

    // pre-conversion: x -> fp16; weights -> transposed fp16 [N][K] (one launch)
    cvt_x_k<<<(ROWS*DIN/8 + 255)/256, thr>>>((const float4*)x, (uint4*)pXh, ROWS*DIN/8);
    wtrans4_k<<<10240, thr>>>(Wq, Wk, Wv, Wo, pWqh, pWkh, pWvh, pWoh);

    // fused QKV projection + RoPE (+ Q log2-scale) + head-transpose
    qkv_h<<<dim3(24, ROWS/128), thr, GEMM_SMEM>>>(
        pXh, pWqh, pWkh, pWvh, cosb, sinb, pQr, pKr, pVr);

    // causal flash attention (fp16 tensor core, log2-domain softmax)
    attn_h<<<dim3(SEQ/128, BATCH*NH), thr, ATTN_SMEM>>>(pQr, pKr, pVr, pCtx);

    // output projection
    wo_h<<<dim3(DOUT/128, ROWS/128), thr, GEMM_SMEM>>>(pCtx, pWoh, out);
}

// round 17
// speedup vs baseline: 1.6800x; 1.0284x over previous
#include <cuda_runtime.h>
#include <cuda_fp16.h>
#include <stdint.h>

#define BATCH 2
#define SEQ   2048
#define DIN   2048
#define DOUT  2048
#define NH    32
#define NKV   8
#define HD    64
#define ROWS  (BATCH*SEQ)    /* 4096 */
#define DKV   (NKV*HD)       /* 512  */

// ---------------- scratch (static device arrays; no allocation) ----------------
__device__ __half g_xh [ROWS*DIN];     // x fp16 row-major [M][K]
__device__ __half g_Wqh[DOUT*DIN];     // Wq^T fp16 [N][K]
__device__ __half g_Wkh[DKV*DIN];      // Wk^T fp16 [N][K]
__device__ __half g_Wvh[DKV*DIN];      // Wv^T fp16 [N][K]
__device__ __half g_Woh[DOUT*DOUT];    // Wo^T fp16 [N][K]
__device__ __half g_Qr [ROWS*DOUT];    // [B,NH,S,HD]  (pre-scaled by 0.125*log2e)
__device__ __half g_Kr [ROWS*DKV];     // [B,NKV,S,HD]
__device__ __half g_Vr [ROWS*DKV];     // [B,NKV,S/16,4u,HD,4j] dual-pair interleave
__device__ __half g_ctx[ROWS*DOUT];    // [B*S, NH*HD]

__device__ __forceinline__ void mma_f16(float* c, const uint32_t* a,
                                        uint32_t b0, uint32_t b1) {
    asm volatile(
        "mma.sync.aligned.m16n8k16.row.col.f32.f16.f16.f32 "
        "{%0,%1,%2,%3}, {%4,%5,%6,%7}, {%8,%9}, {%0,%1,%2,%3};"
        : "+f"(c[0]), "+f"(c[1]), "+f"(c[2]), "+f"(c[3])
        : "r"(a[0]), "r"(a[1]), "r"(a[2]), "r"(a[3]), "r"(b0), "r"(b1));
}

__device__ __forceinline__ void ldsm_x4(uint32_t* r, uint32_t addr) {
    asm volatile("ldmatrix.sync.aligned.m8n8.x4.shared.b16 {%0,%1,%2,%3}, [%4];"
        : "=r"(r[0]), "=r"(r[1]), "=r"(r[2]), "=r"(r[3]) : "r"(addr));
}

__device__ __forceinline__ void cp16(uint32_t smem_byte, const void* g) {
    asm volatile("cp.async.cg.shared.global [%0], [%1], 16;\n"
                 :: "r"(smem_byte), "l"(g));
}
__device__ __forceinline__ void cp_commit() {
    asm volatile("cp.async.commit_group;\n" ::);
}
template <int N>
__device__ __forceinline__ void cp_wait() {
    asm volatile("cp.async.wait_group %0;\n" :: "n"(N));
}
__device__ __forceinline__ uint32_t smem_u32(const void* p) {
    return (uint32_t)__cvta_generic_to_shared(p);
}

#define QLOGSCALE 0.1803368801111204f   /* 0.125 * log2(e) */

// ---------------- pre-kernels ---------------------------------------------------
__global__ __launch_bounds__(256) void cvt_x_k(const float4* __restrict__ in,
                                               uint4* __restrict__ out, int n8)
{
    int i = blockIdx.x * blockDim.x + threadIdx.x;
    if (i < n8) {
        float4 v0 = in[2 * i], v1 = in[2 * i + 1];
        __half2 h0 = __floats2half2_rn(v0.x, v0.y);
        __half2 h1 = __floats2half2_rn(v0.z, v0.w);
        __half2 h2 = __floats2half2_rn(v1.x, v1.y);
        __half2 h3 = __floats2half2_rn(v1.z, v1.w);
        uint4 u;
        u.x = *(uint32_t*)&h0; u.y = *(uint32_t*)&h1;
        u.z = *(uint32_t*)&h2; u.w = *(uint32_t*)&h3;
        out[i] = u;
    }
}

// Fused 4-way weight transpose: W [K][N] fp32 -> Wt [N][K] fp16.
__global__ __launch_bounds__(256) void wtrans4_k(
    const float* __restrict__ Wq, const float* __restrict__ Wk,
    const float* __restrict__ Wv, const float* __restrict__ Wo,
    __half* __restrict__ oq, __half* __restrict__ ok,
    __half* __restrict__ ov, __half* __restrict__ oo)
{
    __shared__ __half t[32][34];
    int bid = blockIdx.x;
    const float* W; __half* out; int K, N, tile;
    if (bid < 4096)      { W = Wq; out = oq; K = DIN;  N = DOUT; tile = bid; }
    else if (bid < 5120) { W = Wk; out = ok; K = DIN;  N = DKV;  tile = bid - 4096; }
    else if (bid < 6144) { W = Wv; out = ov; K = DIN;  N = DKV;  tile = bid - 5120; }
    else                 { W = Wo; out = oo; K = DOUT; N = DOUT; tile = bid - 6144; }
    const int ntn = N / 32;
    int kb = (tile / ntn) * 32, nb = (tile % ntn) * 32;
    int tx = threadIdx.x & 31, ty = threadIdx.x >> 5;
    #pragma unroll
    for (int i = 0; i < 4; i++)
        t[ty + 8*i][tx] = __float2half_rn(W[(size_t)(kb + ty + 8*i) * N + nb + tx]);
    __syncthreads();
    #pragma unroll
    for (int i = 0; i < 4; i++)
        out[(size_t)(nb + ty + 8*i) * K + kb + tx] = t[tx][ty + 8*i];
}

// ================= fp16 GEMM mainloop: 3-stage pipeline + ldmatrix =============
#define GEMM_SMEM 98304

__device__ __forceinline__ void gemm_mainloop_h(
    const __half* __restrict__ A, const __half* __restrict__ Bt,
    int K, int row0, int col0, char* smem, float acc[2][8][4])
{
    const int tid  = threadIdx.x;
    const int lane = tid & 31, warp = tid >> 5;
    const int wm = (warp & 3) * 32, wn = (warp >> 2) * 64;
    const uint32_t sBase = smem_u32(smem);

    const int a_r = tid >> 1;
    const int c8b = (tid & 1) * 4;

    auto LOAD = [&](int k0, int buf) {
        const uint32_t bb = sBase + (uint32_t)buf * 32768;
        #pragma unroll
        for (int j = 0; j < 4; j++) {
            const int c8 = c8b + j;
            const int kb = c8 >> 1, part = c8 & 1;
            const int sw = part ^ ((a_r >> 2) & 1);
            const uint32_t off = (uint32_t)((kb * 128 + a_r) * 32 + sw * 16);
            cp16(bb + off,         A  + (size_t)(row0 + a_r) * K + k0 + c8 * 8);
            cp16(bb + 16384 + off, Bt + (size_t)(col0 + a_r) * K + k0 + c8 * 8);
        }
        cp_commit();
    };

    uint32_t aoff[2], boff[4];
    #pragma unroll
    for (int mi = 0; mi < 2; mi++) {
        int row = wm + mi * 16 + ((lane >> 3) & 1) * 8 + (lane & 7);
        int c   = (lane >> 4) & 1;
        aoff[mi] = (uint32_t)(row * 32 + (c ^ ((row >> 2) & 1)) * 16);
    }
    #pragma unroll
    for (int np = 0; np < 4; np++) {
        int row = wn + np * 16 + ((lane >> 4) & 1) * 8 + (lane & 7);
        int c   = (lane >> 3) & 1;
        boff[np] = (uint32_t)(row * 32 + (c ^ ((row >> 2) & 1)) * 16);
    }

    #pragma unroll
    for (int mi = 0; mi < 2; mi++)
        #pragma unroll
        for (int ni = 0; ni < 8; ni++)
            #pragma unroll
            for (int r = 0; r < 4; r++) acc[mi][ni][r] = 0.f;

    const int niter = K / 64;
    LOAD(0, 0);
    LOAD(64, 1);

    for (int it = 0; it < niter; it++) {
        if (it < niter - 1) cp_wait<1>();
        else                cp_wait<0>();
        __syncthreads();
        if (it + 2 < niter)
            LOAD((it + 2) * 64, (it + 2) % 3);

        const uint32_t Ab = sBase + (uint32_t)(it % 3) * 32768;
        const uint32_t Bb = Ab + 16384;
        #pragma unroll
        for (int kb = 0; kb < 4; kb++) {
            uint32_t a[2][4], b[4][4];
            ldsm_x4(a[0], Ab + kb * 4096 + aoff[0]);
            ldsm_x4(a[1], Ab + kb * 4096 + aoff[1]);
            #pragma unroll
            for (int np = 0; np < 4; np++)
                ldsm_x4(b[np], Bb + kb * 4096 + boff[np]);
            #pragma unroll
            for (int mi = 0; mi < 2; mi++)
                #pragma unroll
                for (int np = 0; np < 4; np++) {
                    mma_f16(acc[mi][2 * np    ], a[mi], b[np][0], b[np][1]);
                    mma_f16(acc[mi][2 * np + 1], a[mi], b[np][2], b[np][3]);
                }
        }
    }
}

// ================= fused QKV projection + RoPE + transpose =====================
// grid (24, 32): bx<16 Q (RoPE + log2-scale), <20 K (RoPE), else V (dual-pair).
__global__ __launch_bounds__(256, 2) void qkv_h(
    const __half* __restrict__ xh,
    const __half* __restrict__ Wqh, const __half* __restrict__ Wkh,
    const __half* __restrict__ Wvh,
    const float* __restrict__ cosb, const float* __restrict__ sinb,
    __half* __restrict__ Qr, __half* __restrict__ Kr, __half* __restrict__ Vr)
{
    extern __shared__ char smem[];
    const int bx = blockIdx.x;
    const __half* W; __half* outp; int col0, nh, kind; float qs;
    if (bx < 16)      { W = Wqh; outp = Qr; col0 = bx * 128;        nh = NH;  kind = 0; qs = QLOGSCALE; }
    else if (bx < 20) { W = Wkh; outp = Kr; col0 = (bx - 16) * 128; nh = NKV; kind = 0; qs = 1.f; }
    else              { W = Wvh; outp = Vr; col0 = (bx - 20) * 128; nh = NKV; kind = 1; qs = 1.f; }
    const int row0 = blockIdx.y * 128;

    float acc[2][8][4];
    gemm_mainloop_h(xh, W, DIN, row0, col0, smem, acc);

    const int lane = threadIdx.x & 31, warp = threadIdx.x >> 5;
    const int g = lane >> 2, t = lane & 3;
    const int wm = (warp & 3) * 32, wn = (warp >> 2) * 64;
    const int hq = (col0 + wn) >> 6;

    #pragma unroll
    for (int mi = 0; mi < 2; mi++) {
        const int rbase = row0 + wm + mi * 16 + g;
        #pragma unroll
        for (int v = 0; v < 2; v++) {
            const int r = rbase + v * 8;
            const int b = r >> 11, s = r & 2047;
            if (kind == 0) {
                __half* row = outp + ((size_t)(b * nh + hq) * SEQ + s) * HD;
                const float* cs = cosb + s * HD;
                const float* sn = sinb + s * HD;
                #pragma unroll
                for (int ni = 0; ni < 4; ni++) {
                    const int d = ni * 8 + 2 * t;
                    float x1a = acc[mi][ni    ][v*2], x1b = acc[mi][ni    ][v*2+1];
                    float x2a = acc[mi][ni + 4][v*2], x2b = acc[mi][ni + 4][v*2+1];
                    float2 c1 = *(const float2*)&cs[d];
                    float2 s1 = *(const float2*)&sn[d];
                    float2 c2 = *(const float2*)&cs[d + 32];
                    float2 s2 = *(const float2*)&sn[d + 32];
                    *(__half2*)&row[d] =
                        __floats2half2_rn((x1a * c1.x - x2a * s1.x) * qs,
                                          (x1b * c1.y - x2b * s1.y) * qs);
                    *(__half2*)&row[d + 32] =
                        __floats2half2_rn((x2a * c2.x + x1a * s2.x) * qs,
                                          (x2b * c2.y + x1b * s2.y) * qs);
                }
            } else {
                // V dual-pair interleave: [S/16][4u][HD][4j]
                // u = (s>>1)&3, j = (s&1) | ((s>>3)&1)<<1
                __half* hb = outp + (size_t)(b * nh + hq) * SEQ * HD;
                const int u = (s >> 1) & 3;
                const int j = (s & 1) | (((s >> 3) & 1) << 1);
                const size_t sb = (size_t)((s >> 4) * 4 + u) * (HD * 4) + j;
                #pragma unroll
                for (int ni = 0; ni < 8; ni++) {
                    const int d = ni * 8 + 2 * t;
                    hb[sb + (size_t)d * 4]       = __float2half_rn(acc[mi][ni][v*2]);
                    hb[sb + (size_t)(d + 1) * 4] = __float2half_rn(acc[mi][ni][v*2+1]);
                }
            }
        }
    }
}

// ================= output projection ===========================================
__global__ __launch_bounds__(256, 2) void wo_h(
    const __half* __restrict__ ctx, const __half* __restrict__ Woh,
    float* __restrict__ out)
{
    extern __shared__ char smem[];
    const int row0 = blockIdx.y * 128, col0 = blockIdx.x * 128;

    float acc[2][8][4];
    gemm_mainloop_h(ctx, Woh, DOUT, row0, col0, smem, acc);

    const int lane = threadIdx.x & 31, warp = threadIdx.x >> 5;
    const int g = lane >> 2, t = lane & 3;
    const int wm = (warp & 3) * 32, wn = (warp >> 2) * 64;

    #pragma unroll
    for (int mi = 0; mi < 2; mi++)
        #pragma unroll
        for (int ni = 0; ni < 8; ni++) {
            const int r = row0 + wm + mi * 16 + g;
            const int c = col0 + wn + ni * 8 + t * 2;
            *(float2*)(out + (size_t)r * DOUT + c) =
                make_float2(acc[mi][ni][0], acc[mi][ni][1]);
            *(float2*)(out + (size_t)(r + 8) * DOUT + c) =
                make_float2(acc[mi][ni][2], acc[mi][ni][3]);
        }
}

// ================= fp16 flash attention ========================================
// 128-key tiles, 2 sub-iters. P stays in registers (S-accumulator layout ==
// A-fragment layout for canonical k-order); V dual-pair interleave gives the
// matching canonical B fragment as one LDS.64.
#define KTB 20480                  /* 128*160 */
#define VST 608
#define VTB (32*VST)               /* 19456 */
#define ATTN_SMEM (20480 + 2*KTB + 2*VTB)   /* 100352 */

__global__ __launch_bounds__(256) void attn_h(
    const __half* __restrict__ Qr, const __half* __restrict__ Kr,
    const __half* __restrict__ Vr, __half* __restrict__ ctx)
{
    extern __shared__ char sm[];
    char* Pq = sm;                 // [128][160B]  Q staging
    char* Ks = sm + 20480;         // [2][128][160B]
    char* Vs = sm + 20480 + 2 * KTB;   // [2][32][608B]

    const int bh = blockIdx.y;
    const int b = bh >> 5, h = bh & 31, g2 = h >> 2;
    const int qt = gridDim.x - 1 - blockIdx.x;     // heavy tiles first
    const int q0 = qt * 128;
    const int tid = threadIdx.x;
    const int warp = tid >> 5, lane = tid & 31;
    const int g = lane >> 2, t = lane & 3;
    const int wq = warp * 16;

    const __half* Qbase = Qr + ((size_t)bh * SEQ + q0) * HD;
    const __half* Kbase = Kr + (size_t)(b * NKV + g2) * SEQ * HD;
    const __half* Vbase = Vr + (size_t)(b * NKV + g2) * SEQ * HD;   // dual-pair

    const uint32_t sK = smem_u32(Ks);
    const uint32_t sV = smem_u32(Vs);
    const uint32_t sP = smem_u32(Pq);

    auto LOADKV = [&](int k0, int buf) {
        #pragma unroll
        for (int i = 0; i < 4; i++) {
            const int ch = tid + i * 256;
            const int row = ch >> 3, c8 = ch & 7;
            cp16(sK + (uint32_t)(buf * KTB + row * 160 + c8 * 16),
                 Kbase + (size_t)(k0 + row) * HD + c8 * 8);
            const int sblk = ch >> 5, c = ch & 31;
            cp16(sV + (uint32_t)(buf * VTB + sblk * VST + c * 16),
                 Vbase + (size_t)k0 * 64 + sblk * 256 + c * 8);
        }
        cp_commit();
    };

    // ones/zero pad columns of V smem: 64 rows (2 bufs x 32) x 96B.
    {
        const int row = tid >> 2, part = tid & 3;
        char* rp = Vs + (row < 32 ? row * VST : VTB + (row - 32) * VST) + 512;
        #pragma unroll
        for (int bgo = 0; bgo < 24; bgo += 4) {
            int off = part * 24 + bgo;
            uint32_t val = (off < 8) ? 0x3C003C00u : 0u;   // d=64 halves = 1.0
            *(uint32_t*)(rp + off) = val;
        }
    }

    // stage Q FIRST, then prefetch KV0; wait<1> drains Q while KV0 flies.
    #pragma unroll
    for (int i = 0; i < 4; i++) {
        const int ch = tid + i * 256;
        const int row = ch >> 3, c8 = ch & 7;
        cp16(sP + (uint32_t)(row * 160 + c8 * 16), Qbase + (size_t)row * HD + c8 * 8);
    }
    cp_commit();
    LOADKV(0, 0);
    cp_wait<1>();
    __syncthreads();

    uint32_t qf[4][4];
    #pragma unroll
    for (int ds = 0; ds < 4; ds++) {
        const char* base = Pq + (wq + g) * 160 + ds * 32 + t * 8;
        uint2 lo = *(const uint2*)base;
        uint2 hi = *(const uint2*)(base + 8 * 160);
        qf[ds][0] = lo.x; qf[ds][1] = hi.x; qf[ds][2] = lo.y; qf[ds][3] = hi.y;
    }
    __syncthreads();   // Q regs everywhere; also covers ones-init

    float o[9][4];     // o[8] = running row-sum (ones column)
    #pragma unroll
    for (int ni = 0; ni < 9; ni++)
        #pragma unroll
        for (int r = 0; r < 4; r++) o[ni][r] = 0.f;
    float m0 = -1e30f, m1 = -1e30f;

    const int nt128 = qt + 1;
    for (int tt = 0; tt < nt128; tt++) {
        const int buf = tt & 1;
        if (tt + 1 < nt128) {
            LOADKV((tt + 1) * 128, buf ^ 1);
            cp_wait<1>();
        } else {
            cp_wait<0>();
        }
        __syncthreads();

        #pragma unroll
        for (int sub = 0; sub < 2; sub++) {
            const char* Ksb = Ks + buf * KTB + sub * 64 * 160;
            const char* Vsb = Vs + buf * VTB + sub * 16 * VST;
            const int k0 = tt * 128 + sub * 64;

            // ---- S = Q @ K^T  (log2 domain via pre-scaled Q)
            float s[8][4];
            #pragma unroll
            for (int ni = 0; ni < 8; ni++)
                #pragma unroll
                for (int r = 0; r < 4; r++) s[ni][r] = 0.f;

            #pragma unroll
            for (int ds = 0; ds < 4; ds++) {
                #pragma unroll
                for (int ni = 0; ni < 8; ni++) {
                    uint2 kb2 = *(const uint2*)(Ksb + (ni * 8 + g) * 160 + ds * 32 + t * 8);
                    mma_f16(s[ni], qf[ds], kb2.x, kb2.y);
                }
            }

            // ---- causal mask
            const bool do_mask = (k0 + 63 > q0);
            const int qg0 = q0 + wq + g, qg1 = qg0 + 8;
            if (do_mask) {
                #pragma unroll
                for (int ni = 0; ni < 8; ni++) {
                    #pragma unroll
                    for (int r = 0; r < 4; r++) {
                        int kg = k0 + ni * 8 + 2 * t + (r & 1);
                        int qg = (r >= 2) ? qg1 : qg0;
                        if (kg > qg) s[ni][r] = -1e30f;
                    }
                }
            }

            // ---- online softmax (log2 domain)
            float tm0 = -1e30f, tm1 = -1e30f;
            #pragma unroll
            for (int ni = 0; ni < 8; ni++) {
                tm0 = fmaxf(tm0, fmaxf(s[ni][0], s[ni][1]));
                tm1 = fmaxf(tm1, fmaxf(s[ni][2], s[ni][3]));
            }
            tm0 = fmaxf(tm0, __shfl_xor_sync(0xffffffffu, tm0, 1));
            tm0 = fmaxf(tm0, __shfl_xor_sync(0xffffffffu, tm0, 2));
            tm1 = fmaxf(tm1, __shfl_xor_sync(0xffffffffu, tm1, 1));
            tm1 = fmaxf(tm1, __shfl_xor_sync(0xffffffffu, tm1, 2));

            float mn0 = fmaxf(m0, tm0), mn1 = fmaxf(m1, tm1);
            float a0 = exp2f(m0 - mn0), a1 = exp2f(m1 - mn1);
            m0 = mn0; m1 = mn1;

            #pragma unroll
            for (int ni = 0; ni < 9; ni++) {
                o[ni][0] *= a0; o[ni][1] *= a0;
                o[ni][2] *= a1; o[ni][3] *= a1;
            }

            // ---- O += P @ V  (P built directly in A-fragment registers;
            //      9th n-block = ones column -> row sums in o[8])
            #pragma unroll
            for (int ks = 0; ks < 4; ks++) {
                __half2 p0 = h2exp2(__floats2half2_rn(s[2*ks  ][0] - mn0, s[2*ks  ][1] - mn0));
                __half2 p1 = h2exp2(__floats2half2_rn(s[2*ks  ][2] - mn1, s[2*ks  ][3] - mn1));
                __half2 p2 = h2exp2(__floats2half2_rn(s[2*ks+1][0] - mn0, s[2*ks+1][1] - mn0));
                __half2 p3 = h2exp2(__floats2half2_rn(s[2*ks+1][2] - mn1, s[2*ks+1][3] - mn1));
                uint32_t a[4];
                a[0] = *(uint32_t*)&p0; a[1] = *(uint32_t*)&p1;
                a[2] = *(uint32_t*)&p2; a[3] = *(uint32_t*)&p3;
                #pragma unroll
                for (int ni = 0; ni < 9; ni++) {
                    uint2 vb = *(const uint2*)(Vsb + (ks * 4 + t) * VST + (ni * 8 + g) * 8);
                    mma_f16(o[ni], a, vb.x, vb.y);
                }
            }
        }
        __syncthreads();
    }

    // ---- epilogue: l lives in o[8] col 64 (t==0 lane of each quad)
    float l0 = __shfl_sync(0xffffffffu, o[8][0], lane & ~3);
    float l1 = __shfl_sync(0xffffffffu, o[8][2], lane & ~3);
    float inv0 = 1.f / l0, inv1 = 1.f / l1;
    const int qg0 = q0 + wq + g, qg1 = qg0 + 8;
    #pragma unroll
    for (int ni = 0; ni < 8; ni++) {
        int c = h * HD + ni * 8 + 2 * t;
        *(__half2*)&ctx[(size_t)(b * SEQ + qg0) * DOUT + c] =
            __floats2half2_rn(o[ni][0] * inv0, o[ni][1] * inv0);
        *(__half2*)&ctx[(size_t)(b * SEQ + qg1) * DOUT + c] =
            __floats2half2_rn(o[ni][2] * inv1, o[ni][3] * inv1);
    }
}

// ------------------------------- launcher -------------------------------------
extern "C" void kernel_launch(void* const* d_in, const int* in_sizes, int n_in,
                              void* d_out, int out_size)
{
    const float* x    = (const float*)d_in[0];
    const float* Wq   = (const float*)d_in[1];
    const float* Wk   = (const float*)d_in[2];
    const float* Wv   = (const float*)d_in[3];
    const float* Wo   = (const float*)d_in[4];
    const float* cosb = (const float*)d_in[5];
    const float* sinb = (const float*)d_in[6];
    float* out = (float*)d_out;

    __half *pXh, *pWqh, *pWkh, *pWvh, *pWoh, *pQr, *pKr, *pVr, *pCtx;
    cudaGetSymbolAddress((void**)&pXh,  g_xh);
    cudaGetSymbolAddress((void**)&pWqh, g_Wqh);
    cudaGetSymbolAddress((void**)&pWkh, g_Wkh);
    cudaGetSymbolAddress((void**)&pWvh, g_Wvh);
    cudaGetSymbolAddress((void**)&pWoh, g_Woh);
    cudaGetSymbolAddress((void**)&pQr,  g_Qr);
    cudaGetSymbolAddress((void**)&pKr,  g_Kr);
    cudaGetSymbolAddress((void**)&pVr,  g_Vr);
    cudaGetSymbolAddress((void**)&pCtx, g_ctx);

    dim3 thr(256);

    cudaFuncSetAttribute(qkv_h,  cudaFuncAttributeMaxDynamicSharedMemorySize, GEMM_SMEM);
    cudaFuncSetAttribute(wo_h,   cudaFuncAttributeMaxDynamicSharedMemorySize, GEMM_SMEM);
    cudaFuncSetAttribute(attn_h, cudaFuncAttributeMaxDynamicSharedMemorySize, ATTN_SMEM);

    // pre-conversion: x -> fp16; weights -> transposed fp16 [N][K] (one launch)
    cvt_x_k<<<(ROWS*DIN/8 + 255)/256, thr>>>((const float4*)x, (uint4*)pXh, ROWS*DIN/8);
    wtrans4_k<<<10240, thr>>>(Wq, Wk, Wv, Wo, pWqh, pWkh, pWvh, pWoh);

    // fused QKV projection + RoPE (+ Q log2-scale) + head-transpose
    qkv_h<<<dim3(24, ROWS/128), thr, GEMM_SMEM>>>(
        pXh, pWqh, pWkh, pWvh, cosb, sinb, pQr, pKr, pVr);

    // causal flash attention (fp16 tensor core, register-resident P)
    attn_h<<<dim3(SEQ/128, BATCH*NH), thr, ATTN_SMEM>>>(pQr, pKr, pVr, pCtx);

    // output projection
    wo_h<<<dim3(DOUT/128, ROWS/128), thr, GEMM_SMEM>>>(pCtx, pWoh, out);
}